// round 8
// baseline (speedup 1.0000x reference)
#include <cuda_runtime.h>
#include <cuda_bf16.h>
#include <math.h>
#include <stdint.h>

#ifndef M_PI
#define M_PI 3.14159265358979323846
#endif

#define Bc 256
#define Lc 256
#define Dc 128
#define Hc 2
#define Ec 64
#define NLc 2
#define TOPKc 5
#define NUM_TOTAL_C 100000
#define INV_SQRT_E 0.125f
#define INV_SQRT_2F 0.70710678118654752440f

typedef __nv_bfloat16 bf16;

// ---------------- scratch ----------------
__device__ float g_x  [Bc*Lc*Dc];
__device__ float g_mask[Bc*Lc];
__device__ float g_vb [Bc*Lc*Dc];
__device__ float g_sp [Bc*Lc*Dc];
__device__ float g_mv [Bc*Lc];
__device__ float g_mvp[16*Bc*Lc];
__device__ int   g_delays[TOPKc];
__device__ float g_w  [Bc*TOPKc];

__device__ bf16 g_Cm3 [Lc*3*Lc];
__device__ bf16 g_xA3 [Bc*Lc*3*Dc];
__device__ bf16 g_xB3 [(size_t)Bc*3*Lc*Dc];
__device__ bf16 g_xtA3[Bc*Lc*3*Dc];
__device__ bf16 g_qt3 [Bc*Lc*3*Dc];
__device__ bf16 g_kt3 [Bc*Lc*3*Dc];
__device__ bf16 g_vth [Bc*Lc*Dc];
__device__ bf16 g_vtl [Bc*Lc*Dc];
__device__ bf16 g_o3  [Bc*Lc*3*Dc];
__device__ bf16 g_a3  [Bc*Lc*3*Dc];
__device__ bf16 g_h3  [(size_t)Bc*Lc*3*2*Dc];
__device__ bf16 g_W3  [6*3*Dc*2*Dc];

#define W3_Q  0
#define W3_K  (3*Dc*Dc)
#define W3_V  (2*3*Dc*Dc)
#define W3_P  (3*3*Dc*Dc)
#define W3_F1 (4*3*Dc*Dc)
#define W3_F2 (4*3*Dc*Dc + 3*Dc*2*Dc)

// ---------------- PTX helpers ----------------
__device__ __forceinline__ uint32_t smem_u32(const void* p) {
    return (uint32_t)__cvta_generic_to_shared(p);
}
__device__ __forceinline__ void cpasync16(void* sp, const void* gp) {
    asm volatile("cp.async.cg.shared.global [%0], [%1], 16;"
                 :: "r"(smem_u32(sp)), "l"(gp));
}
#define CP_COMMIT() asm volatile("cp.async.commit_group;")
#define CP_WAIT0()  asm volatile("cp.async.wait_group 0;")
#define CP_WAIT1()  asm volatile("cp.async.wait_group 1;")

#define LDSM_X4(r0,r1,r2,r3,addr) \
    asm volatile("ldmatrix.sync.aligned.m8n8.x4.shared.b16 {%0,%1,%2,%3}, [%4];" \
        : "=r"(r0),"=r"(r1),"=r"(r2),"=r"(r3) : "r"(addr))
#define LDSM_X4_T(r0,r1,r2,r3,addr) \
    asm volatile("ldmatrix.sync.aligned.m8n8.x4.trans.shared.b16 {%0,%1,%2,%3}, [%4];" \
        : "=r"(r0),"=r"(r1),"=r"(r2),"=r"(r3) : "r"(addr))

#define MMA_BF16(d, a, b0v, b1v) \
    asm volatile("mma.sync.aligned.m16n8k16.row.col.f32.bf16.bf16.f32 " \
        "{%0,%1,%2,%3}, {%4,%5,%6,%7}, {%8,%9}, {%0,%1,%2,%3};" \
        : "+f"(d[0]), "+f"(d[1]), "+f"(d[2]), "+f"(d[3]) \
        : "r"(a[0]), "r"(a[1]), "r"(a[2]), "r"(a[3]), "r"(b0v), "r"(b1v))

// ---------------- bf16x3 tensor-core GEMM, 3-stage pipeline ----------------
// C = A3 @ B3 (NN, K tripled). emit bits: 1=fp32 C, 2=A-role triple(h,h,l)->aux1,
// 4=B-transB triple(h,l,h)->aux1, 8=h->aux1,l->aux2, 16=row-triple(h,l,h)->aux2.
// fuse: 0 none, 1 +=R, 2 exact-erf GELU.
#define MMA_SMEM_BYTES (3*128*40*2 + 3*32*136*2)   // 56832

template<int BN>
__global__ __launch_bounds__(256, 2)
void mma_kernel(const bf16* __restrict__ A, const bf16* __restrict__ Bp,
                float* __restrict__ C,
                int K, int lda, int ldb, int ldc,
                int zdiv, long sA1, long sA2, long sB1, long sB2, long sC1, long sC2,
                const float* __restrict__ R, int ldr, int fuse,
                int emit, bf16* __restrict__ aux1, bf16* __restrict__ aux2)
{
    constexpr int MT   = 4;
    constexpr int NT16 = 2;
    constexpr int BK   = 32;

    extern __shared__ char dynsm[];
    bf16 (*As)[128][40] = (bf16(*)[128][40])dynsm;
    bf16 (*Bs)[32][BN + 8] = (bf16(*)[32][BN + 8])(dynsm + 3*128*40*2);

    const int tid  = threadIdx.x;
    const int warp = tid >> 5;
    const int lane = tid & 31;
    const int warpM0 = (warp & 1) * 64;
    const int warpN0 = (warp >> 1) * 32;

    int z = blockIdx.z, z1 = z / zdiv, z2 = z - z1 * zdiv;
    long coff = z1 * sC1 + z2 * sC2;
    A  += z1 * sA1 + z2 * sA2;
    Bp += z1 * sB1 + z2 * sB2;
    C  += coff;
    if (aux1) aux1 += 3 * coff;
    if (aux2) aux2 += 3 * coff;

    const int m0 = blockIdx.x * 128;
    const int n0 = blockIdx.y * BN;

    auto load_tiles = [&](int buf, int k0) {
        #pragma unroll
        for (int i = 0; i < 2; i++) {
            int c = tid + i * 256;
            int row = c >> 2, kc = (c & 3) << 3;
            cpasync16(&As[buf][row][kc], A + (size_t)(m0 + row) * lda + k0 + kc);
        }
        constexpr int CPR = BN / 8;
        constexpr int BCH = 32 * CPR;
        #pragma unroll
        for (int i = 0; i < BCH / 256; i++) {
            int c = tid + i * 256;
            int row = c / CPR, nc = (c % CPR) << 3;
            cpasync16(&Bs[buf][row][nc], Bp + (size_t)(k0 + row) * ldb + n0 + nc);
        }
    };

    float acc[MT][NT16][2][4];
    #pragma unroll
    for (int i = 0; i < MT; i++)
        #pragma unroll
        for (int j = 0; j < NT16; j++)
            #pragma unroll
            for (int s = 0; s < 2; s++)
                #pragma unroll
                for (int q = 0; q < 4; q++) acc[i][j][s][q] = 0.f;

    const int nk = K / BK;
    load_tiles(0, 0);
    CP_COMMIT();
    if (nk > 1) { load_tiles(1, BK); CP_COMMIT(); }

    for (int kt = 0; kt < nk; kt++) {
        if (kt + 1 < nk) CP_WAIT1(); else CP_WAIT0();
        __syncthreads();
        const int buf = kt % 3;
        if (kt + 2 < nk) { load_tiles((kt + 2) % 3, (kt + 2) * BK); CP_COMMIT(); }
        #pragma unroll
        for (int ks = 0; ks < 2; ks++) {
            uint32_t a[MT][4];
            #pragma unroll
            for (int tm = 0; tm < MT; tm++) {
                uint32_t addr = smem_u32(
                    &As[buf][warpM0 + tm*16 + (lane & 15)][ks*16 + ((lane >> 4) << 3)]);
                LDSM_X4(a[tm][0], a[tm][1], a[tm][2], a[tm][3], addr);
            }
            uint32_t b[NT16][4];
            #pragma unroll
            for (int tn = 0; tn < NT16; tn++) {
                uint32_t addr = smem_u32(
                    &Bs[buf][ks*16 + (lane & 15)][warpN0 + tn*16 + ((lane >> 4) << 3)]);
                LDSM_X4_T(b[tn][0], b[tn][1], b[tn][2], b[tn][3], addr);
            }
            #pragma unroll
            for (int tm = 0; tm < MT; tm++)
                #pragma unroll
                for (int tn = 0; tn < NT16; tn++) {
                    MMA_BF16(acc[tm][tn][0], a[tm], b[tn][0], b[tn][1]);
                    MMA_BF16(acc[tm][tn][1], a[tm], b[tn][2], b[tn][3]);
                }
        }
    }

    #pragma unroll
    for (int tm = 0; tm < MT; tm++)
        #pragma unroll
        for (int tn = 0; tn < NT16; tn++)
            #pragma unroll
            for (int s = 0; s < 2; s++) {
                int col = n0 + warpN0 + tn*16 + s*8 + ((lane & 3) << 1);
                float* cc = acc[tm][tn][s];
                #pragma unroll
                for (int hr = 0; hr < 2; hr++) {
                    int row = m0 + warpM0 + tm*16 + (lane >> 2) + hr*8;
                    float2 v = make_float2(cc[hr*2 + 0], cc[hr*2 + 1]);
                    if (fuse == 1) {
                        float2 r = *(const float2*)&R[(size_t)row * ldr + col];
                        v.x += r.x; v.y += r.y;
                    } else if (fuse == 2) {
                        v.x = v.x * 0.5f * (1.0f + erff(v.x * INV_SQRT_2F));
                        v.y = v.y * 0.5f * (1.0f + erff(v.y * INV_SQRT_2F));
                    }
                    size_t ci = (size_t)row * ldc + col;
                    if (emit & 1) *(float2*)&C[ci] = v;
                    if (emit & 0x1E) {
                        bf16 hx = __float2bfloat16(v.x);
                        bf16 lx = __float2bfloat16(v.x - __bfloat162float(hx));
                        bf16 hy = __float2bfloat16(v.y);
                        bf16 ly = __float2bfloat16(v.y - __bfloat162float(hy));
                        if (emit & 2) {
                            bf16* o = aux1 + (size_t)row * (3*ldc) + 3*col;
                            o[0]=hx; o[1]=hx; o[2]=lx; o[3]=hy; o[4]=hy; o[5]=ly;
                        }
                        if (emit & 4) {
                            bf16* o = aux1 + (size_t)row * (3*ldc) + 3*col;
                            o[0]=hx; o[1]=lx; o[2]=hx; o[3]=hy; o[4]=ly; o[5]=hy;
                        }
                        if (emit & 8) {
                            aux1[ci] = hx; aux1[ci+1] = hy;
                            aux2[ci] = lx; aux2[ci+1] = ly;
                        }
                        if (emit & 16) {
                            bf16* o = aux2 + (size_t)(3*row) * ldc + col;
                            o[0] = hx;        o[1] = hy;
                            o[ldc] = lx;      o[ldc+1] = ly;
                            o[2*ldc] = hx;    o[2*ldc+1] = hy;
                        }
                    }
                }
            }
}

// ---------------- fused attention (512 threads, 16 warps) ----------------
__global__ __launch_bounds__(512, 1)
void fattn_kernel(const bf16* __restrict__ qt3, const bf16* __restrict__ kt3,
                  const bf16* __restrict__ vth, const bf16* __restrict__ vtl,
                  const float* __restrict__ maskg,
                  float* __restrict__ sp, float* __restrict__ mvp)
{
    extern __shared__ char sm[];
    bf16*  Vh = (bf16*) (sm + 0);          // [256][72]
    bf16*  Vl = (bf16*) (sm + 36864);      // [256][72]
    bf16*  Q3 = (bf16*) (sm + 73728);      // [64][200]   (phase-1 only)
    bf16*  K3 = (bf16*) (sm + 99328);      // [256][200]  (phase-1 only)
    float* Ss = (float*)(sm + 73728);      // [64][264]   (overlays Q3/K3 after phase 1)
    bf16*  Ph = (bf16*) (sm + 141312);     // [64][264]
    bf16*  Pl = (bf16*) (sm + 175104);     // [64][264]
    float* mk = (float*)(sm + 208896);     // [256]

    const int tid = threadIdx.x, warp = tid >> 5, lane = tid & 31;
    const int q0 = blockIdx.x * 64;
    const int b  = blockIdx.y >> 1, h = blockIdx.y & 1;

    // prologue
    const bf16* qg = qt3 + ((size_t)(b*Lc + q0)) * 384 + h*192;
    for (int c = tid; c < 1536; c += 512) {
        int r = c / 24, kc = (c % 24) * 8;
        cpasync16(&Q3[r*200 + kc], qg + (size_t)r*384 + kc);
    }
    const bf16* kg = kt3 + ((size_t)(b*Lc)) * 384 + h*192;
    for (int c = tid; c < 6144; c += 512) {
        int r = c / 24, kc = (c % 24) * 8;
        cpasync16(&K3[r*200 + kc], kg + (size_t)r*384 + kc);
    }
    const bf16* vhg = vth + ((size_t)(b*Lc)) * Dc + h*64;
    const bf16* vlg = vtl + ((size_t)(b*Lc)) * Dc + h*64;
    for (int c = tid; c < 2048; c += 512) {
        int r = c >> 3, e = (c & 7) * 8;
        cpasync16(&Vh[r*72 + e], vhg + (size_t)r*Dc + e);
        cpasync16(&Vl[r*72 + e], vlg + (size_t)r*Dc + e);
    }
    for (int c = tid; c < 64; c += 512)
        cpasync16(&mk[c*4], maskg + b*Lc + c*4);
    CP_COMMIT(); CP_WAIT0();
    __syncthreads();

    // phase 1: S = Q3 @ K3^T   (M=64, N=256, K=192); warp grid 2(M) x 8(N), 32x32 tiles
    {
        const int wM = (warp & 1) * 32;
        const int wN = (warp >> 1) * 32;
        float accS[2][2][2][4];
        #pragma unroll
        for (int i=0;i<2;i++) for (int j=0;j<2;j++) for (int s=0;s<2;s++)
            for (int q=0;q<4;q++) accS[i][j][s][q] = 0.f;

        for (int kf = 0; kf < 12; kf++) {
            uint32_t a[2][4], bb[2][4];
            #pragma unroll
            for (int mf = 0; mf < 2; mf++) {
                uint32_t addr = smem_u32(&Q3[(wM + mf*16 + (lane & 15))*200
                                             + kf*16 + ((lane >> 4) << 3)]);
                LDSM_X4(a[mf][0], a[mf][1], a[mf][2], a[mf][3], addr);
            }
            #pragma unroll
            for (int tn = 0; tn < 2; tn++) {
                uint32_t addr = smem_u32(&K3[(wN + tn*16 + (lane & 15))*200
                                             + kf*16 + ((lane >> 4) << 3)]);
                LDSM_X4(bb[tn][0], bb[tn][1], bb[tn][2], bb[tn][3], addr);
            }
            #pragma unroll
            for (int mf = 0; mf < 2; mf++)
                #pragma unroll
                for (int tn = 0; tn < 2; tn++) {
                    MMA_BF16(accS[mf][tn][0], a[mf], bb[tn][0], bb[tn][2]);
                    MMA_BF16(accS[mf][tn][1], a[mf], bb[tn][1], bb[tn][3]);
                }
        }
        __syncthreads();   // done reading Q3/K3 before Ss overlays

        #pragma unroll
        for (int mf = 0; mf < 2; mf++)
            #pragma unroll
            for (int tn = 0; tn < 2; tn++)
                #pragma unroll
                for (int s = 0; s < 2; s++)
                    #pragma unroll
                    for (int hr = 0; hr < 2; hr++) {
                        int row = wM + mf*16 + (lane >> 2) + hr*8;
                        int col = wN + tn*16 + s*8 + ((lane & 3) << 1);
                        *(float2*)&Ss[row*264 + col] =
                            make_float2(accS[mf][tn][s][hr*2], accS[mf][tn][s][hr*2+1]);
                    }
    }
    __syncthreads();

    // meanv partials: 512 threads, d = tid&255, half of m-range each
    {
        int d = tid & 255, half = tid >> 8;
        float s = 0.f;
        #pragma unroll 8
        for (int m = half*32; m < half*32 + 32; m++)
            s += Ss[m*264 + ((q0 + m - d) & 255)];
        int p = (blockIdx.x*2 + h)*2 + half;
        mvp[((size_t)p * Bc + b) * Lc + d] = s * (1.0f/128.0f);
    }
    __syncthreads();

    // softmax: 8 threads per row, 32 cols each
    {
        int row = tid >> 3, part = tid & 7;
        float* Sr = &Ss[row*264 + part*32];
        const float* mr = &mk[part*32];
        float mx = -1e30f;
        #pragma unroll 8
        for (int j = 0; j < 32; j++)
            mx = fmaxf(mx, Sr[j] * INV_SQRT_E + mr[j]);
        mx = fmaxf(mx, __shfl_xor_sync(0xffffffffu, mx, 1));
        mx = fmaxf(mx, __shfl_xor_sync(0xffffffffu, mx, 2));
        mx = fmaxf(mx, __shfl_xor_sync(0xffffffffu, mx, 4));
        float sum = 0.f;
        #pragma unroll 8
        for (int j = 0; j < 32; j++) {
            float e = expf(Sr[j] * INV_SQRT_E + mr[j] - mx);
            Sr[j] = e; sum += e;
        }
        sum += __shfl_xor_sync(0xffffffffu, sum, 1);
        sum += __shfl_xor_sync(0xffffffffu, sum, 2);
        sum += __shfl_xor_sync(0xffffffffu, sum, 4);
        float inv = 1.0f / sum;
        bf16* ph = &Ph[row*264 + part*32];
        bf16* pl = &Pl[row*264 + part*32];
        #pragma unroll 8
        for (int j = 0; j < 32; j++) {
            float p = Sr[j] * inv;
            bf16 hh = __float2bfloat16(p);
            ph[j] = hh;
            pl[j] = __float2bfloat16(p - __bfloat162float(hh));
        }
    }
    __syncthreads();

    // phase 2: O = Ph@Vh + Ph@Vl + Pl@Vh  (M=64,N=64,K=256), K-split across 2 groups
    {
        const int w8  = warp & 7;
        const int kh  = warp >> 3;
        const int wM2 = (w8 & 1) * 32;
        const int wN2 = ((w8 >> 1) & 3) * 16;
        float o[2][2][4];
        #pragma unroll
        for (int i=0;i<2;i++) for (int s=0;s<2;s++) for (int q=0;q<4;q++) o[i][s][q]=0.f;

        for (int kf = kh*8; kf < kh*8 + 8; kf++) {
            uint32_t ah[2][4], al[2][4], bh[4], bl[4];
            #pragma unroll
            for (int mf = 0; mf < 2; mf++) {
                uint32_t r_off = (wM2 + mf*16 + (lane & 15))*264 + kf*16 + ((lane >> 4) << 3);
                LDSM_X4(ah[mf][0], ah[mf][1], ah[mf][2], ah[mf][3], smem_u32(&Ph[r_off]));
                LDSM_X4(al[mf][0], al[mf][1], al[mf][2], al[mf][3], smem_u32(&Pl[r_off]));
            }
            {
                uint32_t v_off = (kf*16 + (lane & 15))*72 + wN2 + ((lane >> 4) << 3);
                LDSM_X4_T(bh[0], bh[1], bh[2], bh[3], smem_u32(&Vh[v_off]));
                LDSM_X4_T(bl[0], bl[1], bl[2], bl[3], smem_u32(&Vl[v_off]));
            }
            #pragma unroll
            for (int mf = 0; mf < 2; mf++) {
                MMA_BF16(o[mf][0], ah[mf], bh[0], bh[1]);
                MMA_BF16(o[mf][1], ah[mf], bh[2], bh[3]);
                MMA_BF16(o[mf][0], ah[mf], bl[0], bl[1]);
                MMA_BF16(o[mf][1], ah[mf], bl[2], bl[3]);
                MMA_BF16(o[mf][0], al[mf], bh[0], bh[1]);
                MMA_BF16(o[mf][1], al[mf], bh[2], bh[3]);
            }
        }
        __syncthreads();    // Ss free; reuse as partial buffer
        float* Os = Ss;
        if (kh == 1) {
            #pragma unroll
            for (int mf = 0; mf < 2; mf++)
                #pragma unroll
                for (int s = 0; s < 2; s++)
                    #pragma unroll
                    for (int hr = 0; hr < 2; hr++) {
                        int rl = wM2 + mf*16 + (lane >> 2) + hr*8;
                        int cl = wN2 + s*8 + ((lane & 3) << 1);
                        *(float2*)&Os[rl*264 + cl] =
                            make_float2(o[mf][s][hr*2], o[mf][s][hr*2+1]);
                    }
        }
        __syncthreads();
        if (kh == 0) {
            #pragma unroll
            for (int mf = 0; mf < 2; mf++)
                #pragma unroll
                for (int s = 0; s < 2; s++)
                    #pragma unroll
                    for (int hr = 0; hr < 2; hr++) {
                        int rl = wM2 + mf*16 + (lane >> 2) + hr*8;
                        int cl = wN2 + s*8 + ((lane & 3) << 1);
                        float2 p = *(float2*)&Os[rl*264 + cl];
                        int row = q0 + rl;
                        int col = h*64 + cl;
                        *(float2*)&sp[((size_t)b*Lc + row)*Dc + col] =
                            make_float2(o[mf][s][hr*2] + p.x, o[mf][s][hr*2+1] + p.y);
                    }
        }
    }
}

// ---------------- small kernels ----------------
__global__ void build_x_kernel(const int* __restrict__ paths,
                               const float* __restrict__ ego,
                               const float* __restrict__ pos)
{
    int bl = blockIdx.x, c = threadIdx.x;
    int p = paths[bl], l = bl & (Lc - 1);
    float v = ego[(size_t)p * Dc + c] + pos[l * Dc + c];
    g_x[(size_t)bl * Dc + c] = v;
    bf16 h = __float2bfloat16(v);
    bf16 lo = __float2bfloat16(v - __bfloat162float(h));
    bf16* oa = g_xA3 + (size_t)bl * 384 + 3*c;
    oa[0] = h; oa[1] = h; oa[2] = lo;
    bf16* ob = g_xB3 + (size_t)3 * bl * Dc + c;
    ob[0] = h; ob[Dc] = lo; ob[2*Dc] = h;
    if (c == 0) g_mask[bl] = (p < NUM_TOTAL_C) ? 0.f : -10000.f;
}

// band-pass circulant, fused: each block computes c[] then writes its row of Cm3
__global__ void buildC3_kernel(int left, int right)
{
    __shared__ float cs[Lc];
    int n = blockIdx.x, m = threadIdx.x;
    double s = 0.0;
    for (int f = left; f < right; f++) {
        double w;
        if (f == 0)           w = 1.0;
        else if (f == Lc/2)   w = (m & 1) ? -1.0 : 1.0;
        else                  w = 2.0 * cos(2.0 * M_PI * (double)f * (double)m / (double)Lc);
        s += w;
    }
    cs[m] = (float)(s / (double)Lc);
    __syncthreads();
    float v = cs[(n - m + Lc) & (Lc - 1)];
    bf16 h = __float2bfloat16(v);
    bf16 l = __float2bfloat16(v - __bfloat162float(h));
    bf16* o = g_Cm3 + (size_t)n * (3*Lc) + 3*m;
    o[0] = h; o[1] = h; o[2] = l;
}

// all six weight matrices -> rows-tripled (h,l,h) bf16, one launch
__global__ void convW_kernel(const float* __restrict__ Wq, const float* __restrict__ Wk,
                             const float* __restrict__ Wv, const float* __restrict__ Wp,
                             const float* __restrict__ F1, const float* __restrict__ F2,
                             bf16* __restrict__ W3)
{
    int idx = blockIdx.x * 256 + threadIdx.x;      // 0..131071
    const float* src; bf16* dst; int N, e;
    if (idx < 65536) {
        int w = idx >> 14; e = idx & 16383;
        src = (w == 0 ? Wq : w == 1 ? Wk : w == 2 ? Wv : Wp);
        dst = W3 + (size_t)w * (3*Dc*Dc);
        N = Dc;
    } else if (idx < 98304) {
        e = idx - 65536; src = F1; dst = W3 + W3_F1; N = 2*Dc;
    } else {
        e = idx - 98304; src = F2; dst = W3 + W3_F2; N = Dc;
    }
    int r = e / N, n = e % N;
    float v = src[e];
    bf16 h = __float2bfloat16(v);
    bf16 l = __float2bfloat16(v - __bfloat162float(h));
    bf16* o = dst + (size_t)(3*r) * N + n;
    o[0] = h; o[(size_t)N] = l; o[(size_t)2*N] = h;
}

__global__ void meanred_kernel()
{
    int b = blockIdx.x, d = threadIdx.x;
    float s = 0.f;
    #pragma unroll
    for (int p = 0; p < 16; p++) s += g_mvp[((size_t)p * Bc + b) * Lc + d];
    g_mv[b * Lc + d] = s;
}

// gmean + topk + wsoft in one single-block kernel
__global__ void stats_kernel()
{
    __shared__ float sv[Lc];
    __shared__ int   si[Lc];
    __shared__ int   dls[TOPKc];
    int t = threadIdx.x;

    float s = 0.f;
    for (int b = 0; b < Bc; b++) s += g_mv[b * Lc + t];
    float my = s * (1.0f / (float)Bc);

    for (int it = 0; it < TOPKc; it++) {
        sv[t] = my; si[t] = t;
        __syncthreads();
        for (int st = 128; st > 0; st >>= 1) {
            if (t < st) {
                float v2 = sv[t + st]; int i2 = si[t + st];
                if (v2 > sv[t] || (v2 == sv[t] && i2 < si[t])) { sv[t] = v2; si[t] = i2; }
            }
            __syncthreads();
        }
        int win = si[0];
        if (t == 0) { g_delays[it] = win; dls[it] = win; }
        __syncthreads();
        if (t == win) my = -INFINITY;
    }

    // wsoft: t = batch index
    float w[TOPKc];
    float mx = -1e30f;
    #pragma unroll
    for (int i = 0; i < TOPKc; i++) {
        w[i] = g_mv[t * Lc + dls[i]];
        mx = fmaxf(mx, w[i]);
    }
    float sm = 0.f;
    #pragma unroll
    for (int i = 0; i < TOPKc; i++) { w[i] = expf(w[i] - mx); sm += w[i]; }
    float inv = 1.0f / sm;
    #pragma unroll
    for (int i = 0; i < TOPKc; i++) g_w[t * TOPKc + i] = w[i] * inv;
}

// 0.9*freq + 0.1*spatial -> A-role triple o3
__global__ void combine_kernel()
{
    int bl = blockIdx.x, c = threadIdx.x;
    int b = bl >> 8, l = bl & 255;
    __shared__ float w[TOPKc];
    __shared__ int   dl[TOPKc];
    if (c < TOPKc) { w[c] = g_w[b * TOPKc + c]; dl[c] = g_delays[c]; }
    __syncthreads();
    float f = 0.f;
    #pragma unroll
    for (int t = 0; t < TOPKc; t++) {
        int ls = (l + dl[t]) & 255;
        f += w[t] * g_vb[((size_t)b * Lc + ls) * Dc + c];
    }
    float v = 0.9f * f + 0.1f * g_sp[(size_t)bl * Dc + c];
    bf16 h = __float2bfloat16(v);
    bf16 lo = __float2bfloat16(v - __bfloat162float(h));
    bf16* o = g_o3 + (size_t)bl * 384 + 3*c;
    o[0] = h; o[1] = h; o[2] = lo;
}

__global__ void gather_kernel(const int* __restrict__ lengths, float* __restrict__ out)
{
    int b = blockIdx.x, c = threadIdx.x;
    int l = lengths[b] - 1;
    out[b * Dc + c] = g_x[((size_t)b * Lc + l) * Dc + c];
}

// ---------------- host side ----------------
static inline void mma_nn(const bf16* A, const bf16* B, float* C,
                          int M, int N, int K, int lda, int ldb, int ldc,
                          int batch, int zdiv,
                          long sA1, long sA2, long sB1, long sB2, long sC1, long sC2,
                          const float* R, int ldr, int fuse,
                          int emit, bf16* aux1, bf16* aux2)
{
    dim3 grid(M / 128, N / 128, batch);
    mma_kernel<128><<<grid, 256, MMA_SMEM_BYTES>>>(A, B, C, K, lda, ldb, ldc,
        zdiv, sA1, sA2, sB1, sB2, sC1, sC2, R, ldr, fuse, emit, aux1, aux2);
}

extern "C" void kernel_launch(void* const* d_in, const int* in_sizes, int n_in,
                              void* d_out, int out_size)
{
    (void)in_sizes; (void)n_in; (void)out_size;
    const int*   paths   = (const int*)  d_in[0];
    const int*   lengths = (const int*)  d_in[1];
    const float* ego     = (const float*)d_in[4];
    const float* pos     = (const float*)d_in[5];
    const float* Wq      = (const float*)d_in[6];
    const float* Wk      = (const float*)d_in[7];
    const float* Wv      = (const float*)d_in[8];
    const float* Wp      = (const float*)d_in[9];
    const float* F1      = (const float*)d_in[10];
    const float* F2      = (const float*)d_in[11];
    float* out = (float*)d_out;

    float *px, *pmask, *pvb, *psp, *pmvp;
    bf16 *pCm3, *pxA3, *pxB3, *pxtA3, *pqt3, *pkt3, *pvth, *pvtl, *po3, *pa3, *ph3, *pW3;
    cudaGetSymbolAddress((void**)&px,    g_x);
    cudaGetSymbolAddress((void**)&pmask, g_mask);
    cudaGetSymbolAddress((void**)&pvb,   g_vb);
    cudaGetSymbolAddress((void**)&psp,   g_sp);
    cudaGetSymbolAddress((void**)&pmvp,  g_mvp);
    cudaGetSymbolAddress((void**)&pCm3,  g_Cm3);
    cudaGetSymbolAddress((void**)&pxA3,  g_xA3);
    cudaGetSymbolAddress((void**)&pxB3,  g_xB3);
    cudaGetSymbolAddress((void**)&pxtA3, g_xtA3);
    cudaGetSymbolAddress((void**)&pqt3,  g_qt3);
    cudaGetSymbolAddress((void**)&pkt3,  g_kt3);
    cudaGetSymbolAddress((void**)&pvth,  g_vth);
    cudaGetSymbolAddress((void**)&pvtl,  g_vtl);
    cudaGetSymbolAddress((void**)&po3,   g_o3);
    cudaGetSymbolAddress((void**)&pa3,   g_a3);
    cudaGetSymbolAddress((void**)&ph3,   g_h3);
    cudaGetSymbolAddress((void**)&pW3,   g_W3);

    static int attr_set = 0;
    if (!attr_set) {
        cudaFuncSetAttribute(fattn_kernel,
                             cudaFuncAttributeMaxDynamicSharedMemorySize, 209920);
        cudaFuncSetAttribute(mma_kernel<128>,
                             cudaFuncAttributeMaxDynamicSharedMemorySize, MMA_SMEM_BYTES);
        attr_set = 1;
    }

    const int  BL = Bc * Lc;
    const long LD = (long)Lc * Dc;

    build_x_kernel<<<BL, Dc>>>(paths, ego, pos);          // launch 1

    const int lefts[NLc]  = {51, 0};
    const int rights[NLc] = {129, 78};

    for (int k = 0; k < NLc; k++) {
        buildC3_kernel<<<Lc, Lc>>>(lefts[k], rights[k]);  // L0: launch 2
        convW_kernel<<<512, 256>>>(Wq + (size_t)k*Dc*Dc, Wk + (size_t)k*Dc*Dc,
                                   Wv + (size_t)k*Dc*Dc, Wp + (size_t)k*Dc*Dc,
                                   F1 + (size_t)k*Dc*2*Dc, F2 + (size_t)k*2*Dc*Dc,
                                   pW3);                  // launch 3

        // xt = Cm @ x -> xtA3 triple                       launch 4
        mma_nn(pCm3, pxB3, psp /*dummy*/, Lc, Dc, 3*Lc, 3*Lc, Dc, Dc,
               Bc, 1, 0, 0, 3*LD, 0, LD, 0,
               nullptr, 0, 0, 2, pxtA3, nullptr);

        // vb = x @ Wv (fp32)                               launch 5
        mma_nn(pxA3, pW3 + W3_V, pvb, BL, Dc, 3*Dc, 3*Dc, Dc, Dc,
               1, 1, 0, 0, 0, 0, 0, 0, nullptr, 0, 0, 1, nullptr, nullptr);

        // projections (launch 6 = Q proj -> ncu capture target)
        mma_nn(pxtA3, pW3 + W3_Q, psp, BL, Dc, 3*Dc, 3*Dc, Dc, Dc,
               1, 1, 0, 0, 0, 0, 0, 0, nullptr, 0, 0, 2, pqt3, nullptr);
        mma_nn(pxtA3, pW3 + W3_K, psp, BL, Dc, 3*Dc, 3*Dc, Dc, Dc,
               1, 1, 0, 0, 0, 0, 0, 0, nullptr, 0, 0, 4, pkt3, nullptr);
        mma_nn(pxtA3, pW3 + W3_V, psp, BL, Dc, 3*Dc, 3*Dc, Dc, Dc,
               1, 1, 0, 0, 0, 0, 0, 0, nullptr, 0, 0, 8, pvth, pvtl);

        // fused attention
        {
            dim3 grid(4, Bc * Hc);
            fattn_kernel<<<grid, 512, 209920>>>(pqt3, pkt3, pvth, pvtl,
                                                pmask, psp, pmvp);
        }
        meanred_kernel<<<Bc, Lc>>>();
        stats_kernel<<<1, Lc>>>();

        combine_kernel<<<BL, Dc>>>();

        // a = o @ Wp + x -> a3 triple
        mma_nn(po3, pW3 + W3_P, psp, BL, Dc, 3*Dc, 3*Dc, Dc, Dc,
               1, 1, 0, 0, 0, 0, 0, 0, px, Dc, 1, 2, pa3, nullptr);

        // h = GELU(a @ F1) -> h3 triple
        mma_nn(pa3, pW3 + W3_F1, psp, BL, 2*Dc, 3*Dc, 3*Dc, 2*Dc, 2*Dc,
               1, 1, 0, 0, 0, 0, 0, 0, nullptr, 0, 2, 2, ph3, nullptr);

        // x = h @ F2 -> fp32 x + xA3 + xB3
        mma_nn(ph3, pW3 + W3_F2, px, BL, Dc, 3*2*Dc, 3*2*Dc, Dc, Dc,
               1, 1, 0, 0, 0, 0, 0, 0, nullptr, 0, 0, 1 | 2 | 16, pxA3, pxB3);
    }

    gather_kernel<<<Bc, Dc>>>(lengths, out);
}

// round 12
// speedup vs baseline: 1.6730x; 1.6730x over previous
#include <cuda_runtime.h>
#include <cuda_bf16.h>
#include <math.h>
#include <stdint.h>

#ifndef M_PI
#define M_PI 3.14159265358979323846
#endif

#define Bc 256
#define Lc 256
#define Dc 128
#define NLc 2
#define TOPKc 5
#define NUM_TOTAL_C 100000
#define INV_SQRT_E 0.125f
#define INV_SQRT_2F 0.70710678118654752440f

typedef __nv_bfloat16 bf16;

// ---------------- scratch ----------------
__device__ float g_x   [Bc*Lc*Dc];
__device__ float g_mask[Bc*Lc];
__device__ float g_vb  [Bc*Lc*Dc];
__device__ float g_sp  [Bc*Lc*Dc];
__device__ float g_mv  [Bc*Lc];
__device__ float g_mvp [16*Bc*Lc];
__device__ int   g_delays[TOPKc];
__device__ float g_w   [Bc*TOPKc];

// h/l plane pairs (logical K, no tripling in memory)
__device__ bf16 g_xh  [Bc*Lc*Dc];
__device__ bf16 g_xl  [Bc*Lc*Dc];
__device__ bf16 g_xth [Bc*Lc*Dc];
__device__ bf16 g_xtl [Bc*Lc*Dc];
__device__ bf16 g_qkvh[(size_t)Bc*Lc*3*Dc];
__device__ bf16 g_qkvl[(size_t)Bc*Lc*3*Dc];
__device__ bf16 g_oh  [Bc*Lc*Dc];
__device__ bf16 g_ol  [Bc*Lc*Dc];
__device__ bf16 g_ah  [Bc*Lc*Dc];
__device__ bf16 g_al  [Bc*Lc*Dc];
__device__ bf16 g_hh  [Bc*Lc*2*Dc];
__device__ bf16 g_hl  [Bc*Lc*2*Dc];
__device__ bf16 g_Cmh [Lc*Lc];
__device__ bf16 g_Cml [Lc*Lc];
__device__ bf16 g_Wh  [131072];    // [QKV 0..49151][Wp 49152..][F1 65536..][F2 98304..]
__device__ bf16 g_Wl  [131072];

#define WO_QKV 0
#define WO_P   49152
#define WO_F1  65536
#define WO_F2  98304

// ---------------- PTX helpers ----------------
__device__ __forceinline__ uint32_t smem_u32(const void* p) {
    return (uint32_t)__cvta_generic_to_shared(p);
}
__device__ __forceinline__ void cpasync16(void* sp, const void* gp) {
    asm volatile("cp.async.cg.shared.global [%0], [%1], 16;"
                 :: "r"(smem_u32(sp)), "l"(gp));
}
#define CP_COMMIT() asm volatile("cp.async.commit_group;")
#define CP_WAIT0()  asm volatile("cp.async.wait_group 0;")

#define LDSM_X4(r0,r1,r2,r3,addr) \
    asm volatile("ldmatrix.sync.aligned.m8n8.x4.shared.b16 {%0,%1,%2,%3}, [%4];" \
        : "=r"(r0),"=r"(r1),"=r"(r2),"=r"(r3) : "r"(addr))
#define LDSM_X4_T(r0,r1,r2,r3,addr) \
    asm volatile("ldmatrix.sync.aligned.m8n8.x4.trans.shared.b16 {%0,%1,%2,%3}, [%4];" \
        : "=r"(r0),"=r"(r1),"=r"(r2),"=r"(r3) : "r"(addr))

#define MMA_BF16(d, a, b0v, b1v) \
    asm volatile("mma.sync.aligned.m16n8k16.row.col.f32.bf16.bf16.f32 " \
        "{%0,%1,%2,%3}, {%4,%5,%6,%7}, {%8,%9}, {%0,%1,%2,%3};" \
        : "+f"(d[0]), "+f"(d[1]), "+f"(d[2]), "+f"(d[3]) \
        : "r"(a[0]), "r"(a[1]), "r"(a[2]), "r"(a[3]), "r"(b0v), "r"(b1v))

__device__ __forceinline__ void split_hl(float v, bf16& h, bf16& l) {
    h = __float2bfloat16(v);
    l = __float2bfloat16(v - __bfloat162float(h));
}

// ---------------- plane-format 3-term tensor GEMM ----------------
// C = Ah*Bh + Al*Bh + Ah*Bl   (logical K; A [M,K], B [K,N] row-major, NN)
// emit: 1 = fp32 C; 2 = h/l planes Oh/Ol (same ldc).  fuse: 0/1(+R)/2(GELU).
// CTA tile 128x128, BK=32, 2-stage cp.async.
#define MMA_SE 18944                       // elements per stage
#define MMA_SMEM_BYTES (2*MMA_SE*2)        // 75776 bytes

__global__ __launch_bounds__(256, 2)
void mma_kernel(const bf16* __restrict__ Ah, const bf16* __restrict__ Al,
                const bf16* __restrict__ Bh, const bf16* __restrict__ Bl,
                float* __restrict__ C,
                int K, int lda, int ldb, int ldc,
                long sA, long sB, long sC,
                const float* __restrict__ R, int ldr, int fuse,
                int emit, bf16* __restrict__ Oh, bf16* __restrict__ Ol)
{
    extern __shared__ bf16 smp[];
    const int tid  = threadIdx.x;
    const int warp = tid >> 5;
    const int lane = tid & 31;
    const int warpM0 = (warp & 1) * 64;
    const int warpN0 = (warp >> 1) * 32;

    const int z = blockIdx.z;
    Ah += (size_t)z * sA;  Al += (size_t)z * sA;
    Bh += (size_t)z * sB;  Bl += (size_t)z * sB;
    const long co = (size_t)z * sC;

    const int m0 = blockIdx.x * 128;
    const int n0 = blockIdx.y * 128;

    auto load_tiles = [&](int st, int k0) {
        bf16* ah_s = smp + st * MMA_SE;
        bf16* al_s = ah_s + 5120;
        bf16* bh_s = ah_s + 10240;
        bf16* bl_s = ah_s + 14592;
        #pragma unroll
        for (int i = 0; i < 2; i++) {
            int c = tid + i * 256;
            int row = c >> 2, kc = (c & 3) << 3;
            cpasync16(ah_s + row*40 + kc, Ah + (size_t)(m0 + row) * lda + k0 + kc);
            cpasync16(al_s + row*40 + kc, Al + (size_t)(m0 + row) * lda + k0 + kc);
        }
        #pragma unroll
        for (int i = 0; i < 2; i++) {
            int c = tid + i * 256;
            int row = c >> 4, nc = (c & 15) << 3;
            cpasync16(bh_s + row*136 + nc, Bh + (size_t)(k0 + row) * ldb + n0 + nc);
            cpasync16(bl_s + row*136 + nc, Bl + (size_t)(k0 + row) * ldb + n0 + nc);
        }
    };

    float acc[4][2][2][4];
    #pragma unroll
    for (int i = 0; i < 4; i++)
        #pragma unroll
        for (int j = 0; j < 2; j++)
            #pragma unroll
            for (int s = 0; s < 2; s++)
                #pragma unroll
                for (int q = 0; q < 4; q++) acc[i][j][s][q] = 0.f;

    const int nk = K / 32;
    load_tiles(0, 0);
    CP_COMMIT();

    for (int kt = 0; kt < nk; kt++) {
        CP_WAIT0();
        __syncthreads();
        if (kt + 1 < nk) { load_tiles((kt + 1) & 1, (kt + 1) * 32); CP_COMMIT(); }

        bf16* ah_s = smp + (kt & 1) * MMA_SE;
        bf16* al_s = ah_s + 5120;
        bf16* bh_s = ah_s + 10240;
        bf16* bl_s = ah_s + 14592;

        #pragma unroll
        for (int ks = 0; ks < 2; ks++) {
            const int acol = ks*16 + ((lane >> 4) << 3);
            uint32_t ah[4][4], bh[2][4];
            #pragma unroll
            for (int tm = 0; tm < 4; tm++) {
                uint32_t ad = smem_u32(&ah_s[(warpM0 + tm*16 + (lane & 15))*40 + acol]);
                LDSM_X4(ah[tm][0], ah[tm][1], ah[tm][2], ah[tm][3], ad);
            }
            #pragma unroll
            for (int tn = 0; tn < 2; tn++) {
                uint32_t ad = smem_u32(&bh_s[(ks*16 + (lane & 15))*136
                                             + warpN0 + tn*16 + ((lane >> 4) << 3)]);
                LDSM_X4_T(bh[tn][0], bh[tn][1], bh[tn][2], bh[tn][3], ad);
            }
            // term 1: ah * bh
            #pragma unroll
            for (int tm = 0; tm < 4; tm++)
                #pragma unroll
                for (int tn = 0; tn < 2; tn++) {
                    MMA_BF16(acc[tm][tn][0], ah[tm], bh[tn][0], bh[tn][1]);
                    MMA_BF16(acc[tm][tn][1], ah[tm], bh[tn][2], bh[tn][3]);
                }
            // term 2: al * bh
            {
                uint32_t xf[4][4];
                #pragma unroll
                for (int tm = 0; tm < 4; tm++) {
                    uint32_t ad = smem_u32(&al_s[(warpM0 + tm*16 + (lane & 15))*40 + acol]);
                    LDSM_X4(xf[tm][0], xf[tm][1], xf[tm][2], xf[tm][3], ad);
                }
                #pragma unroll
                for (int tm = 0; tm < 4; tm++)
                    #pragma unroll
                    for (int tn = 0; tn < 2; tn++) {
                        MMA_BF16(acc[tm][tn][0], xf[tm], bh[tn][0], bh[tn][1]);
                        MMA_BF16(acc[tm][tn][1], xf[tm], bh[tn][2], bh[tn][3]);
                    }
            }
            // term 3: ah * bl
            {
                uint32_t bl[2][4];
                #pragma unroll
                for (int tn = 0; tn < 2; tn++) {
                    uint32_t ad = smem_u32(&bl_s[(ks*16 + (lane & 15))*136
                                                 + warpN0 + tn*16 + ((lane >> 4) << 3)]);
                    LDSM_X4_T(bl[tn][0], bl[tn][1], bl[tn][2], bl[tn][3], ad);
                }
                #pragma unroll
                for (int tm = 0; tm < 4; tm++)
                    #pragma unroll
                    for (int tn = 0; tn < 2; tn++) {
                        MMA_BF16(acc[tm][tn][0], ah[tm], bl[tn][0], bl[tn][1]);
                        MMA_BF16(acc[tm][tn][1], ah[tm], bl[tn][2], bl[tn][3]);
                    }
            }
        }
    }

    // epilogue
    #pragma unroll
    for (int tm = 0; tm < 4; tm++)
        #pragma unroll
        for (int tn = 0; tn < 2; tn++)
            #pragma unroll
            for (int s = 0; s < 2; s++) {
                int col = n0 + warpN0 + tn*16 + s*8 + ((lane & 3) << 1);
                float* cc = acc[tm][tn][s];
                #pragma unroll
                for (int hr = 0; hr < 2; hr++) {
                    int row = m0 + warpM0 + tm*16 + (lane >> 2) + hr*8;
                    float2 v = make_float2(cc[hr*2 + 0], cc[hr*2 + 1]);
                    if (fuse == 1) {
                        float2 r = *(const float2*)&R[(size_t)row * ldr + col];
                        v.x += r.x; v.y += r.y;
                    } else if (fuse == 2) {
                        v.x = v.x * 0.5f * (1.0f + erff(v.x * INV_SQRT_2F));
                        v.y = v.y * 0.5f * (1.0f + erff(v.y * INV_SQRT_2F));
                    }
                    size_t ci = co + (size_t)row * ldc + col;
                    if (emit & 1) *(float2*)&C[ci] = v;
                    if (emit & 2) {
                        bf16 hx, lx, hy, ly;
                        split_hl(v.x, hx, lx);
                        split_hl(v.y, hy, ly);
                        __nv_bfloat162 hv; hv.x = hx; hv.y = hy;
                        __nv_bfloat162 lv; lv.x = lx; lv.y = ly;
                        *(__nv_bfloat162*)&Oh[ci] = hv;
                        *(__nv_bfloat162*)&Ol[ci] = lv;
                    }
                }
            }
}

// ---------------- fused attention (plane inputs, 512 threads) ----------------
// Q/K: 3-term bf16 split. P@V: single-term bf16 (spatial branch weighted 0.1).
#define FA_VH 0
#define FA_QH 36864
#define FA_QL 46080
#define FA_KH 55296
#define FA_KL 92160
#define FA_SS 36864     /* overlays Q/K after phase 1 */
#define FA_PH 129024
#define FA_MK 162816
#define FA_SMEM 163840

__global__ __launch_bounds__(512, 1)
void fattn_kernel(const bf16* __restrict__ qkvh, const bf16* __restrict__ qkvl,
                  const float* __restrict__ maskg,
                  float* __restrict__ sp, float* __restrict__ mvp)
{
    extern __shared__ char sm[];
    bf16*  Vh = (bf16*) (sm + FA_VH);      // [256][72]
    bf16*  Qh = (bf16*) (sm + FA_QH);      // [64][72]
    bf16*  Ql = (bf16*) (sm + FA_QL);
    bf16*  Kh = (bf16*) (sm + FA_KH);      // [256][72]
    bf16*  Kl = (bf16*) (sm + FA_KL);
    float* Ss = (float*)(sm + FA_SS);      // [64][264] (after phase 1)
    bf16*  Ph = (bf16*) (sm + FA_PH);      // [64][264]
    float* mk = (float*)(sm + FA_MK);      // [256]

    const int tid = threadIdx.x, warp = tid >> 5, lane = tid & 31;
    const int q0 = blockIdx.x * 64;
    const int b  = blockIdx.y >> 1, h = blockIdx.y & 1;

    // prologue loads
    const bf16* qgh = qkvh + ((size_t)(b*Lc + q0)) * 384 + h*64;
    const bf16* qgl = qkvl + ((size_t)(b*Lc + q0)) * 384 + h*64;
    const bf16* kgh = qkvh + ((size_t)(b*Lc)) * 384 + 128 + h*64;
    const bf16* kgl = qkvl + ((size_t)(b*Lc)) * 384 + 128 + h*64;
    const bf16* vgh = qkvh + ((size_t)(b*Lc)) * 384 + 256 + h*64;

    {
        int c = tid;                        // Q: 512 chunks/plane
        int r = c >> 3, kc = (c & 7) << 3;
        cpasync16(&Qh[r*72 + kc], qgh + (size_t)r*384 + kc);
        cpasync16(&Ql[r*72 + kc], qgl + (size_t)r*384 + kc);
    }
    for (int c = tid; c < 2048; c += 512) { // K, V: 2048 chunks/plane
        int r = c >> 3, kc = (c & 7) << 3;
        cpasync16(&Kh[r*72 + kc], kgh + (size_t)r*384 + kc);
        cpasync16(&Kl[r*72 + kc], kgl + (size_t)r*384 + kc);
        cpasync16(&Vh[r*72 + kc], vgh + (size_t)r*384 + kc);
    }
    if (tid < 64)
        cpasync16(&mk[tid*4], maskg + b*Lc + tid*4);
    CP_COMMIT(); CP_WAIT0();
    __syncthreads();

    // phase 1: S = qh*kh + ql*kh + qh*kl   (M=64, N=256, logical K=64)
    {
        const int wM = (warp & 1) * 32;
        const int wN = (warp >> 1) * 32;
        float accS[2][2][2][4];
        #pragma unroll
        for (int i=0;i<2;i++) for (int j=0;j<2;j++) for (int s=0;s<2;s++)
            for (int q=0;q<4;q++) accS[i][j][s][q] = 0.f;

        #pragma unroll
        for (int kf = 0; kf < 4; kf++) {
            const int kcol = kf*16 + ((lane >> 4) << 3);
            uint32_t qa[2][4], qb[2][4], ka[2][4], kb[2][4];
            #pragma unroll
            for (int mf = 0; mf < 2; mf++) {
                int ro = (wM + mf*16 + (lane & 15))*72 + kcol;
                LDSM_X4(qa[mf][0], qa[mf][1], qa[mf][2], qa[mf][3], smem_u32(&Qh[ro]));
                LDSM_X4(qb[mf][0], qb[mf][1], qb[mf][2], qb[mf][3], smem_u32(&Ql[ro]));
            }
            #pragma unroll
            for (int tn = 0; tn < 2; tn++) {
                int ro = (wN + tn*16 + (lane & 15))*72 + kcol;
                LDSM_X4(ka[tn][0], ka[tn][1], ka[tn][2], ka[tn][3], smem_u32(&Kh[ro]));
                LDSM_X4(kb[tn][0], kb[tn][1], kb[tn][2], kb[tn][3], smem_u32(&Kl[ro]));
            }
            #pragma unroll
            for (int mf = 0; mf < 2; mf++)
                #pragma unroll
                for (int tn = 0; tn < 2; tn++) {
                    MMA_BF16(accS[mf][tn][0], qa[mf], ka[tn][0], ka[tn][2]);
                    MMA_BF16(accS[mf][tn][1], qa[mf], ka[tn][1], ka[tn][3]);
                    MMA_BF16(accS[mf][tn][0], qb[mf], ka[tn][0], ka[tn][2]);
                    MMA_BF16(accS[mf][tn][1], qb[mf], ka[tn][1], ka[tn][3]);
                    MMA_BF16(accS[mf][tn][0], qa[mf], kb[tn][0], kb[tn][2]);
                    MMA_BF16(accS[mf][tn][1], qa[mf], kb[tn][1], kb[tn][3]);
                }
        }
        __syncthreads();   // Q/K reads done before Ss overlays them

        #pragma unroll
        for (int mf = 0; mf < 2; mf++)
            #pragma unroll
            for (int tn = 0; tn < 2; tn++)
                #pragma unroll
                for (int s = 0; s < 2; s++)
                    #pragma unroll
                    for (int hr = 0; hr < 2; hr++) {
                        int row = wM + mf*16 + (lane >> 2) + hr*8;
                        int col = wN + tn*16 + s*8 + ((lane & 3) << 1);
                        *(float2*)&Ss[row*264 + col] =
                            make_float2(accS[mf][tn][s][hr*2], accS[mf][tn][s][hr*2+1]);
                    }
    }
    __syncthreads();

    // meanv partials (raw scores, diagonal sums)
    {
        int d = tid & 255, half = tid >> 8;
        float s = 0.f;
        #pragma unroll 8
        for (int m = half*32; m < half*32 + 32; m++)
            s += Ss[m*264 + ((q0 + m - d) & 255)];
        int p = (blockIdx.x*2 + h)*2 + half;
        mvp[((size_t)p * Bc + b) * Lc + d] = s * (1.0f/128.0f);
    }
    __syncthreads();

    // softmax -> Ph (single bf16 plane)
    {
        int row = tid >> 3, part = tid & 7;
        float* Sr = &Ss[row*264 + part*32];
        const float* mr = &mk[part*32];
        float mx = -1e30f;
        #pragma unroll 8
        for (int j = 0; j < 32; j++)
            mx = fmaxf(mx, Sr[j] * INV_SQRT_E + mr[j]);
        mx = fmaxf(mx, __shfl_xor_sync(0xffffffffu, mx, 1));
        mx = fmaxf(mx, __shfl_xor_sync(0xffffffffu, mx, 2));
        mx = fmaxf(mx, __shfl_xor_sync(0xffffffffu, mx, 4));
        float sum = 0.f;
        #pragma unroll 8
        for (int j = 0; j < 32; j++) {
            float e = expf(Sr[j] * INV_SQRT_E + mr[j] - mx);
            Sr[j] = e; sum += e;
        }
        sum += __shfl_xor_sync(0xffffffffu, sum, 1);
        sum += __shfl_xor_sync(0xffffffffu, sum, 2);
        sum += __shfl_xor_sync(0xffffffffu, sum, 4);
        float inv = 1.0f / sum;
        bf16* ph = &Ph[row*264 + part*32];
        #pragma unroll 8
        for (int j = 0; j < 32; j++)
            ph[j] = __float2bfloat16(Sr[j] * inv);
    }
    __syncthreads();

    // phase 2: O = Ph @ Vh  (M=64, N=64, K=256), K-split across 2 warp groups
    {
        const int w8  = warp & 7;
        const int kh  = warp >> 3;
        const int wM2 = (w8 & 1) * 32;
        const int wN2 = ((w8 >> 1) & 3) * 16;
        float o[2][2][4];
        #pragma unroll
        for (int i=0;i<2;i++) for (int s=0;s<2;s++) for (int q=0;q<4;q++) o[i][s][q]=0.f;

        for (int kf = kh*8; kf < kh*8 + 8; kf++) {
            uint32_t ah[2][4], bh[4];
            #pragma unroll
            for (int mf = 0; mf < 2; mf++) {
                uint32_t ro = (wM2 + mf*16 + (lane & 15))*264 + kf*16 + ((lane >> 4) << 3);
                LDSM_X4(ah[mf][0], ah[mf][1], ah[mf][2], ah[mf][3], smem_u32(&Ph[ro]));
            }
            {
                uint32_t vo = (kf*16 + (lane & 15))*72 + wN2 + ((lane >> 4) << 3);
                LDSM_X4_T(bh[0], bh[1], bh[2], bh[3], smem_u32(&Vh[vo]));
            }
            #pragma unroll
            for (int mf = 0; mf < 2; mf++) {
                MMA_BF16(o[mf][0], ah[mf], bh[0], bh[1]);
                MMA_BF16(o[mf][1], ah[mf], bh[2], bh[3]);
            }
        }
        __syncthreads();    // Ss free; reuse for partial reduction
        float* Os = Ss;
        if (kh == 1) {
            #pragma unroll
            for (int mf = 0; mf < 2; mf++)
                #pragma unroll
                for (int s = 0; s < 2; s++)
                    #pragma unroll
                    for (int hr = 0; hr < 2; hr++) {
                        int rl = wM2 + mf*16 + (lane >> 2) + hr*8;
                        int cl = wN2 + s*8 + ((lane & 3) << 1);
                        *(float2*)&Os[rl*264 + cl] =
                            make_float2(o[mf][s][hr*2], o[mf][s][hr*2+1]);
                    }
        }
        __syncthreads();
        if (kh == 0) {
            #pragma unroll
            for (int mf = 0; mf < 2; mf++)
                #pragma unroll
                for (int s = 0; s < 2; s++)
                    #pragma unroll
                    for (int hr = 0; hr < 2; hr++) {
                        int rl = wM2 + mf*16 + (lane >> 2) + hr*8;
                        int cl = wN2 + s*8 + ((lane & 3) << 1);
                        float2 p = *(float2*)&Os[rl*264 + cl];
                        int row = q0 + rl;
                        int col = h*64 + cl;
                        *(float2*)&sp[((size_t)b*Lc + row)*Dc + col] =
                            make_float2(o[mf][s][hr*2] + p.x, o[mf][s][hr*2+1] + p.y);
                    }
        }
    }
}

// ---------------- small kernels ----------------
__global__ void build_x_kernel(const int* __restrict__ paths,
                               const float* __restrict__ ego,
                               const float* __restrict__ pos)
{
    int bl = blockIdx.x, c = threadIdx.x;
    int p = paths[bl], l = bl & (Lc - 1);
    float v = ego[(size_t)p * Dc + c] + pos[l * Dc + c];
    g_x[(size_t)bl * Dc + c] = v;
    bf16 h, lo; split_hl(v, h, lo);
    g_xh[(size_t)bl * Dc + c] = h;
    g_xl[(size_t)bl * Dc + c] = lo;
    if (c == 0) g_mask[bl] = (p < NUM_TOTAL_C) ? 0.f : -10000.f;
}

// circulant band filter -> h/l planes
__global__ void buildC_kernel(int left, int right)
{
    __shared__ float cs[Lc];
    int n = blockIdx.x, m = threadIdx.x;
    double s = 0.0;
    for (int f = left; f < right; f++) {
        double w;
        if (f == 0)           w = 1.0;
        else if (f == Lc/2)   w = (m & 1) ? -1.0 : 1.0;
        else                  w = 2.0 * cos(2.0 * M_PI * (double)f * (double)m / (double)Lc);
        s += w;
    }
    cs[m] = (float)(s / (double)Lc);
    __syncthreads();
    float v = cs[(n - m + Lc) & (Lc - 1)];
    bf16 h, l; split_hl(v, h, l);
    g_Cmh[n * Lc + m] = h;
    g_Cml[n * Lc + m] = l;
}

// all weights -> h/l planes; QKV concatenated along N
__global__ void convW_kernel(const float* __restrict__ Wq, const float* __restrict__ Wk,
                             const float* __restrict__ Wv, const float* __restrict__ Wp,
                             const float* __restrict__ F1, const float* __restrict__ F2)
{
    int idx = blockIdx.x * 256 + threadIdx.x;      // 0..131071
    float v; int dst;
    if (idx < 49152) {
        int k = idx / 384, c = idx - k*384;
        int w = c >> 7, n = c & 127;
        const float* src = (w == 0 ? Wq : w == 1 ? Wk : Wv);
        v = src[k*128 + n];
        dst = idx;                                  // [k][c] ld=384
    } else if (idx < 65536) {
        v = Wp[idx - 49152]; dst = idx;
    } else if (idx < 98304) {
        v = F1[idx - 65536]; dst = idx;
    } else {
        v = F2[idx - 98304]; dst = idx;
    }
    bf16 h, l; split_hl(v, h, l);
    g_Wh[dst] = h;
    g_Wl[dst] = l;
}

__global__ void meanred_kernel()
{
    int b = blockIdx.x, d = threadIdx.x;
    float s = 0.f;
    #pragma unroll
    for (int p = 0; p < 16; p++) s += g_mvp[((size_t)p * Bc + b) * Lc + d];
    g_mv[b * Lc + d] = s;
}

__global__ void stats_kernel()
{
    __shared__ float sv[Lc];
    __shared__ int   si[Lc];
    __shared__ int   dls[TOPKc];
    int t = threadIdx.x;

    float s = 0.f;
    for (int b = 0; b < Bc; b++) s += g_mv[b * Lc + t];
    float my = s * (1.0f / (float)Bc);

    for (int it = 0; it < TOPKc; it++) {
        sv[t] = my; si[t] = t;
        __syncthreads();
        for (int st = 128; st > 0; st >>= 1) {
            if (t < st) {
                float v2 = sv[t + st]; int i2 = si[t + st];
                if (v2 > sv[t] || (v2 == sv[t] && i2 < si[t])) { sv[t] = v2; si[t] = i2; }
            }
            __syncthreads();
        }
        int win = si[0];
        if (t == 0) { g_delays[it] = win; dls[it] = win; }
        __syncthreads();
        if (t == win) my = -INFINITY;
    }

    float w[TOPKc];
    float mx = -1e30f;
    #pragma unroll
    for (int i = 0; i < TOPKc; i++) {
        w[i] = g_mv[t * Lc + dls[i]];
        mx = fmaxf(mx, w[i]);
    }
    float sm = 0.f;
    #pragma unroll
    for (int i = 0; i < TOPKc; i++) { w[i] = expf(w[i] - mx); sm += w[i]; }
    float inv = 1.0f / sm;
    #pragma unroll
    for (int i = 0; i < TOPKc; i++) g_w[t * TOPKc + i] = w[i] * inv;
}

// 0.9*freq + 0.1*spatial -> h/l planes
__global__ void combine_kernel()
{
    int bl = blockIdx.x, c = threadIdx.x;
    int b = bl >> 8, l = bl & 255;
    __shared__ float w[TOPKc];
    __shared__ int   dl[TOPKc];
    if (c < TOPKc) { w[c] = g_w[b * TOPKc + c]; dl[c] = g_delays[c]; }
    __syncthreads();
    float f = 0.f;
    #pragma unroll
    for (int t = 0; t < TOPKc; t++) {
        int ls = (l + dl[t]) & 255;
        f += w[t] * g_vb[((size_t)b * Lc + ls) * Dc + c];
    }
    float v = 0.9f * f + 0.1f * g_sp[(size_t)bl * Dc + c];
    bf16 h, lo; split_hl(v, h, lo);
    g_oh[(size_t)bl * Dc + c] = h;
    g_ol[(size_t)bl * Dc + c] = lo;
}

__global__ void gather_kernel(const int* __restrict__ lengths, float* __restrict__ out)
{
    int b = blockIdx.x, c = threadIdx.x;
    int l = lengths[b] - 1;
    out[b * Dc + c] = g_x[((size_t)b * Lc + l) * Dc + c];
}

// ---------------- host side ----------------
static inline void mma_go(const bf16* Ah, const bf16* Al,
                          const bf16* Bh, const bf16* Bl, float* C,
                          int M, int N, int K, int lda, int ldb, int ldc,
                          int batch, long sA, long sB, long sC,
                          const float* R, int ldr, int fuse,
                          int emit, bf16* Oh, bf16* Ol)
{
    dim3 grid(M / 128, N / 128, batch);
    mma_kernel<<<grid, 256, MMA_SMEM_BYTES>>>(Ah, Al, Bh, Bl, C, K, lda, ldb, ldc,
        sA, sB, sC, R, ldr, fuse, emit, Oh, Ol);
}

extern "C" void kernel_launch(void* const* d_in, const int* in_sizes, int n_in,
                              void* d_out, int out_size)
{
    (void)in_sizes; (void)n_in; (void)out_size;
    const int*   paths   = (const int*)  d_in[0];
    const int*   lengths = (const int*)  d_in[1];
    const float* ego     = (const float*)d_in[4];
    const float* pos     = (const float*)d_in[5];
    const float* Wq      = (const float*)d_in[6];
    const float* Wk      = (const float*)d_in[7];
    const float* Wv      = (const float*)d_in[8];
    const float* Wp      = (const float*)d_in[9];
    const float* F1      = (const float*)d_in[10];
    const float* F2      = (const float*)d_in[11];
    float* out = (float*)d_out;

    float *px, *pmask, *pvb, *psp, *pmvp;
    bf16 *pxh, *pxl, *pxth, *pxtl, *pqkvh, *pqkvl, *poh, *pol, *pah, *pal,
         *phh, *phl, *pCmh, *pCml, *pWh, *pWl;
    cudaGetSymbolAddress((void**)&px,    g_x);
    cudaGetSymbolAddress((void**)&pmask, g_mask);
    cudaGetSymbolAddress((void**)&pvb,   g_vb);
    cudaGetSymbolAddress((void**)&psp,   g_sp);
    cudaGetSymbolAddress((void**)&pmvp,  g_mvp);
    cudaGetSymbolAddress((void**)&pxh,   g_xh);
    cudaGetSymbolAddress((void**)&pxl,   g_xl);
    cudaGetSymbolAddress((void**)&pxth,  g_xth);
    cudaGetSymbolAddress((void**)&pxtl,  g_xtl);
    cudaGetSymbolAddress((void**)&pqkvh, g_qkvh);
    cudaGetSymbolAddress((void**)&pqkvl, g_qkvl);
    cudaGetSymbolAddress((void**)&poh,   g_oh);
    cudaGetSymbolAddress((void**)&pol,   g_ol);
    cudaGetSymbolAddress((void**)&pah,   g_ah);
    cudaGetSymbolAddress((void**)&pal,   g_al);
    cudaGetSymbolAddress((void**)&phh,   g_hh);
    cudaGetSymbolAddress((void**)&phl,   g_hl);
    cudaGetSymbolAddress((void**)&pCmh,  g_Cmh);
    cudaGetSymbolAddress((void**)&pCml,  g_Cml);
    cudaGetSymbolAddress((void**)&pWh,   g_Wh);
    cudaGetSymbolAddress((void**)&pWl,   g_Wl);

    // No static guards (harness contract): set attributes unconditionally.
    cudaFuncSetAttribute(fattn_kernel,
                         cudaFuncAttributeMaxDynamicSharedMemorySize, FA_SMEM);
    cudaFuncSetAttribute(mma_kernel,
                         cudaFuncAttributeMaxDynamicSharedMemorySize, MMA_SMEM_BYTES);

    const int  BL = Bc * Lc;
    const long LD = (long)Lc * Dc;

    build_x_kernel<<<BL, Dc>>>(paths, ego, pos);

    const int lefts[NLc]  = {51, 0};
    const int rights[NLc] = {129, 78};

    for (int k = 0; k < NLc; k++) {
        buildC_kernel<<<Lc, Lc>>>(lefts[k], rights[k]);
        convW_kernel<<<512, 256>>>(Wq + (size_t)k*Dc*Dc, Wk + (size_t)k*Dc*Dc,
                                   Wv + (size_t)k*Dc*Dc, Wp + (size_t)k*Dc*Dc,
                                   F1 + (size_t)k*Dc*2*Dc, F2 + (size_t)k*2*Dc*Dc);

        // xt = Cm @ x (batched over b): A=Cm planes [256,256], B=x planes [256,128]
        mma_go(pCmh, pCml, pxh, pxl, psp /*unused*/,
               Lc, Dc, Lc, Lc, Dc, Dc,
               Bc, 0, LD, LD, nullptr, 0, 0, 2, pxth, pxtl);

        // qkv = xt @ [Wq|Wk|Wv]  (N=384, one launch)
        mma_go(pxth, pxtl, pWh + WO_QKV, pWl + WO_QKV, psp /*unused*/,
               BL, 3*Dc, Dc, Dc, 3*Dc, 3*Dc,
               1, 0, 0, 0, nullptr, 0, 0, 2, pqkvh, pqkvl);

        // vb = x @ Wv (fp32; Wv = QKV cols 256..383)
        mma_go(pxh, pxl, pWh + WO_QKV + 256, pWl + WO_QKV + 256, pvb,
               BL, Dc, Dc, Dc, 3*Dc, Dc,
               1, 0, 0, 0, nullptr, 0, 0, 1, nullptr, nullptr);

        // fused attention: S + meanv partials + softmax + P@V
        {
            dim3 grid(4, Bc * 2);
            fattn_kernel<<<grid, 512, FA_SMEM>>>(pqkvh, pqkvl, pmask, psp, pmvp);
        }
        meanred_kernel<<<Bc, Lc>>>();
        stats_kernel<<<1, Lc>>>();

        combine_kernel<<<BL, Dc>>>();

        // a = o @ Wp + x
        mma_go(poh, pol, pWh + WO_P, pWl + WO_P, psp /*unused*/,
               BL, Dc, Dc, Dc, Dc, Dc,
               1, 0, 0, 0, px, Dc, 1, 2, pah, pal);

        // h = GELU(a @ F1)  (N=256)
        mma_go(pah, pal, pWh + WO_F1, pWl + WO_F1, psp /*unused*/,
               BL, 2*Dc, Dc, Dc, 2*Dc, 2*Dc,
               1, 0, 0, 0, nullptr, 0, 2, 2, phh, phl);

        // x = h @ F2  (K=256) -> fp32 x + planes
        mma_go(phh, phl, pWh + WO_F2, pWl + WO_F2, px,
               BL, Dc, 2*Dc, 2*Dc, Dc, Dc,
               1, 0, 0, 0, nullptr, 0, 0, 3, pxh, pxl);
    }

    gather_kernel<<<Bc, Dc>>>(lengths, out);
}

// round 13
// speedup vs baseline: 1.9491x; 1.1651x over previous
#include <cuda_runtime.h>
#include <cuda_bf16.h>
#include <math.h>
#include <stdint.h>

#ifndef M_PI
#define M_PI 3.14159265358979323846
#endif

#define Bc 256
#define Lc 256
#define Dc 128
#define NLc 2
#define TOPKc 5
#define NUM_TOTAL_C 100000
#define INV_SQRT_E 0.125f
#define INV_SQRT_2F 0.70710678118654752440f

typedef __nv_bfloat16 bf16;

// ---------------- scratch ----------------
__device__ float g_x   [Bc*Lc*Dc];
__device__ float g_mask[Bc*Lc];
__device__ float g_vb  [Bc*Lc*Dc];
__device__ float g_sp  [Bc*Lc*Dc];
__device__ float g_mv  [Bc*Lc];
__device__ float g_mvp [16*Bc*Lc];
__device__ int   g_delays[TOPKc];
__device__ float g_w   [Bc*TOPKc];
__device__ float g_cs  [Lc];

// h/l plane pairs (logical K, no tripling in memory)
__device__ bf16 g_xh  [Bc*Lc*Dc];
__device__ bf16 g_xl  [Bc*Lc*Dc];
__device__ bf16 g_xth [Bc*Lc*Dc];
__device__ bf16 g_xtl [Bc*Lc*Dc];
__device__ bf16 g_qkvh[(size_t)Bc*Lc*3*Dc];
__device__ bf16 g_qkvl[(size_t)Bc*Lc*3*Dc];
__device__ bf16 g_oh  [Bc*Lc*Dc];
__device__ bf16 g_ol  [Bc*Lc*Dc];
__device__ bf16 g_ah  [Bc*Lc*Dc];
__device__ bf16 g_al  [Bc*Lc*Dc];
__device__ bf16 g_hh  [Bc*Lc*2*Dc];
__device__ bf16 g_hl  [Bc*Lc*2*Dc];
__device__ bf16 g_Cmh [Lc*Lc];
__device__ bf16 g_Cml [Lc*Lc];
__device__ bf16 g_Wh  [131072];    // [QKV 0..49151][Wp 49152..][F1 65536..][F2 98304..]
__device__ bf16 g_Wl  [131072];

#define WO_QKV 0
#define WO_P   49152
#define WO_F1  65536
#define WO_F2  98304

// ---------------- PTX helpers ----------------
__device__ __forceinline__ uint32_t smem_u32(const void* p) {
    return (uint32_t)__cvta_generic_to_shared(p);
}
__device__ __forceinline__ void cpasync16(void* sp, const void* gp) {
    asm volatile("cp.async.cg.shared.global [%0], [%1], 16;"
                 :: "r"(smem_u32(sp)), "l"(gp));
}
#define CP_COMMIT() asm volatile("cp.async.commit_group;")
#define CP_WAIT0()  asm volatile("cp.async.wait_group 0;")
#define CP_WAIT1()  asm volatile("cp.async.wait_group 1;")

#define LDSM_X4(r0,r1,r2,r3,addr) \
    asm volatile("ldmatrix.sync.aligned.m8n8.x4.shared.b16 {%0,%1,%2,%3}, [%4];" \
        : "=r"(r0),"=r"(r1),"=r"(r2),"=r"(r3) : "r"(addr))
#define LDSM_X4_T(r0,r1,r2,r3,addr) \
    asm volatile("ldmatrix.sync.aligned.m8n8.x4.trans.shared.b16 {%0,%1,%2,%3}, [%4];" \
        : "=r"(r0),"=r"(r1),"=r"(r2),"=r"(r3) : "r"(addr))

#define MMA_BF16(d, a, b0v, b1v) \
    asm volatile("mma.sync.aligned.m16n8k16.row.col.f32.bf16.bf16.f32 " \
        "{%0,%1,%2,%3}, {%4,%5,%6,%7}, {%8,%9}, {%0,%1,%2,%3};" \
        : "+f"(d[0]), "+f"(d[1]), "+f"(d[2]), "+f"(d[3]) \
        : "r"(a[0]), "r"(a[1]), "r"(a[2]), "r"(a[3]), "r"(b0v), "r"(b1v))

__device__ __forceinline__ void split_hl(float v, bf16& h, bf16& l) {
    h = __float2bfloat16(v);
    l = __float2bfloat16(v - __bfloat162float(h));
}

// ---------------- plane-format 3-term tensor GEMM, 3-stage pipeline ----------------
// C = Ah*Bh + Al*Bh + Ah*Bl   (logical K; A [M,K], B [K,N] row-major, NN)
// emit: 1 = fp32 C; 2 = h/l planes Oh/Ol (same ldc).  fuse: 0/1(+R)/2(GELU).
// CTA tile 128x128, BK=32, 3-stage cp.async.
#define MMA_SE 18944                       // elements per stage
#define MMA_SMEM_BYTES (3*MMA_SE*2)        // 113664 bytes

__global__ __launch_bounds__(256, 2)
void mma_kernel(const bf16* __restrict__ Ah, const bf16* __restrict__ Al,
                const bf16* __restrict__ Bh, const bf16* __restrict__ Bl,
                float* __restrict__ C,
                int K, int lda, int ldb, int ldc,
                long sA, long sB, long sC,
                const float* __restrict__ R, int ldr, int fuse,
                int emit, bf16* __restrict__ Oh, bf16* __restrict__ Ol)
{
    extern __shared__ bf16 smp[];
    const int tid  = threadIdx.x;
    const int warp = tid >> 5;
    const int lane = tid & 31;
    const int warpM0 = (warp & 1) * 64;
    const int warpN0 = (warp >> 1) * 32;

    const int z = blockIdx.z;
    Ah += (size_t)z * sA;  Al += (size_t)z * sA;
    Bh += (size_t)z * sB;  Bl += (size_t)z * sB;
    const long co = (size_t)z * sC;

    const int m0 = blockIdx.x * 128;
    const int n0 = blockIdx.y * 128;

    auto load_tiles = [&](int st, int k0) {
        bf16* ah_s = smp + st * MMA_SE;
        bf16* al_s = ah_s + 5120;
        bf16* bh_s = ah_s + 10240;
        bf16* bl_s = ah_s + 14592;
        #pragma unroll
        for (int i = 0; i < 2; i++) {
            int c = tid + i * 256;
            int row = c >> 2, kc = (c & 3) << 3;
            cpasync16(ah_s + row*40 + kc, Ah + (size_t)(m0 + row) * lda + k0 + kc);
            cpasync16(al_s + row*40 + kc, Al + (size_t)(m0 + row) * lda + k0 + kc);
        }
        #pragma unroll
        for (int i = 0; i < 2; i++) {
            int c = tid + i * 256;
            int row = c >> 4, nc = (c & 15) << 3;
            cpasync16(bh_s + row*136 + nc, Bh + (size_t)(k0 + row) * ldb + n0 + nc);
            cpasync16(bl_s + row*136 + nc, Bl + (size_t)(k0 + row) * ldb + n0 + nc);
        }
    };

    float acc[4][2][2][4];
    #pragma unroll
    for (int i = 0; i < 4; i++)
        #pragma unroll
        for (int j = 0; j < 2; j++)
            #pragma unroll
            for (int s = 0; s < 2; s++)
                #pragma unroll
                for (int q = 0; q < 4; q++) acc[i][j][s][q] = 0.f;

    const int nk = K / 32;
    load_tiles(0, 0);
    CP_COMMIT();
    if (nk > 1) { load_tiles(1, 32); CP_COMMIT(); }

    for (int kt = 0; kt < nk; kt++) {
        if (kt + 1 < nk) CP_WAIT1(); else CP_WAIT0();
        __syncthreads();
        if (kt + 2 < nk) { load_tiles((kt + 2) % 3, (kt + 2) * 32); CP_COMMIT(); }

        bf16* ah_s = smp + (kt % 3) * MMA_SE;
        bf16* al_s = ah_s + 5120;
        bf16* bh_s = ah_s + 10240;
        bf16* bl_s = ah_s + 14592;

        #pragma unroll
        for (int ks = 0; ks < 2; ks++) {
            const int acol = ks*16 + ((lane >> 4) << 3);
            uint32_t ah[4][4], bh[2][4];
            #pragma unroll
            for (int tm = 0; tm < 4; tm++) {
                uint32_t ad = smem_u32(&ah_s[(warpM0 + tm*16 + (lane & 15))*40 + acol]);
                LDSM_X4(ah[tm][0], ah[tm][1], ah[tm][2], ah[tm][3], ad);
            }
            #pragma unroll
            for (int tn = 0; tn < 2; tn++) {
                uint32_t ad = smem_u32(&bh_s[(ks*16 + (lane & 15))*136
                                             + warpN0 + tn*16 + ((lane >> 4) << 3)]);
                LDSM_X4_T(bh[tn][0], bh[tn][1], bh[tn][2], bh[tn][3], ad);
            }
            // term 1: ah * bh
            #pragma unroll
            for (int tm = 0; tm < 4; tm++)
                #pragma unroll
                for (int tn = 0; tn < 2; tn++) {
                    MMA_BF16(acc[tm][tn][0], ah[tm], bh[tn][0], bh[tn][1]);
                    MMA_BF16(acc[tm][tn][1], ah[tm], bh[tn][2], bh[tn][3]);
                }
            // term 2: al * bh
            {
                uint32_t xf[4][4];
                #pragma unroll
                for (int tm = 0; tm < 4; tm++) {
                    uint32_t ad = smem_u32(&al_s[(warpM0 + tm*16 + (lane & 15))*40 + acol]);
                    LDSM_X4(xf[tm][0], xf[tm][1], xf[tm][2], xf[tm][3], ad);
                }
                #pragma unroll
                for (int tm = 0; tm < 4; tm++)
                    #pragma unroll
                    for (int tn = 0; tn < 2; tn++) {
                        MMA_BF16(acc[tm][tn][0], xf[tm], bh[tn][0], bh[tn][1]);
                        MMA_BF16(acc[tm][tn][1], xf[tm], bh[tn][2], bh[tn][3]);
                    }
            }
            // term 3: ah * bl
            {
                uint32_t bl[2][4];
                #pragma unroll
                for (int tn = 0; tn < 2; tn++) {
                    uint32_t ad = smem_u32(&bl_s[(ks*16 + (lane & 15))*136
                                                 + warpN0 + tn*16 + ((lane >> 4) << 3)]);
                    LDSM_X4_T(bl[tn][0], bl[tn][1], bl[tn][2], bl[tn][3], ad);
                }
                #pragma unroll
                for (int tm = 0; tm < 4; tm++)
                    #pragma unroll
                    for (int tn = 0; tn < 2; tn++) {
                        MMA_BF16(acc[tm][tn][0], ah[tm], bl[tn][0], bl[tn][1]);
                        MMA_BF16(acc[tm][tn][1], ah[tm], bl[tn][2], bl[tn][3]);
                    }
            }
        }
    }

    // epilogue
    #pragma unroll
    for (int tm = 0; tm < 4; tm++)
        #pragma unroll
        for (int tn = 0; tn < 2; tn++)
            #pragma unroll
            for (int s = 0; s < 2; s++) {
                int col = n0 + warpN0 + tn*16 + s*8 + ((lane & 3) << 1);
                float* cc = acc[tm][tn][s];
                #pragma unroll
                for (int hr = 0; hr < 2; hr++) {
                    int row = m0 + warpM0 + tm*16 + (lane >> 2) + hr*8;
                    float2 v = make_float2(cc[hr*2 + 0], cc[hr*2 + 1]);
                    if (fuse == 1) {
                        float2 r = *(const float2*)&R[(size_t)row * ldr + col];
                        v.x += r.x; v.y += r.y;
                    } else if (fuse == 2) {
                        v.x = v.x * 0.5f * (1.0f + erff(v.x * INV_SQRT_2F));
                        v.y = v.y * 0.5f * (1.0f + erff(v.y * INV_SQRT_2F));
                    }
                    size_t ci = co + (size_t)row * ldc + col;
                    if (emit & 1) *(float2*)&C[ci] = v;
                    if (emit & 2) {
                        bf16 hx, lx, hy, ly;
                        split_hl(v.x, hx, lx);
                        split_hl(v.y, hy, ly);
                        __nv_bfloat162 hv; hv.x = hx; hv.y = hy;
                        __nv_bfloat162 lv; lv.x = lx; lv.y = ly;
                        *(__nv_bfloat162*)&Oh[ci] = hv;
                        *(__nv_bfloat162*)&Ol[ci] = lv;
                    }
                }
            }
}

// ---------------- fused attention (plane inputs, 512 threads) ----------------
#define FA_VH 0
#define FA_QH 36864
#define FA_QL 46080
#define FA_KH 55296
#define FA_KL 92160
#define FA_SS 36864     /* overlays Q/K after phase 1 */
#define FA_PH 129024
#define FA_MK 162816
#define FA_SMEM 163840

__global__ __launch_bounds__(512, 1)
void fattn_kernel(const bf16* __restrict__ qkvh, const bf16* __restrict__ qkvl,
                  const float* __restrict__ maskg,
                  float* __restrict__ sp, float* __restrict__ mvp)
{
    extern __shared__ char sm[];
    bf16*  Vh = (bf16*) (sm + FA_VH);      // [256][72]
    bf16*  Qh = (bf16*) (sm + FA_QH);      // [64][72]
    bf16*  Ql = (bf16*) (sm + FA_QL);
    bf16*  Kh = (bf16*) (sm + FA_KH);      // [256][72]
    bf16*  Kl = (bf16*) (sm + FA_KL);
    float* Ss = (float*)(sm + FA_SS);      // [64][264] (after phase 1)
    bf16*  Ph = (bf16*) (sm + FA_PH);      // [64][264]
    float* mk = (float*)(sm + FA_MK);      // [256]

    const int tid = threadIdx.x, warp = tid >> 5, lane = tid & 31;
    const int q0 = blockIdx.x * 64;
    const int b  = blockIdx.y >> 1, h = blockIdx.y & 1;

    // prologue loads
    const bf16* qgh = qkvh + ((size_t)(b*Lc + q0)) * 384 + h*64;
    const bf16* qgl = qkvl + ((size_t)(b*Lc + q0)) * 384 + h*64;
    const bf16* kgh = qkvh + ((size_t)(b*Lc)) * 384 + 128 + h*64;
    const bf16* kgl = qkvl + ((size_t)(b*Lc)) * 384 + 128 + h*64;
    const bf16* vgh = qkvh + ((size_t)(b*Lc)) * 384 + 256 + h*64;

    {
        int c = tid;                        // Q: 512 chunks/plane
        int r = c >> 3, kc = (c & 7) << 3;
        cpasync16(&Qh[r*72 + kc], qgh + (size_t)r*384 + kc);
        cpasync16(&Ql[r*72 + kc], qgl + (size_t)r*384 + kc);
    }
    for (int c = tid; c < 2048; c += 512) { // K, V: 2048 chunks/plane
        int r = c >> 3, kc = (c & 7) << 3;
        cpasync16(&Kh[r*72 + kc], kgh + (size_t)r*384 + kc);
        cpasync16(&Kl[r*72 + kc], kgl + (size_t)r*384 + kc);
        cpasync16(&Vh[r*72 + kc], vgh + (size_t)r*384 + kc);
    }
    if (tid < 64)
        cpasync16(&mk[tid*4], maskg + b*Lc + tid*4);
    CP_COMMIT(); CP_WAIT0();
    __syncthreads();

    // phase 1: S = qh*kh + ql*kh + qh*kl   (M=64, N=256, logical K=64)
    {
        const int wM = (warp & 1) * 32;
        const int wN = (warp >> 1) * 32;
        float accS[2][2][2][4];
        #pragma unroll
        for (int i=0;i<2;i++) for (int j=0;j<2;j++) for (int s=0;s<2;s++)
            for (int q=0;q<4;q++) accS[i][j][s][q] = 0.f;

        #pragma unroll
        for (int kf = 0; kf < 4; kf++) {
            const int kcol = kf*16 + ((lane >> 4) << 3);
            uint32_t qa[2][4], qb[2][4], ka[2][4], kb[2][4];
            #pragma unroll
            for (int mf = 0; mf < 2; mf++) {
                int ro = (wM + mf*16 + (lane & 15))*72 + kcol;
                LDSM_X4(qa[mf][0], qa[mf][1], qa[mf][2], qa[mf][3], smem_u32(&Qh[ro]));
                LDSM_X4(qb[mf][0], qb[mf][1], qb[mf][2], qb[mf][3], smem_u32(&Ql[ro]));
            }
            #pragma unroll
            for (int tn = 0; tn < 2; tn++) {
                int ro = (wN + tn*16 + (lane & 15))*72 + kcol;
                LDSM_X4(ka[tn][0], ka[tn][1], ka[tn][2], ka[tn][3], smem_u32(&Kh[ro]));
                LDSM_X4(kb[tn][0], kb[tn][1], kb[tn][2], kb[tn][3], smem_u32(&Kl[ro]));
            }
            #pragma unroll
            for (int mf = 0; mf < 2; mf++)
                #pragma unroll
                for (int tn = 0; tn < 2; tn++) {
                    MMA_BF16(accS[mf][tn][0], qa[mf], ka[tn][0], ka[tn][2]);
                    MMA_BF16(accS[mf][tn][1], qa[mf], ka[tn][1], ka[tn][3]);
                    MMA_BF16(accS[mf][tn][0], qb[mf], ka[tn][0], ka[tn][2]);
                    MMA_BF16(accS[mf][tn][1], qb[mf], ka[tn][1], ka[tn][3]);
                    MMA_BF16(accS[mf][tn][0], qa[mf], kb[tn][0], kb[tn][2]);
                    MMA_BF16(accS[mf][tn][1], qa[mf], kb[tn][1], kb[tn][3]);
                }
        }
        __syncthreads();   // Q/K reads done before Ss overlays them

        #pragma unroll
        for (int mf = 0; mf < 2; mf++)
            #pragma unroll
            for (int tn = 0; tn < 2; tn++)
                #pragma unroll
                for (int s = 0; s < 2; s++)
                    #pragma unroll
                    for (int hr = 0; hr < 2; hr++) {
                        int row = wM + mf*16 + (lane >> 2) + hr*8;
                        int col = wN + tn*16 + s*8 + ((lane & 3) << 1);
                        *(float2*)&Ss[row*264 + col] =
                            make_float2(accS[mf][tn][s][hr*2], accS[mf][tn][s][hr*2+1]);
                    }
    }
    __syncthreads();

    // meanv partials (raw scores, diagonal sums)
    {
        int d = tid & 255, half = tid >> 8;
        float s = 0.f;
        #pragma unroll 8
        for (int m = half*32; m < half*32 + 32; m++)
            s += Ss[m*264 + ((q0 + m - d) & 255)];
        int p = (blockIdx.x*2 + h)*2 + half;
        mvp[((size_t)p * Bc + b) * Lc + d] = s * (1.0f/128.0f);
    }
    __syncthreads();

    // softmax -> Ph (single bf16 plane)
    {
        int row = tid >> 3, part = tid & 7;
        float* Sr = &Ss[row*264 + part*32];
        const float* mr = &mk[part*32];
        float mx = -1e30f;
        #pragma unroll 8
        for (int j = 0; j < 32; j++)
            mx = fmaxf(mx, Sr[j] * INV_SQRT_E + mr[j]);
        mx = fmaxf(mx, __shfl_xor_sync(0xffffffffu, mx, 1));
        mx = fmaxf(mx, __shfl_xor_sync(0xffffffffu, mx, 2));
        mx = fmaxf(mx, __shfl_xor_sync(0xffffffffu, mx, 4));
        float sum = 0.f;
        #pragma unroll 8
        for (int j = 0; j < 32; j++) {
            float e = expf(Sr[j] * INV_SQRT_E + mr[j] - mx);
            Sr[j] = e; sum += e;
        }
        sum += __shfl_xor_sync(0xffffffffu, sum, 1);
        sum += __shfl_xor_sync(0xffffffffu, sum, 2);
        sum += __shfl_xor_sync(0xffffffffu, sum, 4);
        float inv = 1.0f / sum;
        bf16* ph = &Ph[row*264 + part*32];
        #pragma unroll 8
        for (int j = 0; j < 32; j++)
            ph[j] = __float2bfloat16(Sr[j] * inv);
    }
    __syncthreads();

    // phase 2: O = Ph @ Vh  (M=64, N=64, K=256), K-split across 2 warp groups
    {
        const int w8  = warp & 7;
        const int kh  = warp >> 3;
        const int wM2 = (w8 & 1) * 32;
        const int wN2 = ((w8 >> 1) & 3) * 16;
        float o[2][2][4];
        #pragma unroll
        for (int i=0;i<2;i++) for (int s=0;s<2;s++) for (int q=0;q<4;q++) o[i][s][q]=0.f;

        for (int kf = kh*8; kf < kh*8 + 8; kf++) {
            uint32_t ah[2][4], bh[4];
            #pragma unroll
            for (int mf = 0; mf < 2; mf++) {
                uint32_t ro = (wM2 + mf*16 + (lane & 15))*264 + kf*16 + ((lane >> 4) << 3);
                LDSM_X4(ah[mf][0], ah[mf][1], ah[mf][2], ah[mf][3], smem_u32(&Ph[ro]));
            }
            {
                uint32_t vo = (kf*16 + (lane & 15))*72 + wN2 + ((lane >> 4) << 3);
                LDSM_X4_T(bh[0], bh[1], bh[2], bh[3], smem_u32(&Vh[vo]));
            }
            #pragma unroll
            for (int mf = 0; mf < 2; mf++) {
                MMA_BF16(o[mf][0], ah[mf], bh[0], bh[1]);
                MMA_BF16(o[mf][1], ah[mf], bh[2], bh[3]);
            }
        }
        __syncthreads();    // Ss free; reuse for partial reduction
        float* Os = Ss;
        if (kh == 1) {
            #pragma unroll
            for (int mf = 0; mf < 2; mf++)
                #pragma unroll
                for (int s = 0; s < 2; s++)
                    #pragma unroll
                    for (int hr = 0; hr < 2; hr++) {
                        int rl = wM2 + mf*16 + (lane >> 2) + hr*8;
                        int cl = wN2 + s*8 + ((lane & 3) << 1);
                        *(float2*)&Os[rl*264 + cl] =
                            make_float2(o[mf][s][hr*2], o[mf][s][hr*2+1]);
                    }
        }
        __syncthreads();
        if (kh == 0) {
            #pragma unroll
            for (int mf = 0; mf < 2; mf++)
                #pragma unroll
                for (int s = 0; s < 2; s++)
                    #pragma unroll
                    for (int hr = 0; hr < 2; hr++) {
                        int rl = wM2 + mf*16 + (lane >> 2) + hr*8;
                        int cl = wN2 + s*8 + ((lane & 3) << 1);
                        float2 p = *(float2*)&Os[rl*264 + cl];
                        int row = q0 + rl;
                        int col = h*64 + cl;
                        *(float2*)&sp[((size_t)b*Lc + row)*Dc + col] =
                            make_float2(o[mf][s][hr*2] + p.x, o[mf][s][hr*2+1] + p.y);
                    }
        }
    }
}

// ---------------- small kernels ----------------
__global__ void build_x_kernel(const int* __restrict__ paths,
                               const float* __restrict__ ego,
                               const float* __restrict__ pos)
{
    int bl = blockIdx.x, c = threadIdx.x;
    int p = paths[bl], l = bl & (Lc - 1);
    float v = ego[(size_t)p * Dc + c] + pos[l * Dc + c];
    g_x[(size_t)bl * Dc + c] = v;
    bf16 h, lo; split_hl(v, h, lo);
    g_xh[(size_t)bl * Dc + c] = h;
    g_xl[(size_t)bl * Dc + c] = lo;
    if (c == 0) g_mask[bl] = (p < NUM_TOTAL_C) ? 0.f : -10000.f;
}

// band-pass impulse response (ONE block — the FP64 cos work runs once, not 256x)
__global__ void build_cs_kernel(int left, int right)
{
    int n = threadIdx.x;
    double s = 0.0;
    for (int f = left; f < right; f++) {
        double w;
        if (f == 0)           w = 1.0;
        else if (f == Lc/2)   w = (n & 1) ? -1.0 : 1.0;
        else                  w = 2.0 * cos(2.0 * M_PI * (double)f * (double)n / (double)Lc);
        s += w;
    }
    g_cs[n] = (float)(s / (double)Lc);
}

// circulant plane build (trivial gather from g_cs)
__global__ void buildC_kernel()
{
    int n = blockIdx.x, m = threadIdx.x;
    float v = g_cs[(n - m + Lc) & (Lc - 1)];
    bf16 h, l; split_hl(v, h, l);
    g_Cmh[n * Lc + m] = h;
    g_Cml[n * Lc + m] = l;
}

// all weights -> h/l planes; QKV concatenated along N
__global__ void convW_kernel(const float* __restrict__ Wq, const float* __restrict__ Wk,
                             const float* __restrict__ Wv, const float* __restrict__ Wp,
                             const float* __restrict__ F1, const float* __restrict__ F2)
{
    int idx = blockIdx.x * 256 + threadIdx.x;      // 0..131071
    float v; int dst;
    if (idx < 49152) {
        int k = idx / 384, c = idx - k*384;
        int w = c >> 7, n = c & 127;
        const float* src = (w == 0 ? Wq : w == 1 ? Wk : Wv);
        v = src[k*128 + n];
        dst = idx;                                  // [k][c] ld=384
    } else if (idx < 65536) {
        v = Wp[idx - 49152]; dst = idx;
    } else if (idx < 98304) {
        v = F1[idx - 65536]; dst = idx;
    } else {
        v = F2[idx - 98304]; dst = idx;
    }
    bf16 h, l; split_hl(v, h, l);
    g_Wh[dst] = h;
    g_Wl[dst] = l;
}

__global__ void meanred_kernel()
{
    int b = blockIdx.x, d = threadIdx.x;
    float s = 0.f;
    #pragma unroll
    for (int p = 0; p < 16; p++) s += g_mvp[((size_t)p * Bc + b) * Lc + d];
    g_mv[b * Lc + d] = s;
}

__global__ void stats_kernel()
{
    __shared__ float sv[Lc];
    __shared__ int   si[Lc];
    __shared__ int   dls[TOPKc];
    int t = threadIdx.x;

    float s = 0.f;
    for (int b = 0; b < Bc; b++) s += g_mv[b * Lc + t];
    float my = s * (1.0f / (float)Bc);

    for (int it = 0; it < TOPKc; it++) {
        sv[t] = my; si[t] = t;
        __syncthreads();
        for (int st = 128; st > 0; st >>= 1) {
            if (t < st) {
                float v2 = sv[t + st]; int i2 = si[t + st];
                if (v2 > sv[t] || (v2 == sv[t] && i2 < si[t])) { sv[t] = v2; si[t] = i2; }
            }
            __syncthreads();
        }
        int win = si[0];
        if (t == 0) { g_delays[it] = win; dls[it] = win; }
        __syncthreads();
        if (t == win) my = -INFINITY;
    }

    float w[TOPKc];
    float mx = -1e30f;
    #pragma unroll
    for (int i = 0; i < TOPKc; i++) {
        w[i] = g_mv[t * Lc + dls[i]];
        mx = fmaxf(mx, w[i]);
    }
    float sm = 0.f;
    #pragma unroll
    for (int i = 0; i < TOPKc; i++) { w[i] = expf(w[i] - mx); sm += w[i]; }
    float inv = 1.0f / sm;
    #pragma unroll
    for (int i = 0; i < TOPKc; i++) g_w[t * TOPKc + i] = w[i] * inv;
}

// 0.9*freq + 0.1*spatial -> h/l planes
__global__ void combine_kernel()
{
    int bl = blockIdx.x, c = threadIdx.x;
    int b = bl >> 8, l = bl & 255;
    __shared__ float w[TOPKc];
    __shared__ int   dl[TOPKc];
    if (c < TOPKc) { w[c] = g_w[b * TOPKc + c]; dl[c] = g_delays[c]; }
    __syncthreads();
    float f = 0.f;
    #pragma unroll
    for (int t = 0; t < TOPKc; t++) {
        int ls = (l + dl[t]) & 255;
        f += w[t] * g_vb[((size_t)b * Lc + ls) * Dc + c];
    }
    float v = 0.9f * f + 0.1f * g_sp[(size_t)bl * Dc + c];
    bf16 h, lo; split_hl(v, h, lo);
    g_oh[(size_t)bl * Dc + c] = h;
    g_ol[(size_t)bl * Dc + c] = lo;
}

__global__ void gather_kernel(const int* __restrict__ lengths, float* __restrict__ out)
{
    int b = blockIdx.x, c = threadIdx.x;
    int l = lengths[b] - 1;
    out[b * Dc + c] = g_x[((size_t)b * Lc + l) * Dc + c];
}

// ---------------- host side ----------------
static inline void mma_go(const bf16* Ah, const bf16* Al,
                          const bf16* Bh, const bf16* Bl, float* C,
                          int M, int N, int K, int lda, int ldb, int ldc,
                          int batch, long sA, long sB, long sC,
                          const float* R, int ldr, int fuse,
                          int emit, bf16* Oh, bf16* Ol)
{
    dim3 grid(M / 128, N / 128, batch);
    mma_kernel<<<grid, 256, MMA_SMEM_BYTES>>>(Ah, Al, Bh, Bl, C, K, lda, ldb, ldc,
        sA, sB, sC, R, ldr, fuse, emit, Oh, Ol);
}

extern "C" void kernel_launch(void* const* d_in, const int* in_sizes, int n_in,
                              void* d_out, int out_size)
{
    (void)in_sizes; (void)n_in; (void)out_size;
    const int*   paths   = (const int*)  d_in[0];
    const int*   lengths = (const int*)  d_in[1];
    const float* ego     = (const float*)d_in[4];
    const float* pos     = (const float*)d_in[5];
    const float* Wq      = (const float*)d_in[6];
    const float* Wk      = (const float*)d_in[7];
    const float* Wv      = (const float*)d_in[8];
    const float* Wp      = (const float*)d_in[9];
    const float* F1      = (const float*)d_in[10];
    const float* F2      = (const float*)d_in[11];
    float* out = (float*)d_out;

    float *px, *pmask, *pvb, *psp, *pmvp;
    bf16 *pxh, *pxl, *pxth, *pxtl, *pqkvh, *pqkvl, *poh, *pol, *pah, *pal,
         *phh, *phl, *pCmh, *pCml, *pWh, *pWl;
    cudaGetSymbolAddress((void**)&px,    g_x);
    cudaGetSymbolAddress((void**)&pmask, g_mask);
    cudaGetSymbolAddress((void**)&pvb,   g_vb);
    cudaGetSymbolAddress((void**)&psp,   g_sp);
    cudaGetSymbolAddress((void**)&pmvp,  g_mvp);
    cudaGetSymbolAddress((void**)&pxh,   g_xh);
    cudaGetSymbolAddress((void**)&pxl,   g_xl);
    cudaGetSymbolAddress((void**)&pxth,  g_xth);
    cudaGetSymbolAddress((void**)&pxtl,  g_xtl);
    cudaGetSymbolAddress((void**)&pqkvh, g_qkvh);
    cudaGetSymbolAddress((void**)&pqkvl, g_qkvl);
    cudaGetSymbolAddress((void**)&poh,   g_oh);
    cudaGetSymbolAddress((void**)&pol,   g_ol);
    cudaGetSymbolAddress((void**)&pah,   g_ah);
    cudaGetSymbolAddress((void**)&pal,   g_al);
    cudaGetSymbolAddress((void**)&phh,   g_hh);
    cudaGetSymbolAddress((void**)&phl,   g_hl);
    cudaGetSymbolAddress((void**)&pCmh,  g_Cmh);
    cudaGetSymbolAddress((void**)&pCml,  g_Cml);
    cudaGetSymbolAddress((void**)&pWh,   g_Wh);
    cudaGetSymbolAddress((void**)&pWl,   g_Wl);

    // No static guards (harness contract): set attributes unconditionally.
    cudaFuncSetAttribute(fattn_kernel,
                         cudaFuncAttributeMaxDynamicSharedMemorySize, FA_SMEM);
    cudaFuncSetAttribute(mma_kernel,
                         cudaFuncAttributeMaxDynamicSharedMemorySize, MMA_SMEM_BYTES);

    const int  BL = Bc * Lc;
    const long LD = (long)Lc * Dc;

    build_x_kernel<<<BL, Dc>>>(paths, ego, pos);

    const int lefts[NLc]  = {51, 0};
    const int rights[NLc] = {129, 78};

    for (int k = 0; k < NLc; k++) {
        build_cs_kernel<<<1, Lc>>>(lefts[k], rights[k]);
        buildC_kernel<<<Lc, Lc>>>();
        convW_kernel<<<512, 256>>>(Wq + (size_t)k*Dc*Dc, Wk + (size_t)k*Dc*Dc,
                                   Wv + (size_t)k*Dc*Dc, Wp + (size_t)k*Dc*Dc,
                                   F1 + (size_t)k*Dc*2*Dc, F2 + (size_t)k*2*Dc*Dc);

        // xt = Cm @ x (batched over b): A=Cm planes [256,256], B=x planes [256,128]
        mma_go(pCmh, pCml, pxh, pxl, psp /*unused*/,
               Lc, Dc, Lc, Lc, Dc, Dc,
               Bc, 0, LD, LD, nullptr, 0, 0, 2, pxth, pxtl);

        // qkv = xt @ [Wq|Wk|Wv]  (N=384; 6th launch overall -> ncu capture target)
        mma_go(pxth, pxtl, pWh + WO_QKV, pWl + WO_QKV, psp /*unused*/,
               BL, 3*Dc, Dc, Dc, 3*Dc, 3*Dc,
               1, 0, 0, 0, nullptr, 0, 0, 2, pqkvh, pqkvl);

        // fused attention: S + meanv partials + softmax + P@V
        {
            dim3 grid(4, Bc * 2);
            fattn_kernel<<<grid, 512, FA_SMEM>>>(pqkvh, pqkvl, pmask, psp, pmvp);
        }
        meanred_kernel<<<Bc, Lc>>>();
        stats_kernel<<<1, Lc>>>();

        // vb = x @ Wv (fp32; Wv = QKV cols 256..383) — needed only by combine
        mma_go(pxh, pxl, pWh + WO_QKV + 256, pWl + WO_QKV + 256, pvb,
               BL, Dc, Dc, Dc, 3*Dc, Dc,
               1, 0, 0, 0, nullptr, 0, 0, 1, nullptr, nullptr);

        combine_kernel<<<BL, Dc>>>();

        // a = o @ Wp + x
        mma_go(poh, pol, pWh + WO_P, pWl + WO_P, psp /*unused*/,
               BL, Dc, Dc, Dc, Dc, Dc,
               1, 0, 0, 0, px, Dc, 1, 2, pah, pal);

        // h = GELU(a @ F1)  (N=256)
        mma_go(pah, pal, pWh + WO_F1, pWl + WO_F1, psp /*unused*/,
               BL, 2*Dc, Dc, Dc, 2*Dc, 2*Dc,
               1, 0, 0, 0, nullptr, 0, 2, 2, phh, phl);

        // x = h @ F2  (K=256) -> fp32 x + planes
        mma_go(phh, phl, pWh + WO_F2, pWl + WO_F2, px,
               BL, Dc, 2*Dc, 2*Dc, Dc, Dc,
               1, 0, 0, 0, nullptr, 0, 0, 3, pxh, pxl);
    }

    gather_kernel<<<Bc, Dc>>>(lengths, out);
}

// round 15
// speedup vs baseline: 2.3272x; 1.1940x over previous
#include <cuda_runtime.h>
#include <cuda_bf16.h>
#include <math.h>
#include <stdint.h>

#ifndef M_PI
#define M_PI 3.14159265358979323846
#endif

#define Bc 256
#define Lc 256
#define Dc 128
#define NLc 2
#define TOPKc 5
#define NUM_TOTAL_C 100000
#define INV_SQRT_E 0.125f
#define INV_SQRT_2F 0.70710678118654752440f

typedef __nv_bfloat16 bf16;

// ---------------- scratch ----------------
__device__ float g_x   [Bc*Lc*Dc];
__device__ float g_mask[Bc*Lc];
__device__ float g_vb  [Bc*Lc*Dc];
__device__ float g_sp  [Bc*Lc*Dc];
__device__ float g_mv  [Bc*Lc];
__device__ float g_mvp [16*Bc*Lc];
__device__ int   g_delays[TOPKc];
__device__ float g_w   [Bc*TOPKc];
__device__ float g_cs  [NLc*Lc];

// h/l plane pairs (logical K, no tripling in memory)
__device__ bf16 g_xh  [Bc*Lc*Dc];
__device__ bf16 g_xl  [Bc*Lc*Dc];
__device__ bf16 g_xth [Bc*Lc*Dc];
__device__ bf16 g_xtl [Bc*Lc*Dc];
__device__ bf16 g_qkvh[(size_t)Bc*Lc*3*Dc];    // h plane only (l plane eliminated)
__device__ bf16 g_oh  [Bc*Lc*Dc];
__device__ bf16 g_ol  [Bc*Lc*Dc];
__device__ bf16 g_ah  [Bc*Lc*Dc];
__device__ bf16 g_al  [Bc*Lc*Dc];
__device__ bf16 g_hh  [Bc*Lc*2*Dc];
__device__ bf16 g_hl  [Bc*Lc*2*Dc];
__device__ bf16 g_Cmh [NLc*Lc*Lc];
__device__ bf16 g_Cml [NLc*Lc*Lc];
__device__ bf16 g_Wh  [NLc*131072];  // per layer: [QKV 0..49151][Wp][F1][F2]
__device__ bf16 g_Wl  [NLc*131072];

#define WO_QKV 0
#define WO_P   49152
#define WO_F1  65536
#define WO_F2  98304

__device__ const int c_lefts [NLc] = {51, 0};
__device__ const int c_rights[NLc] = {129, 78};

// ---------------- PTX helpers ----------------
__device__ __forceinline__ uint32_t smem_u32(const void* p) {
    return (uint32_t)__cvta_generic_to_shared(p);
}
__device__ __forceinline__ void cpasync16(void* sp, const void* gp) {
    asm volatile("cp.async.cg.shared.global [%0], [%1], 16;"
                 :: "r"(smem_u32(sp)), "l"(gp));
}
#define CP_COMMIT() asm volatile("cp.async.commit_group;")
#define CP_WAIT0()  asm volatile("cp.async.wait_group 0;")
#define CP_WAIT1()  asm volatile("cp.async.wait_group 1;")

#define LDSM_X4(r0,r1,r2,r3,addr) \
    asm volatile("ldmatrix.sync.aligned.m8n8.x4.shared.b16 {%0,%1,%2,%3}, [%4];" \
        : "=r"(r0),"=r"(r1),"=r"(r2),"=r"(r3) : "r"(addr))
#define LDSM_X4_T(r0,r1,r2,r3,addr) \
    asm volatile("ldmatrix.sync.aligned.m8n8.x4.trans.shared.b16 {%0,%1,%2,%3}, [%4];" \
        : "=r"(r0),"=r"(r1),"=r"(r2),"=r"(r3) : "r"(addr))

#define MMA_BF16(d, a, b0v, b1v) \
    asm volatile("mma.sync.aligned.m16n8k16.row.col.f32.bf16.bf16.f32 " \
        "{%0,%1,%2,%3}, {%4,%5,%6,%7}, {%8,%9}, {%0,%1,%2,%3};" \
        : "+f"(d[0]), "+f"(d[1]), "+f"(d[2]), "+f"(d[3]) \
        : "r"(a[0]), "r"(a[1]), "r"(a[2]), "r"(a[3]), "r"(b0v), "r"(b1v))

__device__ __forceinline__ void split_hl(float v, bf16& h, bf16& l) {
    h = __float2bfloat16(v);
    l = __float2bfloat16(v - __bfloat162float(h));
}

// ---------------- plane-format 3-term tensor GEMM, 3-stage pipeline ----------------
// C = Ah*Bh + Al*Bh + Ah*Bl   (logical K; A [M,K], B [K,N] row-major, NN)
// emit bits: 1 = fp32 C; 2 = h+l planes -> Oh/Ol; 4 = h plane only -> Oh.
// fuse: 0 none, 1 +=R, 2 exact-erf GELU.
#define MMA_SE 18944                       // elements per stage
#define MMA_SMEM_BYTES (3*MMA_SE*2)        // 113664 bytes

__global__ __launch_bounds__(256, 2)
void mma_kernel(const bf16* __restrict__ Ah, const bf16* __restrict__ Al,
                const bf16* __restrict__ Bh, const bf16* __restrict__ Bl,
                float* __restrict__ C,
                int K, int lda, int ldb, int ldc,
                long sA, long sB, long sC,
                const float* __restrict__ R, int ldr, int fuse,
                int emit, bf16* __restrict__ Oh, bf16* __restrict__ Ol)
{
    extern __shared__ bf16 smp[];
    const int tid  = threadIdx.x;
    const int warp = tid >> 5;
    const int lane = tid & 31;
    const int warpM0 = (warp & 1) * 64;
    const int warpN0 = (warp >> 1) * 32;

    const int z = blockIdx.z;
    Ah += (size_t)z * sA;  Al += (size_t)z * sA;
    Bh += (size_t)z * sB;  Bl += (size_t)z * sB;
    const long co = (size_t)z * sC;

    const int m0 = blockIdx.x * 128;
    const int n0 = blockIdx.y * 128;

    auto load_tiles = [&](int st, int k0) {
        bf16* ah_s = smp + st * MMA_SE;
        bf16* al_s = ah_s + 5120;
        bf16* bh_s = ah_s + 10240;
        bf16* bl_s = ah_s + 14592;
        #pragma unroll
        for (int i = 0; i < 2; i++) {
            int c = tid + i * 256;
            int row = c >> 2, kc = (c & 3) << 3;
            cpasync16(ah_s + row*40 + kc, Ah + (size_t)(m0 + row) * lda + k0 + kc);
            cpasync16(al_s + row*40 + kc, Al + (size_t)(m0 + row) * lda + k0 + kc);
        }
        #pragma unroll
        for (int i = 0; i < 2; i++) {
            int c = tid + i * 256;
            int row = c >> 4, nc = (c & 15) << 3;
            cpasync16(bh_s + row*136 + nc, Bh + (size_t)(k0 + row) * ldb + n0 + nc);
            cpasync16(bl_s + row*136 + nc, Bl + (size_t)(k0 + row) * ldb + n0 + nc);
        }
    };

    float acc[4][2][2][4];
    #pragma unroll
    for (int i = 0; i < 4; i++)
        #pragma unroll
        for (int j = 0; j < 2; j++)
            #pragma unroll
            for (int s = 0; s < 2; s++)
                #pragma unroll
                for (int q = 0; q < 4; q++) acc[i][j][s][q] = 0.f;

    const int nk = K / 32;
    load_tiles(0, 0);
    CP_COMMIT();
    if (nk > 1) { load_tiles(1, 32); CP_COMMIT(); }

    for (int kt = 0; kt < nk; kt++) {
        if (kt + 1 < nk) CP_WAIT1(); else CP_WAIT0();
        __syncthreads();
        if (kt + 2 < nk) { load_tiles((kt + 2) % 3, (kt + 2) * 32); CP_COMMIT(); }

        bf16* ah_s = smp + (kt % 3) * MMA_SE;
        bf16* al_s = ah_s + 5120;
        bf16* bh_s = ah_s + 10240;
        bf16* bl_s = ah_s + 14592;

        #pragma unroll
        for (int ks = 0; ks < 2; ks++) {
            const int acol = ks*16 + ((lane >> 4) << 3);
            uint32_t ah[4][4], bh[2][4];
            #pragma unroll
            for (int tm = 0; tm < 4; tm++) {
                uint32_t ad = smem_u32(&ah_s[(warpM0 + tm*16 + (lane & 15))*40 + acol]);
                LDSM_X4(ah[tm][0], ah[tm][1], ah[tm][2], ah[tm][3], ad);
            }
            #pragma unroll
            for (int tn = 0; tn < 2; tn++) {
                uint32_t ad = smem_u32(&bh_s[(ks*16 + (lane & 15))*136
                                             + warpN0 + tn*16 + ((lane >> 4) << 3)]);
                LDSM_X4_T(bh[tn][0], bh[tn][1], bh[tn][2], bh[tn][3], ad);
            }
            // term 1: ah * bh
            #pragma unroll
            for (int tm = 0; tm < 4; tm++)
                #pragma unroll
                for (int tn = 0; tn < 2; tn++) {
                    MMA_BF16(acc[tm][tn][0], ah[tm], bh[tn][0], bh[tn][1]);
                    MMA_BF16(acc[tm][tn][1], ah[tm], bh[tn][2], bh[tn][3]);
                }
            // term 2: al * bh
            {
                uint32_t xf[4][4];
                #pragma unroll
                for (int tm = 0; tm < 4; tm++) {
                    uint32_t ad = smem_u32(&al_s[(warpM0 + tm*16 + (lane & 15))*40 + acol]);
                    LDSM_X4(xf[tm][0], xf[tm][1], xf[tm][2], xf[tm][3], ad);
                }
                #pragma unroll
                for (int tm = 0; tm < 4; tm++)
                    #pragma unroll
                    for (int tn = 0; tn < 2; tn++) {
                        MMA_BF16(acc[tm][tn][0], xf[tm], bh[tn][0], bh[tn][1]);
                        MMA_BF16(acc[tm][tn][1], xf[tm], bh[tn][2], bh[tn][3]);
                    }
            }
            // term 3: ah * bl
            {
                uint32_t bl[2][4];
                #pragma unroll
                for (int tn = 0; tn < 2; tn++) {
                    uint32_t ad = smem_u32(&bl_s[(ks*16 + (lane & 15))*136
                                                 + warpN0 + tn*16 + ((lane >> 4) << 3)]);
                    LDSM_X4_T(bl[tn][0], bl[tn][1], bl[tn][2], bl[tn][3], ad);
                }
                #pragma unroll
                for (int tm = 0; tm < 4; tm++)
                    #pragma unroll
                    for (int tn = 0; tn < 2; tn++) {
                        MMA_BF16(acc[tm][tn][0], ah[tm], bl[tn][0], bl[tn][1]);
                        MMA_BF16(acc[tm][tn][1], ah[tm], bl[tn][2], bl[tn][3]);
                    }
            }
        }
    }

    // epilogue
    #pragma unroll
    for (int tm = 0; tm < 4; tm++)
        #pragma unroll
        for (int tn = 0; tn < 2; tn++)
            #pragma unroll
            for (int s = 0; s < 2; s++) {
                int col = n0 + warpN0 + tn*16 + s*8 + ((lane & 3) << 1);
                float* cc = acc[tm][tn][s];
                #pragma unroll
                for (int hr = 0; hr < 2; hr++) {
                    int row = m0 + warpM0 + tm*16 + (lane >> 2) + hr*8;
                    float2 v = make_float2(cc[hr*2 + 0], cc[hr*2 + 1]);
                    if (fuse == 1) {
                        float2 r = *(const float2*)&R[(size_t)row * ldr + col];
                        v.x += r.x; v.y += r.y;
                    } else if (fuse == 2) {
                        v.x = v.x * 0.5f * (1.0f + erff(v.x * INV_SQRT_2F));
                        v.y = v.y * 0.5f * (1.0f + erff(v.y * INV_SQRT_2F));
                    }
                    size_t ci = co + (size_t)row * ldc + col;
                    if (emit & 1) *(float2*)&C[ci] = v;
                    if (emit & 6) {
                        bf16 hx, lx, hy, ly;
                        split_hl(v.x, hx, lx);
                        split_hl(v.y, hy, ly);
                        __nv_bfloat162 hv; hv.x = hx; hv.y = hy;
                        *(__nv_bfloat162*)&Oh[ci] = hv;
                        if (emit & 2) {
                            __nv_bfloat162 lv; lv.x = lx; lv.y = ly;
                            *(__nv_bfloat162*)&Ol[ci] = lv;
                        }
                    }
                }
            }
}

// ---------------- fused attention (h-plane inputs, single-term QK, 512 threads) ----------------
#define FA_VH 0          /* [256][72] bf16 = 36864 */
#define FA_QH 36864      /* [64][72]  bf16 =  9216 */
#define FA_KH 46080      /* [256][72] bf16 = 36864, ends 82944 */
#define FA_SS 36864      /* [64][264] f32  = 67584, overlays QH/KH after phase 1 */
#define FA_PH 104448     /* [64][264] bf16 = 33792 */
#define FA_MK 138240     /* [256] f32 = 1024 */
#define FA_SMEM 139264

__global__ __launch_bounds__(512, 1)
void fattn_kernel(const bf16* __restrict__ qkvh,
                  const float* __restrict__ maskg,
                  float* __restrict__ sp, float* __restrict__ mvp)
{
    extern __shared__ char sm[];
    bf16*  Vh = (bf16*) (sm + FA_VH);
    bf16*  Qh = (bf16*) (sm + FA_QH);
    bf16*  Kh = (bf16*) (sm + FA_KH);
    float* Ss = (float*)(sm + FA_SS);
    bf16*  Ph = (bf16*) (sm + FA_PH);
    float* mk = (float*)(sm + FA_MK);

    const int tid = threadIdx.x, warp = tid >> 5, lane = tid & 31;
    const int q0 = blockIdx.x * 64;
    const int b  = blockIdx.y >> 1, h = blockIdx.y & 1;

    // prologue loads (h planes only)
    const bf16* qg = qkvh + ((size_t)(b*Lc + q0)) * 384 + h*64;
    const bf16* kg = qkvh + ((size_t)(b*Lc)) * 384 + 128 + h*64;
    const bf16* vg = qkvh + ((size_t)(b*Lc)) * 384 + 256 + h*64;

    {
        int c = tid;                        // Q: exactly 512 16B chunks
        int r = c >> 3, kc = (c & 7) << 3;
        cpasync16(&Qh[r*72 + kc], qg + (size_t)r*384 + kc);
    }
    for (int c = tid; c < 2048; c += 512) { // K, V: 2048 chunks each
        int r = c >> 3, kc = (c & 7) << 3;
        cpasync16(&Kh[r*72 + kc], kg + (size_t)r*384 + kc);
        cpasync16(&Vh[r*72 + kc], vg + (size_t)r*384 + kc);
    }
    if (tid < 64)
        cpasync16(&mk[tid*4], maskg + b*Lc + tid*4);
    CP_COMMIT(); CP_WAIT0();
    __syncthreads();

    // phase 1: S = Qh @ Kh^T   (M=64, N=256, K=64, single term)
    {
        const int wM = (warp & 1) * 32;
        const int wN = (warp >> 1) * 32;
        float accS[2][2][2][4];
        #pragma unroll
        for (int i=0;i<2;i++) for (int j=0;j<2;j++) for (int s=0;s<2;s++)
            for (int q=0;q<4;q++) accS[i][j][s][q] = 0.f;

        #pragma unroll
        for (int kf = 0; kf < 4; kf++) {
            const int kcol = kf*16 + ((lane >> 4) << 3);
            uint32_t qa[2][4], ka[2][4];
            #pragma unroll
            for (int mf = 0; mf < 2; mf++) {
                int ro = (wM + mf*16 + (lane & 15))*72 + kcol;
                LDSM_X4(qa[mf][0], qa[mf][1], qa[mf][2], qa[mf][3], smem_u32(&Qh[ro]));
            }
            #pragma unroll
            for (int tn = 0; tn < 2; tn++) {
                int ro = (wN + tn*16 + (lane & 15))*72 + kcol;
                LDSM_X4(ka[tn][0], ka[tn][1], ka[tn][2], ka[tn][3], smem_u32(&Kh[ro]));
            }
            #pragma unroll
            for (int mf = 0; mf < 2; mf++)
                #pragma unroll
                for (int tn = 0; tn < 2; tn++) {
                    MMA_BF16(accS[mf][tn][0], qa[mf], ka[tn][0], ka[tn][2]);
                    MMA_BF16(accS[mf][tn][1], qa[mf], ka[tn][1], ka[tn][3]);
                }
        }
        __syncthreads();   // Qh/Kh reads done before Ss overlays them

        #pragma unroll
        for (int mf = 0; mf < 2; mf++)
            #pragma unroll
            for (int tn = 0; tn < 2; tn++)
                #pragma unroll
                for (int s = 0; s < 2; s++)
                    #pragma unroll
                    for (int hr = 0; hr < 2; hr++) {
                        int row = wM + mf*16 + (lane >> 2) + hr*8;
                        int col = wN + tn*16 + s*8 + ((lane & 3) << 1);
                        *(float2*)&Ss[row*264 + col] =
                            make_float2(accS[mf][tn][s][hr*2], accS[mf][tn][s][hr*2+1]);
                    }
    }
    __syncthreads();

    // meanv partials (raw scores, diagonal sums)
    {
        int d = tid & 255, half = tid >> 8;
        float s = 0.f;
        #pragma unroll 8
        for (int m = half*32; m < half*32 + 32; m++)
            s += Ss[m*264 + ((q0 + m - d) & 255)];
        int p = (blockIdx.x*2 + h)*2 + half;
        mvp[((size_t)p * Bc + b) * Lc + d] = s * (1.0f/128.0f);
    }
    __syncthreads();

    // softmax -> Ph (bf16)
    {
        int row = tid >> 3, part = tid & 7;
        float* Sr = &Ss[row*264 + part*32];
        const float* mr = &mk[part*32];
        float mx = -1e30f;
        #pragma unroll 8
        for (int j = 0; j < 32; j++)
            mx = fmaxf(mx, Sr[j] * INV_SQRT_E + mr[j]);
        mx = fmaxf(mx, __shfl_xor_sync(0xffffffffu, mx, 1));
        mx = fmaxf(mx, __shfl_xor_sync(0xffffffffu, mx, 2));
        mx = fmaxf(mx, __shfl_xor_sync(0xffffffffu, mx, 4));
        float sum = 0.f;
        #pragma unroll 8
        for (int j = 0; j < 32; j++) {
            float e = expf(Sr[j] * INV_SQRT_E + mr[j] - mx);
            Sr[j] = e; sum += e;
        }
        sum += __shfl_xor_sync(0xffffffffu, sum, 1);
        sum += __shfl_xor_sync(0xffffffffu, sum, 2);
        sum += __shfl_xor_sync(0xffffffffu, sum, 4);
        float inv = 1.0f / sum;
        bf16* ph = &Ph[row*264 + part*32];
        #pragma unroll 8
        for (int j = 0; j < 32; j++)
            ph[j] = __float2bfloat16(Sr[j] * inv);
    }
    __syncthreads();

    // phase 2: O = Ph @ Vh  (M=64, N=64, K=256), K-split across 2 warp groups
    {
        const int w8  = warp & 7;
        const int kh  = warp >> 3;
        const int wM2 = (w8 & 1) * 32;
        const int wN2 = ((w8 >> 1) & 3) * 16;
        float o[2][2][4];
        #pragma unroll
        for (int i=0;i<2;i++) for (int s=0;s<2;s++) for (int q=0;q<4;q++) o[i][s][q]=0.f;

        for (int kf = kh*8; kf < kh*8 + 8; kf++) {
            uint32_t ah[2][4], bh[4];
            #pragma unroll
            for (int mf = 0; mf < 2; mf++) {
                uint32_t ro = (wM2 + mf*16 + (lane & 15))*264 + kf*16 + ((lane >> 4) << 3);
                LDSM_X4(ah[mf][0], ah[mf][1], ah[mf][2], ah[mf][3], smem_u32(&Ph[ro]));
            }
            {
                uint32_t vo = (kf*16 + (lane & 15))*72 + wN2 + ((lane >> 4) << 3);
                LDSM_X4_T(bh[0], bh[1], bh[2], bh[3], smem_u32(&Vh[vo]));
            }
            #pragma unroll
            for (int mf = 0; mf < 2; mf++) {
                MMA_BF16(o[mf][0], ah[mf], bh[0], bh[1]);
                MMA_BF16(o[mf][1], ah[mf], bh[2], bh[3]);
            }
        }
        __syncthreads();    // Ss free; reuse for partial reduction
        float* Os = Ss;
        if (kh == 1) {
            #pragma unroll
            for (int mf = 0; mf < 2; mf++)
                #pragma unroll
                for (int s = 0; s < 2; s++)
                    #pragma unroll
                    for (int hr = 0; hr < 2; hr++) {
                        int rl = wM2 + mf*16 + (lane >> 2) + hr*8;
                        int cl = wN2 + s*8 + ((lane & 3) << 1);
                        *(float2*)&Os[rl*264 + cl] =
                            make_float2(o[mf][s][hr*2], o[mf][s][hr*2+1]);
                    }
        }
        __syncthreads();
        if (kh == 0) {
            #pragma unroll
            for (int mf = 0; mf < 2; mf++)
                #pragma unroll
                for (int s = 0; s < 2; s++)
                    #pragma unroll
                    for (int hr = 0; hr < 2; hr++) {
                        int rl = wM2 + mf*16 + (lane >> 2) + hr*8;
                        int cl = wN2 + s*8 + ((lane & 3) << 1);
                        float2 p = *(float2*)&Os[rl*264 + cl];
                        int row = q0 + rl;
                        int col = h*64 + cl;
                        *(float2*)&sp[((size_t)b*Lc + row)*Dc + col] =
                            make_float2(o[mf][s][hr*2] + p.x, o[mf][s][hr*2+1] + p.y);
                    }
        }
    }
}

// ---------------- small kernels ----------------
__global__ void build_x_kernel(const int* __restrict__ paths,
                               const float* __restrict__ ego,
                               const float* __restrict__ pos)
{
    int bl = blockIdx.x, c = threadIdx.x;
    int p = paths[bl], l = bl & (Lc - 1);
    float v = ego[(size_t)p * Dc + c] + pos[l * Dc + c];
    g_x[(size_t)bl * Dc + c] = v;
    bf16 h, lo; split_hl(v, h, lo);
    g_xh[(size_t)bl * Dc + c] = h;
    g_xl[(size_t)bl * Dc + c] = lo;
    if (c == 0) g_mask[bl] = (p < NUM_TOTAL_C) ? 0.f : -10000.f;
}

// band-pass impulse responses, both layers, one launch (grid 2)
__global__ void build_cs_kernel()
{
    int layer = blockIdx.x, n = threadIdx.x;
    int left = c_lefts[layer], right = c_rights[layer];
    double s = 0.0;
    for (int f = left; f < right; f++) {
        double w;
        if (f == 0)           w = 1.0;
        else if (f == Lc/2)   w = (n & 1) ? -1.0 : 1.0;
        else                  w = 2.0 * cos(2.0 * M_PI * (double)f * (double)n / (double)Lc);
        s += w;
    }
    g_cs[layer*Lc + n] = (float)(s / (double)Lc);
}

// circulant plane build, both layers (grid (256,2))
__global__ void buildC_kernel()
{
    int n = blockIdx.x, layer = blockIdx.y, m = threadIdx.x;
    float v = g_cs[layer*Lc + ((n - m + Lc) & (Lc - 1))];
    bf16 h, l; split_hl(v, h, l);
    g_Cmh[layer*Lc*Lc + n*Lc + m] = h;
    g_Cml[layer*Lc*Lc + n*Lc + m] = l;
}

// all weights, both layers -> h/l planes; QKV concatenated along N
__global__ void convW_kernel(const float* __restrict__ Wq, const float* __restrict__ Wk,
                             const float* __restrict__ Wv, const float* __restrict__ Wp,
                             const float* __restrict__ F1, const float* __restrict__ F2)
{
    int gidx = blockIdx.x * 256 + threadIdx.x;     // 0..262143
    int layer = gidx >> 17;
    int idx = gidx & 131071;
    float v;
    if (idx < 49152) {
        int k = idx / 384, c = idx - k*384;
        int w = c >> 7, n = c & 127;
        const float* src = (w == 0 ? Wq : w == 1 ? Wk : Wv) + layer*Dc*Dc;
        v = src[k*128 + n];
    } else if (idx < 65536) {
        v = Wp[layer*Dc*Dc + idx - 49152];
    } else if (idx < 98304) {
        v = F1[layer*Dc*2*Dc + idx - 65536];
    } else {
        v = F2[layer*2*Dc*Dc + idx - 98304];
    }
    bf16 h, l; split_hl(v, h, l);
    g_Wh[layer*131072 + idx] = h;
    g_Wl[layer*131072 + idx] = l;
}

__global__ void meanred_kernel()
{
    int b = blockIdx.x, d = threadIdx.x;
    float s = 0.f;
    #pragma unroll
    for (int p = 0; p < 16; p++) s += g_mvp[((size_t)p * Bc + b) * Lc + d];
    g_mv[b * Lc + d] = s;
}

__global__ void stats_kernel()
{
    __shared__ float sv[Lc];
    __shared__ int   si[Lc];
    __shared__ int   dls[TOPKc];
    int t = threadIdx.x;

    float s = 0.f;
    for (int b = 0; b < Bc; b++) s += g_mv[b * Lc + t];
    float my = s * (1.0f / (float)Bc);

    for (int it = 0; it < TOPKc; it++) {
        sv[t] = my; si[t] = t;
        __syncthreads();
        for (int st = 128; st > 0; st >>= 1) {
            if (t < st) {
                float v2 = sv[t + st]; int i2 = si[t + st];
                if (v2 > sv[t] || (v2 == sv[t] && i2 < si[t])) { sv[t] = v2; si[t] = i2; }
            }
            __syncthreads();
        }
        int win = si[0];
        if (t == 0) { g_delays[it] = win; dls[it] = win; }
        __syncthreads();
        if (t == win) my = -INFINITY;
    }

    float w[TOPKc];
    float mx = -1e30f;
    #pragma unroll
    for (int i = 0; i < TOPKc; i++) {
        w[i] = g_mv[t * Lc + dls[i]];
        mx = fmaxf(mx, w[i]);
    }
    float sm = 0.f;
    #pragma unroll
    for (int i = 0; i < TOPKc; i++) { w[i] = expf(w[i] - mx); sm += w[i]; }
    float inv = 1.0f / sm;
    #pragma unroll
    for (int i = 0; i < TOPKc; i++) g_w[t * TOPKc + i] = w[i] * inv;
}

// 0.9*freq + 0.1*spatial -> h/l planes
__global__ void combine_kernel()
{
    int bl = blockIdx.x, c = threadIdx.x;
    int b = bl >> 8, l = bl & 255;
    __shared__ float w[TOPKc];
    __shared__ int   dl[TOPKc];
    if (c < TOPKc) { w[c] = g_w[b * TOPKc + c]; dl[c] = g_delays[c]; }
    __syncthreads();
    float f = 0.f;
    #pragma unroll
    for (int t = 0; t < TOPKc; t++) {
        int ls = (l + dl[t]) & 255;
        f += w[t] * g_vb[((size_t)b * Lc + ls) * Dc + c];
    }
    float v = 0.9f * f + 0.1f * g_sp[(size_t)bl * Dc + c];
    bf16 h, lo; split_hl(v, h, lo);
    g_oh[(size_t)bl * Dc + c] = h;
    g_ol[(size_t)bl * Dc + c] = lo;
}

__global__ void gather_kernel(const int* __restrict__ lengths, float* __restrict__ out)
{
    int b = blockIdx.x, c = threadIdx.x;
    int l = lengths[b] - 1;
    out[b * Dc + c] = g_x[((size_t)b * Lc + l) * Dc + c];
}

// ---------------- host side ----------------
static inline void mma_go(const bf16* Ah, const bf16* Al,
                          const bf16* Bh, const bf16* Bl, float* C,
                          int M, int N, int K, int lda, int ldb, int ldc,
                          int batch, long sA, long sB, long sC,
                          const float* R, int ldr, int fuse,
                          int emit, bf16* Oh, bf16* Ol)
{
    dim3 grid(M / 128, N / 128, batch);
    mma_kernel<<<grid, 256, MMA_SMEM_BYTES>>>(Ah, Al, Bh, Bl, C, K, lda, ldb, ldc,
        sA, sB, sC, R, ldr, fuse, emit, Oh, Ol);
}

extern "C" void kernel_launch(void* const* d_in, const int* in_sizes, int n_in,
                              void* d_out, int out_size)
{
    (void)in_sizes; (void)n_in; (void)out_size;
    const int*   paths   = (const int*)  d_in[0];
    const int*   lengths = (const int*)  d_in[1];
    const float* ego     = (const float*)d_in[4];
    const float* pos     = (const float*)d_in[5];
    const float* Wq      = (const float*)d_in[6];
    const float* Wk      = (const float*)d_in[7];
    const float* Wv      = (const float*)d_in[8];
    const float* Wp      = (const float*)d_in[9];
    const float* F1      = (const float*)d_in[10];
    const float* F2      = (const float*)d_in[11];
    float* out = (float*)d_out;

    float *px, *pmask, *pvb, *psp, *pmvp;
    bf16 *pxh, *pxl, *pxth, *pxtl, *pqkvh, *poh, *pol, *pah, *pal,
         *phh, *phl, *pCmh, *pCml, *pWh, *pWl;
    cudaGetSymbolAddress((void**)&px,    g_x);
    cudaGetSymbolAddress((void**)&pmask, g_mask);
    cudaGetSymbolAddress((void**)&pvb,   g_vb);
    cudaGetSymbolAddress((void**)&psp,   g_sp);
    cudaGetSymbolAddress((void**)&pmvp,  g_mvp);
    cudaGetSymbolAddress((void**)&pxh,   g_xh);
    cudaGetSymbolAddress((void**)&pxl,   g_xl);
    cudaGetSymbolAddress((void**)&pxth,  g_xth);
    cudaGetSymbolAddress((void**)&pxtl,  g_xtl);
    cudaGetSymbolAddress((void**)&pqkvh, g_qkvh);
    cudaGetSymbolAddress((void**)&poh,   g_oh);
    cudaGetSymbolAddress((void**)&pol,   g_ol);
    cudaGetSymbolAddress((void**)&pah,   g_ah);
    cudaGetSymbolAddress((void**)&pal,   g_al);
    cudaGetSymbolAddress((void**)&phh,   g_hh);
    cudaGetSymbolAddress((void**)&phl,   g_hl);
    cudaGetSymbolAddress((void**)&pCmh,  g_Cmh);
    cudaGetSymbolAddress((void**)&pCml,  g_Cml);
    cudaGetSymbolAddress((void**)&pWh,   g_Wh);
    cudaGetSymbolAddress((void**)&pWl,   g_Wl);

    // No static guards (harness contract): set attributes unconditionally.
    cudaFuncSetAttribute(fattn_kernel,
                         cudaFuncAttributeMaxDynamicSharedMemorySize, FA_SMEM);
    cudaFuncSetAttribute(mma_kernel,
                         cudaFuncAttributeMaxDynamicSharedMemorySize, MMA_SMEM_BYTES);

    const int  BL = Bc * Lc;
    const long LD = (long)Lc * Dc;

    // input prep: x build + both layers' filters/weights, all upfront
    build_x_kernel<<<BL, Dc>>>(paths, ego, pos);
    build_cs_kernel<<<NLc, Lc>>>();
    buildC_kernel<<<dim3(Lc, NLc), Lc>>>();
    convW_kernel<<<1024, 256>>>(Wq, Wk, Wv, Wp, F1, F2);

    for (int k = 0; k < NLc; k++) {
        const bf16* Cmh = pCmh + (size_t)k * Lc * Lc;
        const bf16* Cml = pCml + (size_t)k * Lc * Lc;
        const bf16* Wh  = pWh  + (size_t)k * 131072;
        const bf16* Wl  = pWl  + (size_t)k * 131072;

        // xt = Cm @ x (batched over b)
        mma_go(Cmh, Cml, pxh, pxl, psp /*unused*/,
               Lc, Dc, Lc, Lc, Dc, Dc,
               Bc, 0, LD, LD, nullptr, 0, 0, 2, pxth, pxtl);

        // qkv = xt @ [Wq|Wk|Wv]  (N=384, h plane only — l planes are never consumed)
        mma_go(pxth, pxtl, Wh + WO_QKV, Wl + WO_QKV, psp /*unused*/,
               BL, 3*Dc, Dc, Dc, 3*Dc, 3*Dc,
               1, 0, 0, 0, nullptr, 0, 0, 4, pqkvh, nullptr);

        // fused attention: S (single-term) + meanv partials + softmax + P@V
        {
            dim3 grid(4, Bc * 2);
            fattn_kernel<<<grid, 512, FA_SMEM>>>(pqkvh, pmask, psp, pmvp);
        }
        meanred_kernel<<<Bc, Lc>>>();
        stats_kernel<<<1, Lc>>>();

        // vb = x @ Wv (fp32, 3-term; Wv = QKV cols 256..383) — feeds 0.9-weighted branch
        mma_go(pxh, pxl, Wh + WO_QKV + 256, Wl + WO_QKV + 256, pvb,
               BL, Dc, Dc, Dc, 3*Dc, Dc,
               1, 0, 0, 0, nullptr, 0, 0, 1, nullptr, nullptr);

        combine_kernel<<<BL, Dc>>>();

        // a = o @ Wp + x
        mma_go(poh, pol, Wh + WO_P, Wl + WO_P, psp /*unused*/,
               BL, Dc, Dc, Dc, Dc, Dc,
               1, 0, 0, 0, px, Dc, 1, 2, pah, pal);

        // h = GELU(a @ F1)  (N=256)
        mma_go(pah, pal, Wh + WO_F1, Wl + WO_F1, psp /*unused*/,
               BL, 2*Dc, Dc, Dc, 2*Dc, 2*Dc,
               1, 0, 0, 0, nullptr, 0, 2, 2, phh, phl);

        // x = h @ F2  (K=256) -> fp32 x + planes
        mma_go(phh, phl, Wh + WO_F2, Wl + WO_F2, px,
               BL, Dc, 2*Dc, 2*Dc, Dc, Dc,
               1, 0, 0, 0, nullptr, 0, 0, 3, pxh, pxl);
    }

    gather_kernel<<<Bc, Dc>>>(lengths, out);
}

// round 16
// speedup vs baseline: 3.0343x; 1.3038x over previous
#include <cuda_runtime.h>
#include <cuda_bf16.h>
#include <math.h>
#include <stdint.h>

#ifndef M_PI
#define M_PI 3.14159265358979323846
#endif

#define Bc 256
#define Lc 256
#define Dc 128
#define NLc 2
#define TOPKc 5
#define NUM_TOTAL_C 100000
#define INV_SQRT_E 0.125f
#define INV_SQRT_2F 0.70710678118654752440f

typedef __nv_bfloat16 bf16;

// ---------------- scratch ----------------
__device__ float g_x   [Bc*Lc*Dc];
__device__ float g_mask[Bc*Lc];
__device__ float g_vb  [Bc*Lc*Dc];
__device__ float g_sp  [Bc*Lc*Dc];
__device__ float g_mv  [Bc*Lc];
__device__ float g_mvp [16*Bc*Lc];
__device__ int   g_delays[TOPKc];
__device__ float g_w   [Bc*TOPKc];
__device__ float g_cs  [NLc*Lc];

// h/l plane pairs (logical K, no tripling in memory)
__device__ bf16 g_xh  [Bc*Lc*Dc];
__device__ bf16 g_xl  [Bc*Lc*Dc];
__device__ bf16 g_xth [Bc*Lc*Dc];
__device__ bf16 g_qkvh[(size_t)Bc*Lc*3*Dc];
__device__ bf16 g_oh  [Bc*Lc*Dc];
__device__ bf16 g_ol  [Bc*Lc*Dc];
__device__ bf16 g_ah  [Bc*Lc*Dc];
__device__ bf16 g_al  [Bc*Lc*Dc];
__device__ bf16 g_hh  [Bc*Lc*2*Dc];
__device__ bf16 g_hl  [Bc*Lc*2*Dc];
__device__ bf16 g_Cmh [NLc*Lc*Lc];
__device__ bf16 g_Cml [NLc*Lc*Lc];
__device__ bf16 g_Wh  [NLc*131072];  // per layer: [QKV 0..49151][Wp][F1][F2]
__device__ bf16 g_Wl  [NLc*131072];

#define WO_QKV 0
#define WO_P   49152
#define WO_F1  65536
#define WO_F2  98304

__device__ const int c_lefts [NLc] = {51, 0};
__device__ const int c_rights[NLc] = {129, 78};

// ---------------- PTX helpers ----------------
__device__ __forceinline__ uint32_t smem_u32(const void* p) {
    return (uint32_t)__cvta_generic_to_shared(p);
}
__device__ __forceinline__ void cpasync16(void* sp, const void* gp) {
    asm volatile("cp.async.cg.shared.global [%0], [%1], 16;"
                 :: "r"(smem_u32(sp)), "l"(gp));
}
#define CP_COMMIT() asm volatile("cp.async.commit_group;")
#define CP_WAIT0()  asm volatile("cp.async.wait_group 0;")
#define CP_WAIT1()  asm volatile("cp.async.wait_group 1;")

#define LDSM_X4(r0,r1,r2,r3,addr) \
    asm volatile("ldmatrix.sync.aligned.m8n8.x4.shared.b16 {%0,%1,%2,%3}, [%4];" \
        : "=r"(r0),"=r"(r1),"=r"(r2),"=r"(r3) : "r"(addr))
#define LDSM_X4_T(r0,r1,r2,r3,addr) \
    asm volatile("ldmatrix.sync.aligned.m8n8.x4.trans.shared.b16 {%0,%1,%2,%3}, [%4];" \
        : "=r"(r0),"=r"(r1),"=r"(r2),"=r"(r3) : "r"(addr))

#define MMA_BF16(d, a, b0v, b1v) \
    asm volatile("mma.sync.aligned.m16n8k16.row.col.f32.bf16.bf16.f32 " \
        "{%0,%1,%2,%3}, {%4,%5,%6,%7}, {%8,%9}, {%0,%1,%2,%3};" \
        : "+f"(d[0]), "+f"(d[1]), "+f"(d[2]), "+f"(d[3]) \
        : "r"(a[0]), "r"(a[1]), "r"(a[2]), "r"(a[3]), "r"(b0v), "r"(b1v))

__device__ __forceinline__ void split_hl(float v, bf16& h, bf16& l) {
    h = __float2bfloat16(v);
    l = __float2bfloat16(v - __bfloat162float(h));
}

// ---------------- plane-format tensor GEMM, 3-stage pipeline ----------------
// nterms==3: C = Ah*Bh + Al*Bh + Ah*Bl; nterms==1: C = Ah*Bh (Al/Bl never read).
// emit bits: 1 = fp32 C; 2 = h+l planes -> Oh/Ol; 4 = h plane only -> Oh.
// fuse: 0 none, 1 +=R, 2 exact-erf GELU.
#define MMA_SE 18944                       // elements per stage
#define MMA_SMEM_BYTES (3*MMA_SE*2)        // 113664 bytes

__global__ __launch_bounds__(256, 2)
void mma_kernel(const bf16* __restrict__ Ah, const bf16* __restrict__ Al,
                const bf16* __restrict__ Bh, const bf16* __restrict__ Bl,
                float* __restrict__ C,
                int K, int lda, int ldb, int ldc,
                long sA, long sB, long sC,
                const float* __restrict__ R, int ldr, int fuse,
                int emit, bf16* __restrict__ Oh, bf16* __restrict__ Ol,
                int nterms)
{
    extern __shared__ bf16 smp[];
    const int tid  = threadIdx.x;
    const int warp = tid >> 5;
    const int lane = tid & 31;
    const int warpM0 = (warp & 1) * 64;
    const int warpN0 = (warp >> 1) * 32;

    const int z = blockIdx.z;
    Ah += (size_t)z * sA;  Al += (size_t)z * sA;
    Bh += (size_t)z * sB;  Bl += (size_t)z * sB;
    const long co = (size_t)z * sC;

    const int m0 = blockIdx.x * 128;
    const int n0 = blockIdx.y * 128;

    auto load_tiles = [&](int st, int k0) {
        bf16* ah_s = smp + st * MMA_SE;
        bf16* al_s = ah_s + 5120;
        bf16* bh_s = ah_s + 10240;
        bf16* bl_s = ah_s + 14592;
        #pragma unroll
        for (int i = 0; i < 2; i++) {
            int c = tid + i * 256;
            int row = c >> 2, kc = (c & 3) << 3;
            cpasync16(ah_s + row*40 + kc, Ah + (size_t)(m0 + row) * lda + k0 + kc);
            if (nterms == 3)
                cpasync16(al_s + row*40 + kc, Al + (size_t)(m0 + row) * lda + k0 + kc);
        }
        #pragma unroll
        for (int i = 0; i < 2; i++) {
            int c = tid + i * 256;
            int row = c >> 4, nc = (c & 15) << 3;
            cpasync16(bh_s + row*136 + nc, Bh + (size_t)(k0 + row) * ldb + n0 + nc);
            if (nterms == 3)
                cpasync16(bl_s + row*136 + nc, Bl + (size_t)(k0 + row) * ldb + n0 + nc);
        }
    };

    float acc[4][2][2][4];
    #pragma unroll
    for (int i = 0; i < 4; i++)
        #pragma unroll
        for (int j = 0; j < 2; j++)
            #pragma unroll
            for (int s = 0; s < 2; s++)
                #pragma unroll
                for (int q = 0; q < 4; q++) acc[i][j][s][q] = 0.f;

    const int nk = K / 32;
    load_tiles(0, 0);
    CP_COMMIT();
    if (nk > 1) { load_tiles(1, 32); CP_COMMIT(); }

    for (int kt = 0; kt < nk; kt++) {
        if (kt + 1 < nk) CP_WAIT1(); else CP_WAIT0();
        __syncthreads();
        if (kt + 2 < nk) { load_tiles((kt + 2) % 3, (kt + 2) * 32); CP_COMMIT(); }

        bf16* ah_s = smp + (kt % 3) * MMA_SE;
        bf16* al_s = ah_s + 5120;
        bf16* bh_s = ah_s + 10240;
        bf16* bl_s = ah_s + 14592;

        #pragma unroll
        for (int ks = 0; ks < 2; ks++) {
            const int acol = ks*16 + ((lane >> 4) << 3);
            uint32_t ah[4][4], bh[2][4];
            #pragma unroll
            for (int tm = 0; tm < 4; tm++) {
                uint32_t ad = smem_u32(&ah_s[(warpM0 + tm*16 + (lane & 15))*40 + acol]);
                LDSM_X4(ah[tm][0], ah[tm][1], ah[tm][2], ah[tm][3], ad);
            }
            #pragma unroll
            for (int tn = 0; tn < 2; tn++) {
                uint32_t ad = smem_u32(&bh_s[(ks*16 + (lane & 15))*136
                                             + warpN0 + tn*16 + ((lane >> 4) << 3)]);
                LDSM_X4_T(bh[tn][0], bh[tn][1], bh[tn][2], bh[tn][3], ad);
            }
            // term 1: ah * bh
            #pragma unroll
            for (int tm = 0; tm < 4; tm++)
                #pragma unroll
                for (int tn = 0; tn < 2; tn++) {
                    MMA_BF16(acc[tm][tn][0], ah[tm], bh[tn][0], bh[tn][1]);
                    MMA_BF16(acc[tm][tn][1], ah[tm], bh[tn][2], bh[tn][3]);
                }
            if (nterms == 3) {
                // term 2: al * bh
                {
                    uint32_t xf[4][4];
                    #pragma unroll
                    for (int tm = 0; tm < 4; tm++) {
                        uint32_t ad = smem_u32(&al_s[(warpM0 + tm*16 + (lane & 15))*40 + acol]);
                        LDSM_X4(xf[tm][0], xf[tm][1], xf[tm][2], xf[tm][3], ad);
                    }
                    #pragma unroll
                    for (int tm = 0; tm < 4; tm++)
                        #pragma unroll
                        for (int tn = 0; tn < 2; tn++) {
                            MMA_BF16(acc[tm][tn][0], xf[tm], bh[tn][0], bh[tn][1]);
                            MMA_BF16(acc[tm][tn][1], xf[tm], bh[tn][2], bh[tn][3]);
                        }
                }
                // term 3: ah * bl
                {
                    uint32_t bl[2][4];
                    #pragma unroll
                    for (int tn = 0; tn < 2; tn++) {
                        uint32_t ad = smem_u32(&bl_s[(ks*16 + (lane & 15))*136
                                                     + warpN0 + tn*16 + ((lane >> 4) << 3)]);
                        LDSM_X4_T(bl[tn][0], bl[tn][1], bl[tn][2], bl[tn][3], ad);
                    }
                    #pragma unroll
                    for (int tm = 0; tm < 4; tm++)
                        #pragma unroll
                        for (int tn = 0; tn < 2; tn++) {
                            MMA_BF16(acc[tm][tn][0], ah[tm], bl[tn][0], bl[tn][1]);
                            MMA_BF16(acc[tm][tn][1], ah[tm], bl[tn][2], bl[tn][3]);
                        }
                }
            }
        }
    }

    // epilogue
    #pragma unroll
    for (int tm = 0; tm < 4; tm++)
        #pragma unroll
        for (int tn = 0; tn < 2; tn++)
            #pragma unroll
            for (int s = 0; s < 2; s++) {
                int col = n0 + warpN0 + tn*16 + s*8 + ((lane & 3) << 1);
                float* cc = acc[tm][tn][s];
                #pragma unroll
                for (int hr = 0; hr < 2; hr++) {
                    int row = m0 + warpM0 + tm*16 + (lane >> 2) + hr*8;
                    float2 v = make_float2(cc[hr*2 + 0], cc[hr*2 + 1]);
                    if (fuse == 1) {
                        float2 r = *(const float2*)&R[(size_t)row * ldr + col];
                        v.x += r.x; v.y += r.y;
                    } else if (fuse == 2) {
                        v.x = v.x * 0.5f * (1.0f + erff(v.x * INV_SQRT_2F));
                        v.y = v.y * 0.5f * (1.0f + erff(v.y * INV_SQRT_2F));
                    }
                    size_t ci = co + (size_t)row * ldc + col;
                    if (emit & 1) *(float2*)&C[ci] = v;
                    if (emit & 6) {
                        bf16 hx, lx, hy, ly;
                        split_hl(v.x, hx, lx);
                        split_hl(v.y, hy, ly);
                        __nv_bfloat162 hv; hv.x = hx; hv.y = hy;
                        *(__nv_bfloat162*)&Oh[ci] = hv;
                        if (emit & 2) {
                            __nv_bfloat162 lv; lv.x = lx; lv.y = ly;
                            *(__nv_bfloat162*)&Ol[ci] = lv;
                        }
                    }
                }
            }
}

// ---------------- fused attention (occ 2: 105.5KB smem, 512 threads) ----------------
// Region layout:
//   [0, 36864)            Vh [256][72] bf16                (whole kernel)
//   R = [36864, 104448):  phase1 Qh[64][72]+Kh[256][72]  ->
//                         Ss [64][264] f32 (overlay)      ->
//                         Ph [64][264] bf16 (in-place overlay, first 33792 B)
//                         Os [64][68] f32 at R+34816 (17408 B, after Ph)
//   [104448, 105472)      mk [256] f32
#define FA_VH 0
#define FA_R  36864
#define FA_QH (FA_R)
#define FA_KH (FA_R + 9216)
#define FA_SS (FA_R)
#define FA_PH (FA_R)
#define FA_OS (FA_R + 34816)
#define FA_MK 104448
#define FA_SMEM 105472

__global__ __launch_bounds__(512, 2)
void fattn_kernel(const bf16* __restrict__ qkvh,
                  const float* __restrict__ maskg,
                  float* __restrict__ sp, float* __restrict__ mvp)
{
    extern __shared__ char sm[];
    bf16*  Vh = (bf16*) (sm + FA_VH);
    bf16*  Qh = (bf16*) (sm + FA_QH);
    bf16*  Kh = (bf16*) (sm + FA_KH);
    float* Ss = (float*)(sm + FA_SS);
    bf16*  Ph = (bf16*) (sm + FA_PH);
    float* Os = (float*)(sm + FA_OS);
    float* mk = (float*)(sm + FA_MK);

    const int tid = threadIdx.x, warp = tid >> 5, lane = tid & 31;
    const int q0 = blockIdx.x * 64;
    const int b  = blockIdx.y >> 1, h = blockIdx.y & 1;

    // prologue loads (h planes only)
    const bf16* qg = qkvh + ((size_t)(b*Lc + q0)) * 384 + h*64;
    const bf16* kg = qkvh + ((size_t)(b*Lc)) * 384 + 128 + h*64;
    const bf16* vg = qkvh + ((size_t)(b*Lc)) * 384 + 256 + h*64;

    {
        int c = tid;                        // Q: exactly 512 16B chunks
        int r = c >> 3, kc = (c & 7) << 3;
        cpasync16(&Qh[r*72 + kc], qg + (size_t)r*384 + kc);
    }
    for (int c = tid; c < 2048; c += 512) { // K, V: 2048 chunks each
        int r = c >> 3, kc = (c & 7) << 3;
        cpasync16(&Kh[r*72 + kc], kg + (size_t)r*384 + kc);
        cpasync16(&Vh[r*72 + kc], vg + (size_t)r*384 + kc);
    }
    if (tid < 64)
        cpasync16(&mk[tid*4], maskg + b*Lc + tid*4);
    CP_COMMIT(); CP_WAIT0();
    __syncthreads();

    // phase 1: S = Qh @ Kh^T   (M=64, N=256, K=64, single term)
    {
        const int wM = (warp & 1) * 32;
        const int wN = (warp >> 1) * 32;
        float accS[2][2][2][4];
        #pragma unroll
        for (int i=0;i<2;i++) for (int j=0;j<2;j++) for (int s=0;s<2;s++)
            for (int q=0;q<4;q++) accS[i][j][s][q] = 0.f;

        #pragma unroll
        for (int kf = 0; kf < 4; kf++) {
            const int kcol = kf*16 + ((lane >> 4) << 3);
            uint32_t qa[2][4], ka[2][4];
            #pragma unroll
            for (int mf = 0; mf < 2; mf++) {
                int ro = (wM + mf*16 + (lane & 15))*72 + kcol;
                LDSM_X4(qa[mf][0], qa[mf][1], qa[mf][2], qa[mf][3], smem_u32(&Qh[ro]));
            }
            #pragma unroll
            for (int tn = 0; tn < 2; tn++) {
                int ro = (wN + tn*16 + (lane & 15))*72 + kcol;
                LDSM_X4(ka[tn][0], ka[tn][1], ka[tn][2], ka[tn][3], smem_u32(&Kh[ro]));
            }
            #pragma unroll
            for (int mf = 0; mf < 2; mf++)
                #pragma unroll
                for (int tn = 0; tn < 2; tn++) {
                    MMA_BF16(accS[mf][tn][0], qa[mf], ka[tn][0], ka[tn][2]);
                    MMA_BF16(accS[mf][tn][1], qa[mf], ka[tn][1], ka[tn][3]);
                }
        }
        __syncthreads();   // Qh/Kh reads done before Ss overlays them

        #pragma unroll
        for (int mf = 0; mf < 2; mf++)
            #pragma unroll
            for (int tn = 0; tn < 2; tn++)
                #pragma unroll
                for (int s = 0; s < 2; s++)
                    #pragma unroll
                    for (int hr = 0; hr < 2; hr++) {
                        int row = wM + mf*16 + (lane >> 2) + hr*8;
                        int col = wN + tn*16 + s*8 + ((lane & 3) << 1);
                        *(float2*)&Ss[row*264 + col] =
                            make_float2(accS[mf][tn][s][hr*2], accS[mf][tn][s][hr*2+1]);
                    }
    }
    __syncthreads();

    // meanv partials (raw scores, diagonal sums)
    {
        int d = tid & 255, half = tid >> 8;
        float s = 0.f;
        #pragma unroll 8
        for (int m = half*32; m < half*32 + 32; m++)
            s += Ss[m*264 + ((q0 + m - d) & 255)];
        int p = (blockIdx.x*2 + h)*2 + half;
        mvp[((size_t)p * Bc + b) * Lc + d] = s * (1.0f/128.0f);
    }
    __syncthreads();

    // softmax -> Ph written IN PLACE over Ss (register-buffered; barrier between
    // all Ss reads and the overlapping bf16 writes)
    {
        int row = tid >> 3, part = tid & 7;
        float* Sr = &Ss[row*264 + part*32];
        const float* mr = &mk[part*32];
        float r[32];
        #pragma unroll
        for (int j = 0; j < 32; j++)
            r[j] = Sr[j] * INV_SQRT_E + mr[j];
        float mx = -1e30f;
        #pragma unroll
        for (int j = 0; j < 32; j++) mx = fmaxf(mx, r[j]);
        mx = fmaxf(mx, __shfl_xor_sync(0xffffffffu, mx, 1));
        mx = fmaxf(mx, __shfl_xor_sync(0xffffffffu, mx, 2));
        mx = fmaxf(mx, __shfl_xor_sync(0xffffffffu, mx, 4));
        float sum = 0.f;
        #pragma unroll
        for (int j = 0; j < 32; j++) { r[j] = expf(r[j] - mx); sum += r[j]; }
        sum += __shfl_xor_sync(0xffffffffu, sum, 1);
        sum += __shfl_xor_sync(0xffffffffu, sum, 2);
        sum += __shfl_xor_sync(0xffffffffu, sum, 4);
        float inv = 1.0f / sum;
        __syncthreads();   // ALL Ss float reads complete before bf16 overlay writes
        bf16* ph = &Ph[row*264 + part*32];
        #pragma unroll
        for (int j = 0; j < 32; j++)
            ph[j] = __float2bfloat16(r[j] * inv);
    }
    __syncthreads();

    // phase 2: O = Ph @ Vh  (M=64, N=64, K=256), K-split across 2 warp groups
    {
        const int w8  = warp & 7;
        const int kh  = warp >> 3;
        const int wM2 = (w8 & 1) * 32;
        const int wN2 = ((w8 >> 1) & 3) * 16;
        float o[2][2][4];
        #pragma unroll
        for (int i=0;i<2;i++) for (int s=0;s<2;s++) for (int q=0;q<4;q++) o[i][s][q]=0.f;

        for (int kf = kh*8; kf < kh*8 + 8; kf++) {
            uint32_t ah[2][4], bh[4];
            #pragma unroll
            for (int mf = 0; mf < 2; mf++) {
                uint32_t ro = (wM2 + mf*16 + (lane & 15))*264 + kf*16 + ((lane >> 4) << 3);
                LDSM_X4(ah[mf][0], ah[mf][1], ah[mf][2], ah[mf][3], smem_u32(&Ph[ro]));
            }
            {
                uint32_t vo = (kf*16 + (lane & 15))*72 + wN2 + ((lane >> 4) << 3);
                LDSM_X4_T(bh[0], bh[1], bh[2], bh[3], smem_u32(&Vh[vo]));
            }
            #pragma unroll
            for (int mf = 0; mf < 2; mf++) {
                MMA_BF16(o[mf][0], ah[mf], bh[0], bh[1]);
                MMA_BF16(o[mf][1], ah[mf], bh[2], bh[3]);
            }
        }
        __syncthreads();
        if (kh == 1) {
            #pragma unroll
            for (int mf = 0; mf < 2; mf++)
                #pragma unroll
                for (int s = 0; s < 2; s++)
                    #pragma unroll
                    for (int hr = 0; hr < 2; hr++) {
                        int rl = wM2 + mf*16 + (lane >> 2) + hr*8;
                        int cl = wN2 + s*8 + ((lane & 3) << 1);
                        *(float2*)&Os[rl*68 + cl] =
                            make_float2(o[mf][s][hr*2], o[mf][s][hr*2+1]);
                    }
        }
        __syncthreads();
        if (kh == 0) {
            #pragma unroll
            for (int mf = 0; mf < 2; mf++)
                #pragma unroll
                for (int s = 0; s < 2; s++)
                    #pragma unroll
                    for (int hr = 0; hr < 2; hr++) {
                        int rl = wM2 + mf*16 + (lane >> 2) + hr*8;
                        int cl = wN2 + s*8 + ((lane & 3) << 1);
                        float2 p = *(float2*)&Os[rl*68 + cl];
                        int row = q0 + rl;
                        int col = h*64 + cl;
                        *(float2*)&sp[((size_t)b*Lc + row)*Dc + col] =
                            make_float2(o[mf][s][hr*2] + p.x, o[mf][s][hr*2+1] + p.y);
                    }
        }
    }
}

// ---------------- small kernels ----------------
__global__ void build_x_kernel(const int* __restrict__ paths,
                               const float* __restrict__ ego,
                               const float* __restrict__ pos)
{
    int bl = blockIdx.x, c = threadIdx.x;
    int p = paths[bl], l = bl & (Lc - 1);
    float v = ego[(size_t)p * Dc + c] + pos[l * Dc + c];
    g_x[(size_t)bl * Dc + c] = v;
    bf16 h, lo; split_hl(v, h, lo);
    g_xh[(size_t)bl * Dc + c] = h;
    g_xl[(size_t)bl * Dc + c] = lo;
    if (c == 0) g_mask[bl] = (p < NUM_TOTAL_C) ? 0.f : -10000.f;
}

// band-pass impulse responses, both layers, one launch
__global__ void build_cs_kernel()
{
    int layer = blockIdx.x, n = threadIdx.x;
    int left = c_lefts[layer], right = c_rights[layer];
    double s = 0.0;
    for (int f = left; f < right; f++) {
        double w;
        if (f == 0)           w = 1.0;
        else if (f == Lc/2)   w = (n & 1) ? -1.0 : 1.0;
        else                  w = 2.0 * cos(2.0 * M_PI * (double)f * (double)n / (double)Lc);
        s += w;
    }
    g_cs[layer*Lc + n] = (float)(s / (double)Lc);
}

// circulant plane build, both layers
__global__ void buildC_kernel()
{
    int n = blockIdx.x, layer = blockIdx.y, m = threadIdx.x;
    float v = g_cs[layer*Lc + ((n - m + Lc) & (Lc - 1))];
    bf16 h, l; split_hl(v, h, l);
    g_Cmh[layer*Lc*Lc + n*Lc + m] = h;
    g_Cml[layer*Lc*Lc + n*Lc + m] = l;
}

// all weights, both layers -> h/l planes; QKV concatenated along N
__global__ void convW_kernel(const float* __restrict__ Wq, const float* __restrict__ Wk,
                             const float* __restrict__ Wv, const float* __restrict__ Wp,
                             const float* __restrict__ F1, const float* __restrict__ F2)
{
    int gidx = blockIdx.x * 256 + threadIdx.x;     // 0..262143
    int layer = gidx >> 17;
    int idx = gidx & 131071;
    float v;
    if (idx < 49152) {
        int k = idx / 384, c = idx - k*384;
        int w = c >> 7, n = c & 127;
        const float* src = (w == 0 ? Wq : w == 1 ? Wk : Wv) + layer*Dc*Dc;
        v = src[k*128 + n];
    } else if (idx < 65536) {
        v = Wp[layer*Dc*Dc + idx - 49152];
    } else if (idx < 98304) {
        v = F1[layer*Dc*2*Dc + idx - 65536];
    } else {
        v = F2[layer*2*Dc*Dc + idx - 98304];
    }
    bf16 h, l; split_hl(v, h, l);
    g_Wh[layer*131072 + idx] = h;
    g_Wl[layer*131072 + idx] = l;
}

__global__ void meanred_kernel()
{
    int b = blockIdx.x, d = threadIdx.x;
    float s = 0.f;
    #pragma unroll
    for (int p = 0; p < 16; p++) s += g_mvp[((size_t)p * Bc + b) * Lc + d];
    g_mv[b * Lc + d] = s;
}

__global__ void stats_kernel()
{
    __shared__ float sv[Lc];
    __shared__ int   si[Lc];
    __shared__ int   dls[TOPKc];
    int t = threadIdx.x;

    float s = 0.f;
    for (int b = 0; b < Bc; b++) s += g_mv[b * Lc + t];
    float my = s * (1.0f / (float)Bc);

    for (int it = 0; it < TOPKc; it++) {
        sv[t] = my; si[t] = t;
        __syncthreads();
        for (int st = 128; st > 0; st >>= 1) {
            if (t < st) {
                float v2 = sv[t + st]; int i2 = si[t + st];
                if (v2 > sv[t] || (v2 == sv[t] && i2 < si[t])) { sv[t] = v2; si[t] = i2; }
            }
            __syncthreads();
        }
        int win = si[0];
        if (t == 0) { g_delays[it] = win; dls[it] = win; }
        __syncthreads();
        if (t == win) my = -INFINITY;
    }

    float w[TOPKc];
    float mx = -1e30f;
    #pragma unroll
    for (int i = 0; i < TOPKc; i++) {
        w[i] = g_mv[t * Lc + dls[i]];
        mx = fmaxf(mx, w[i]);
    }
    float sm = 0.f;
    #pragma unroll
    for (int i = 0; i < TOPKc; i++) { w[i] = expf(w[i] - mx); sm += w[i]; }
    float inv = 1.0f / sm;
    #pragma unroll
    for (int i = 0; i < TOPKc; i++) g_w[t * TOPKc + i] = w[i] * inv;
}

// 0.9*freq + 0.1*spatial -> h/l planes
__global__ void combine_kernel()
{
    int bl = blockIdx.x, c = threadIdx.x;
    int b = bl >> 8, l = bl & 255;
    __shared__ float w[TOPKc];
    __shared__ int   dl[TOPKc];
    if (c < TOPKc) { w[c] = g_w[b * TOPKc + c]; dl[c] = g_delays[c]; }
    __syncthreads();
    float f = 0.f;
    #pragma unroll
    for (int t = 0; t < TOPKc; t++) {
        int ls = (l + dl[t]) & 255;
        f += w[t] * g_vb[((size_t)b * Lc + ls) * Dc + c];
    }
    float v = 0.9f * f + 0.1f * g_sp[(size_t)bl * Dc + c];
    bf16 h, lo; split_hl(v, h, lo);
    g_oh[(size_t)bl * Dc + c] = h;
    g_ol[(size_t)bl * Dc + c] = lo;
}

__global__ void gather_kernel(const int* __restrict__ lengths, float* __restrict__ out)
{
    int b = blockIdx.x, c = threadIdx.x;
    int l = lengths[b] - 1;
    out[b * Dc + c] = g_x[((size_t)b * Lc + l) * Dc + c];
}

// ---------------- host side ----------------
static inline void mma_go(const bf16* Ah, const bf16* Al,
                          const bf16* Bh, const bf16* Bl, float* C,
                          int M, int N, int K, int lda, int ldb, int ldc,
                          int batch, long sA, long sB, long sC,
                          const float* R, int ldr, int fuse,
                          int emit, bf16* Oh, bf16* Ol, int nterms)
{
    dim3 grid(M / 128, N / 128, batch);
    mma_kernel<<<grid, 256, MMA_SMEM_BYTES>>>(Ah, Al, Bh, Bl, C, K, lda, ldb, ldc,
        sA, sB, sC, R, ldr, fuse, emit, Oh, Ol, nterms);
}

extern "C" void kernel_launch(void* const* d_in, const int* in_sizes, int n_in,
                              void* d_out, int out_size)
{
    (void)in_sizes; (void)n_in; (void)out_size;
    const int*   paths   = (const int*)  d_in[0];
    const int*   lengths = (const int*)  d_in[1];
    const float* ego     = (const float*)d_in[4];
    const float* pos     = (const float*)d_in[5];
    const float* Wq      = (const float*)d_in[6];
    const float* Wk      = (const float*)d_in[7];
    const float* Wv      = (const float*)d_in[8];
    const float* Wp      = (const float*)d_in[9];
    const float* F1      = (const float*)d_in[10];
    const float* F2      = (const float*)d_in[11];
    float* out = (float*)d_out;

    float *px, *pmask, *pvb, *psp, *pmvp;
    bf16 *pxh, *pxl, *pxth, *pqkvh, *poh, *pol, *pah, *pal,
         *phh, *phl, *pCmh, *pCml, *pWh, *pWl;
    cudaGetSymbolAddress((void**)&px,    g_x);
    cudaGetSymbolAddress((void**)&pmask, g_mask);
    cudaGetSymbolAddress((void**)&pvb,   g_vb);
    cudaGetSymbolAddress((void**)&psp,   g_sp);
    cudaGetSymbolAddress((void**)&pmvp,  g_mvp);
    cudaGetSymbolAddress((void**)&pxh,   g_xh);
    cudaGetSymbolAddress((void**)&pxl,   g_xl);
    cudaGetSymbolAddress((void**)&pxth,  g_xth);
    cudaGetSymbolAddress((void**)&pqkvh, g_qkvh);
    cudaGetSymbolAddress((void**)&poh,   g_oh);
    cudaGetSymbolAddress((void**)&pol,   g_ol);
    cudaGetSymbolAddress((void**)&pah,   g_ah);
    cudaGetSymbolAddress((void**)&pal,   g_al);
    cudaGetSymbolAddress((void**)&phh,   g_hh);
    cudaGetSymbolAddress((void**)&phl,   g_hl);
    cudaGetSymbolAddress((void**)&pCmh,  g_Cmh);
    cudaGetSymbolAddress((void**)&pCml,  g_Cml);
    cudaGetSymbolAddress((void**)&pWh,   g_Wh);
    cudaGetSymbolAddress((void**)&pWl,   g_Wl);

    // No static guards (harness contract): set attributes unconditionally.
    cudaFuncSetAttribute(fattn_kernel,
                         cudaFuncAttributeMaxDynamicSharedMemorySize, FA_SMEM);
    cudaFuncSetAttribute(mma_kernel,
                         cudaFuncAttributeMaxDynamicSharedMemorySize, MMA_SMEM_BYTES);

    const int  BL = Bc * Lc;
    const long LD = (long)Lc * Dc;

    // input prep: x build + both layers' filters/weights, all upfront
    build_x_kernel<<<BL, Dc>>>(paths, ego, pos);
    build_cs_kernel<<<NLc, Lc>>>();
    buildC_kernel<<<dim3(Lc, NLc), Lc>>>();
    convW_kernel<<<1024, 256>>>(Wq, Wk, Wv, Wp, F1, F2);

    for (int k = 0; k < NLc; k++) {
        const bf16* Cmh = pCmh + (size_t)k * Lc * Lc;
        const bf16* Cml = pCml + (size_t)k * Lc * Lc;
        const bf16* Wh  = pWh  + (size_t)k * 131072;
        const bf16* Wl  = pWl  + (size_t)k * 131072;

        // xt = Cm @ x (batched over b), h-plane output only
        mma_go(Cmh, Cml, pxh, pxl, psp /*unused*/,
               Lc, Dc, Lc, Lc, Dc, Dc,
               Bc, 0, LD, LD, nullptr, 0, 0, 4, pxth, nullptr, 3);

        // qkv = xt @ [Wq|Wk|Wv]  (N=384, SINGLE-TERM: S-path proven noise-tolerant)
        mma_go(pxth, pxth, Wh + WO_QKV, Wh + WO_QKV, psp /*unused*/,
               BL, 3*Dc, Dc, Dc, 3*Dc, 3*Dc,
               1, 0, 0, 0, nullptr, 0, 0, 4, pqkvh, nullptr, 1);

        // fused attention: S (single-term) + meanv partials + softmax + P@V, occ 2
        {
            dim3 grid(4, Bc * 2);
            fattn_kernel<<<grid, 512, FA_SMEM>>>(pqkvh, pmask, psp, pmvp);
        }
        meanred_kernel<<<Bc, Lc>>>();
        stats_kernel<<<1, Lc>>>();

        // vb = x @ Wv (fp32, 3-term; Wv = QKV cols 256..383) — 0.9-weighted branch
        mma_go(pxh, pxl, Wh + WO_QKV + 256, Wl + WO_QKV + 256, pvb,
               BL, Dc, Dc, Dc, 3*Dc, Dc,
               1, 0, 0, 0, nullptr, 0, 0, 1, nullptr, nullptr, 3);

        combine_kernel<<<BL, Dc>>>();

        // a = o @ Wp + x
        mma_go(poh, pol, Wh + WO_P, Wl + WO_P, psp /*unused*/,
               BL, Dc, Dc, Dc, Dc, Dc,
               1, 0, 0, 0, px, Dc, 1, 2, pah, pal, 3);

        // h = GELU(a @ F1)  (N=256)
        mma_go(pah, pal, Wh + WO_F1, Wl + WO_F1, psp /*unused*/,
               BL, 2*Dc, Dc, Dc, 2*Dc, 2*Dc,
               1, 0, 0, 0, nullptr, 0, 2, 2, phh, phl, 3);

        // x = h @ F2  (K=256) -> fp32 x + planes
        mma_go(phh, phl, Wh + WO_F2, Wl + WO_F2, px,
               BL, Dc, 2*Dc, 2*Dc, Dc, Dc,
               1, 0, 0, 0, nullptr, 0, 0, 3, pxh, pxl, 3);
    }

    gather_kernel<<<Bc, Dc>>>(lengths, out);
}

// round 17
// speedup vs baseline: 3.0895x; 1.0182x over previous
#include <cuda_runtime.h>
#include <cuda_bf16.h>
#include <math.h>
#include <stdint.h>

#ifndef M_PI
#define M_PI 3.14159265358979323846
#endif

#define Bc 256
#define Lc 256
#define Dc 128
#define NLc 2
#define TOPKc 5
#define NUM_TOTAL_C 100000
#define INV_SQRT_E 0.125f
#define INV_SQRT_2F 0.70710678118654752440f

typedef __nv_bfloat16 bf16;

// ---------------- scratch ----------------
__device__ float g_x   [Bc*Lc*Dc];
__device__ float g_mask[Bc*Lc];
__device__ float g_vb  [Bc*Lc*Dc];
__device__ float g_sp  [Bc*Lc*Dc];
__device__ float g_mv  [Bc*Lc];
__device__ float g_mvp [16*Bc*Lc];
__device__ int   g_delays[TOPKc];
__device__ float g_w   [Bc*TOPKc];
__device__ float g_cs  [NLc*Lc];

__device__ bf16 g_xh  [Bc*Lc*Dc];
__device__ bf16 g_xl  [Bc*Lc*Dc];
__device__ bf16 g_xth [Bc*Lc*Dc];
__device__ bf16 g_qkvh[(size_t)Bc*Lc*3*Dc];
__device__ bf16 g_oh  [Bc*Lc*Dc];
__device__ bf16 g_ol  [Bc*Lc*Dc];
__device__ bf16 g_ah  [Bc*Lc*Dc];
__device__ bf16 g_al  [Bc*Lc*Dc];
__device__ bf16 g_hh  [Bc*Lc*2*Dc];
__device__ bf16 g_hl  [Bc*Lc*2*Dc];
__device__ bf16 g_Cmh [NLc*Lc*Lc];
__device__ bf16 g_Cml [NLc*Lc*Lc];
__device__ bf16 g_Wh  [NLc*131072];  // per layer: [QKV 0..49151][Wp][F1][F2]
__device__ bf16 g_Wl  [NLc*131072];

#define WO_QKV 0
#define WO_P   49152
#define WO_F1  65536
#define WO_F2  98304

__device__ const int c_lefts [NLc] = {51, 0};
__device__ const int c_rights[NLc] = {129, 78};

// ---------------- PTX helpers ----------------
__device__ __forceinline__ uint32_t smem_u32(const void* p) {
    return (uint32_t)__cvta_generic_to_shared(p);
}
__device__ __forceinline__ void cpasync16(void* sp, const void* gp) {
    asm volatile("cp.async.cg.shared.global [%0], [%1], 16;"
                 :: "r"(smem_u32(sp)), "l"(gp));
}
#define CP_COMMIT() asm volatile("cp.async.commit_group;")
#define CP_WAIT0()  asm volatile("cp.async.wait_group 0;")
#define CP_WAIT1()  asm volatile("cp.async.wait_group 1;")
#define CP_WAIT2()  asm volatile("cp.async.wait_group 2;")
#define CP_WAIT3()  asm volatile("cp.async.wait_group 3;")
#define CP_WAIT4()  asm volatile("cp.async.wait_group 4;")

#define LDSM_X4(r0,r1,r2,r3,addr) \
    asm volatile("ldmatrix.sync.aligned.m8n8.x4.shared.b16 {%0,%1,%2,%3}, [%4];" \
        : "=r"(r0),"=r"(r1),"=r"(r2),"=r"(r3) : "r"(addr))
#define LDSM_X4_T(r0,r1,r2,r3,addr) \
    asm volatile("ldmatrix.sync.aligned.m8n8.x4.trans.shared.b16 {%0,%1,%2,%3}, [%4];" \
        : "=r"(r0),"=r"(r1),"=r"(r2),"=r"(r3) : "r"(addr))

#define MMA_BF16(d, a, b0v, b1v) \
    asm volatile("mma.sync.aligned.m16n8k16.row.col.f32.bf16.bf16.f32 " \
        "{%0,%1,%2,%3}, {%4,%5,%6,%7}, {%8,%9}, {%0,%1,%2,%3};" \
        : "+f"(d[0]), "+f"(d[1]), "+f"(d[2]), "+f"(d[3]) \
        : "r"(a[0]), "r"(a[1]), "r"(a[2]), "r"(a[3]), "r"(b0v), "r"(b1v))

__device__ __forceinline__ void split_hl(float v, bf16& h, bf16& l) {
    h = __float2bfloat16(v);
    l = __float2bfloat16(v - __bfloat162float(h));
}

// ---------------- plane-format tensor GEMM (templated on term count) ----------------
// NT==3: C = Ah*Bh + Al*Bh + Ah*Bl, 3-stage pipeline.
// NT==1: C = Ah*Bh (Al/Bl never read), 6-stage pipeline (same smem footprint).
// emit bits: 1 = fp32 C; 2 = h+l planes -> Oh/Ol; 4 = h plane only -> Oh.
// fuse: 0 none, 1 +=R, 2 exact-erf GELU.
#define MMA_SMEM_BYTES 113664

template<int NT>
__global__ __launch_bounds__(256, 2)
void mma_kernel(const bf16* __restrict__ Ah, const bf16* __restrict__ Al,
                const bf16* __restrict__ Bh, const bf16* __restrict__ Bl,
                float* __restrict__ C,
                int K, int lda, int ldb, int ldc,
                long sA, long sB, long sC,
                const float* __restrict__ R, int ldr, int fuse,
                int emit, bf16* __restrict__ Oh, bf16* __restrict__ Ol)
{
    constexpr int SE     = (NT == 1) ? 9472 : 18944;   // elements per stage
    constexpr int NS     = (NT == 1) ? 6    : 3;       // pipeline depth
    constexpr int BH_OFF = (NT == 1) ? 5120 : 10240;

    extern __shared__ bf16 smp[];
    const int tid  = threadIdx.x;
    const int warp = tid >> 5;
    const int lane = tid & 31;
    const int warpM0 = (warp & 1) * 64;
    const int warpN0 = (warp >> 1) * 32;

    const int z = blockIdx.z;
    Ah += (size_t)z * sA;  Al += (size_t)z * sA;
    Bh += (size_t)z * sB;  Bl += (size_t)z * sB;
    const long co = (size_t)z * sC;

    const int m0 = blockIdx.x * 128;
    const int n0 = blockIdx.y * 128;

    auto load_tiles = [&](int st, int k0) {
        bf16* ah_s = smp + st * SE;
        bf16* bh_s = ah_s + BH_OFF;
        #pragma unroll
        for (int i = 0; i < 2; i++) {
            int c = tid + i * 256;
            int row = c >> 2, kc = (c & 3) << 3;
            cpasync16(ah_s + row*40 + kc, Ah + (size_t)(m0 + row) * lda + k0 + kc);
            if (NT == 3)
                cpasync16(ah_s + 5120 + row*40 + kc,
                          Al + (size_t)(m0 + row) * lda + k0 + kc);
        }
        #pragma unroll
        for (int i = 0; i < 2; i++) {
            int c = tid + i * 256;
            int row = c >> 4, nc = (c & 15) << 3;
            cpasync16(bh_s + row*136 + nc, Bh + (size_t)(k0 + row) * ldb + n0 + nc);
            if (NT == 3)
                cpasync16(ah_s + 14592 + row*136 + nc,
                          Bl + (size_t)(k0 + row) * ldb + n0 + nc);
        }
    };

    float acc[4][2][2][4];
    #pragma unroll
    for (int i = 0; i < 4; i++)
        #pragma unroll
        for (int j = 0; j < 2; j++)
            #pragma unroll
            for (int s = 0; s < 2; s++)
                #pragma unroll
                for (int q = 0; q < 4; q++) acc[i][j][s][q] = 0.f;

    const int nk = K / 32;
    int committed = 0;
    #pragma unroll
    for (int i = 0; i < NS - 1; i++) {
        if (i < nk) { load_tiles(i, i * 32); CP_COMMIT(); committed++; }
    }

    for (int kt = 0; kt < nk; kt++) {
        const int pa = committed - (kt + 1);  // pending groups allowed after wait
        if (pa <= 0)      CP_WAIT0();
        else if (pa == 1) CP_WAIT1();
        else if (pa == 2) CP_WAIT2();
        else if (pa == 3) CP_WAIT3();
        else              CP_WAIT4();
        __syncthreads();
        if (kt + NS - 1 < nk) {
            load_tiles((kt + NS - 1) % NS, (kt + NS - 1) * 32);
            CP_COMMIT(); committed++;
        }

        bf16* ah_s = smp + (kt % NS) * SE;
        bf16* bh_s = ah_s + BH_OFF;

        #pragma unroll
        for (int ks = 0; ks < 2; ks++) {
            const int acol = ks*16 + ((lane >> 4) << 3);
            uint32_t ah[4][4], bh[2][4];
            #pragma unroll
            for (int tm = 0; tm < 4; tm++) {
                uint32_t ad = smem_u32(&ah_s[(warpM0 + tm*16 + (lane & 15))*40 + acol]);
                LDSM_X4(ah[tm][0], ah[tm][1], ah[tm][2], ah[tm][3], ad);
            }
            #pragma unroll
            for (int tn = 0; tn < 2; tn++) {
                uint32_t ad = smem_u32(&bh_s[(ks*16 + (lane & 15))*136
                                             + warpN0 + tn*16 + ((lane >> 4) << 3)]);
                LDSM_X4_T(bh[tn][0], bh[tn][1], bh[tn][2], bh[tn][3], ad);
            }
            // term 1: ah * bh
            #pragma unroll
            for (int tm = 0; tm < 4; tm++)
                #pragma unroll
                for (int tn = 0; tn < 2; tn++) {
                    MMA_BF16(acc[tm][tn][0], ah[tm], bh[tn][0], bh[tn][1]);
                    MMA_BF16(acc[tm][tn][1], ah[tm], bh[tn][2], bh[tn][3]);
                }
            if (NT == 3) {
                bf16* al_s = ah_s + 5120;
                bf16* bl_s = ah_s + 14592;
                // term 2: al * bh
                {
                    uint32_t xf[4][4];
                    #pragma unroll
                    for (int tm = 0; tm < 4; tm++) {
                        uint32_t ad = smem_u32(&al_s[(warpM0 + tm*16 + (lane & 15))*40 + acol]);
                        LDSM_X4(xf[tm][0], xf[tm][1], xf[tm][2], xf[tm][3], ad);
                    }
                    #pragma unroll
                    for (int tm = 0; tm < 4; tm++)
                        #pragma unroll
                        for (int tn = 0; tn < 2; tn++) {
                            MMA_BF16(acc[tm][tn][0], xf[tm], bh[tn][0], bh[tn][1]);
                            MMA_BF16(acc[tm][tn][1], xf[tm], bh[tn][2], bh[tn][3]);
                        }
                }
                // term 3: ah * bl
                {
                    uint32_t bl[2][4];
                    #pragma unroll
                    for (int tn = 0; tn < 2; tn++) {
                        uint32_t ad = smem_u32(&bl_s[(ks*16 + (lane & 15))*136
                                                     + warpN0 + tn*16 + ((lane >> 4) << 3)]);
                        LDSM_X4_T(bl[tn][0], bl[tn][1], bl[tn][2], bl[tn][3], ad);
                    }
                    #pragma unroll
                    for (int tm = 0; tm < 4; tm++)
                        #pragma unroll
                        for (int tn = 0; tn < 2; tn++) {
                            MMA_BF16(acc[tm][tn][0], ah[tm], bl[tn][0], bl[tn][1]);
                            MMA_BF16(acc[tm][tn][1], ah[tm], bl[tn][2], bl[tn][3]);
                        }
                }
            }
        }
    }

    // epilogue
    #pragma unroll
    for (int tm = 0; tm < 4; tm++)
        #pragma unroll
        for (int tn = 0; tn < 2; tn++)
            #pragma unroll
            for (int s = 0; s < 2; s++) {
                int col = n0 + warpN0 + tn*16 + s*8 + ((lane & 3) << 1);
                float* cc = acc[tm][tn][s];
                #pragma unroll
                for (int hr = 0; hr < 2; hr++) {
                    int row = m0 + warpM0 + tm*16 + (lane >> 2) + hr*8;
                    float2 v = make_float2(cc[hr*2 + 0], cc[hr*2 + 1]);
                    if (fuse == 1) {
                        float2 r = *(const float2*)&R[(size_t)row * ldr + col];
                        v.x += r.x; v.y += r.y;
                    } else if (fuse == 2) {
                        v.x = v.x * 0.5f * (1.0f + erff(v.x * INV_SQRT_2F));
                        v.y = v.y * 0.5f * (1.0f + erff(v.y * INV_SQRT_2F));
                    }
                    size_t ci = co + (size_t)row * ldc + col;
                    if (emit & 1) *(float2*)&C[ci] = v;
                    if (emit & 6) {
                        bf16 hx, lx, hy, ly;
                        split_hl(v.x, hx, lx);
                        split_hl(v.y, hy, ly);
                        __nv_bfloat162 hv; hv.x = hx; hv.y = hy;
                        *(__nv_bfloat162*)&Oh[ci] = hv;
                        if (emit & 2) {
                            __nv_bfloat162 lv; lv.x = lx; lv.y = ly;
                            *(__nv_bfloat162*)&Ol[ci] = lv;
                        }
                    }
                }
            }
}

// ---------------- fused attention (occ 2, 512 threads, no K-split in phase 2) ----------------
#define FA_VH 0
#define FA_R  36864
#define FA_QH (FA_R)
#define FA_KH (FA_R + 9216)
#define FA_SS (FA_R)
#define FA_PH (FA_R)
#define FA_MK 104448
#define FA_SMEM 105472

__global__ __launch_bounds__(512, 2)
void fattn_kernel(const bf16* __restrict__ qkvh,
                  const float* __restrict__ maskg,
                  float* __restrict__ sp, float* __restrict__ mvp)
{
    extern __shared__ char sm[];
    bf16*  Vh = (bf16*) (sm + FA_VH);
    bf16*  Qh = (bf16*) (sm + FA_QH);
    bf16*  Kh = (bf16*) (sm + FA_KH);
    float* Ss = (float*)(sm + FA_SS);
    bf16*  Ph = (bf16*) (sm + FA_PH);
    float* mk = (float*)(sm + FA_MK);

    const int tid = threadIdx.x, warp = tid >> 5, lane = tid & 31;
    const int q0 = blockIdx.x * 64;
    const int b  = blockIdx.y >> 1, h = blockIdx.y & 1;

    const bf16* qg = qkvh + ((size_t)(b*Lc + q0)) * 384 + h*64;
    const bf16* kg = qkvh + ((size_t)(b*Lc)) * 384 + 128 + h*64;
    const bf16* vg = qkvh + ((size_t)(b*Lc)) * 384 + 256 + h*64;

    {
        int c = tid;
        int r = c >> 3, kc = (c & 7) << 3;
        cpasync16(&Qh[r*72 + kc], qg + (size_t)r*384 + kc);
    }
    for (int c = tid; c < 2048; c += 512) {
        int r = c >> 3, kc = (c & 7) << 3;
        cpasync16(&Kh[r*72 + kc], kg + (size_t)r*384 + kc);
        cpasync16(&Vh[r*72 + kc], vg + (size_t)r*384 + kc);
    }
    if (tid < 64)
        cpasync16(&mk[tid*4], maskg + b*Lc + tid*4);
    CP_COMMIT(); CP_WAIT0();
    __syncthreads();

    // phase 1: S = Qh @ Kh^T   (M=64, N=256, K=64)
    {
        const int wM = (warp & 1) * 32;
        const int wN = (warp >> 1) * 32;
        float accS[2][2][2][4];
        #pragma unroll
        for (int i=0;i<2;i++) for (int j=0;j<2;j++) for (int s=0;s<2;s++)
            for (int q=0;q<4;q++) accS[i][j][s][q] = 0.f;

        #pragma unroll
        for (int kf = 0; kf < 4; kf++) {
            const int kcol = kf*16 + ((lane >> 4) << 3);
            uint32_t qa[2][4], ka[2][4];
            #pragma unroll
            for (int mf = 0; mf < 2; mf++) {
                int ro = (wM + mf*16 + (lane & 15))*72 + kcol;
                LDSM_X4(qa[mf][0], qa[mf][1], qa[mf][2], qa[mf][3], smem_u32(&Qh[ro]));
            }
            #pragma unroll
            for (int tn = 0; tn < 2; tn++) {
                int ro = (wN + tn*16 + (lane & 15))*72 + kcol;
                LDSM_X4(ka[tn][0], ka[tn][1], ka[tn][2], ka[tn][3], smem_u32(&Kh[ro]));
            }
            #pragma unroll
            for (int mf = 0; mf < 2; mf++)
                #pragma unroll
                for (int tn = 0; tn < 2; tn++) {
                    MMA_BF16(accS[mf][tn][0], qa[mf], ka[tn][0], ka[tn][2]);
                    MMA_BF16(accS[mf][tn][1], qa[mf], ka[tn][1], ka[tn][3]);
                }
        }
        __syncthreads();   // Qh/Kh reads done before Ss overlays them

        #pragma unroll
        for (int mf = 0; mf < 2; mf++)
            #pragma unroll
            for (int tn = 0; tn < 2; tn++)
                #pragma unroll
                for (int s = 0; s < 2; s++)
                    #pragma unroll
                    for (int hr = 0; hr < 2; hr++) {
                        int row = wM + mf*16 + (lane >> 2) + hr*8;
                        int col = wN + tn*16 + s*8 + ((lane & 3) << 1);
                        *(float2*)&Ss[row*264 + col] =
                            make_float2(accS[mf][tn][s][hr*2], accS[mf][tn][s][hr*2+1]);
                    }
    }
    __syncthreads();

    // meanv partials
    {
        int d = tid & 255, half = tid >> 8;
        float s = 0.f;
        #pragma unroll 8
        for (int m = half*32; m < half*32 + 32; m++)
            s += Ss[m*264 + ((q0 + m - d) & 255)];
        int p = (blockIdx.x*2 + h)*2 + half;
        mvp[((size_t)p * Bc + b) * Lc + d] = s * (1.0f/128.0f);
    }
    __syncthreads();

    // softmax -> Ph in place over Ss (register-buffered)
    {
        int row = tid >> 3, part = tid & 7;
        float* Sr = &Ss[row*264 + part*32];
        const float* mr = &mk[part*32];
        float r[32];
        #pragma unroll
        for (int j = 0; j < 32; j++)
            r[j] = Sr[j] * INV_SQRT_E + mr[j];
        float mx = -1e30f;
        #pragma unroll
        for (int j = 0; j < 32; j++) mx = fmaxf(mx, r[j]);
        mx = fmaxf(mx, __shfl_xor_sync(0xffffffffu, mx, 1));
        mx = fmaxf(mx, __shfl_xor_sync(0xffffffffu, mx, 2));
        mx = fmaxf(mx, __shfl_xor_sync(0xffffffffu, mx, 4));
        float sum = 0.f;
        #pragma unroll
        for (int j = 0; j < 32; j++) { r[j] = expf(r[j] - mx); sum += r[j]; }
        sum += __shfl_xor_sync(0xffffffffu, sum, 1);
        sum += __shfl_xor_sync(0xffffffffu, sum, 2);
        sum += __shfl_xor_sync(0xffffffffu, sum, 4);
        float inv = 1.0f / sum;
        __syncthreads();   // all Ss reads complete before overlay writes
        bf16* ph = &Ph[row*264 + part*32];
        #pragma unroll
        for (int j = 0; j < 32; j++)
            ph[j] = __float2bfloat16(r[j] * inv);
    }
    __syncthreads();

    // phase 2: O = Ph @ Vh  (M=64, N=64, K=256); 16 warps map 4x4 over (M,N),
    // each with a full-K loop — no cross-warp reduction needed.
    {
        const int wM2 = (warp & 3) * 16;
        const int wN2 = (warp >> 2) * 16;
        float o[2][4];
        #pragma unroll
        for (int s = 0; s < 2; s++)
            #pragma unroll
            for (int q = 0; q < 4; q++) o[s][q] = 0.f;

        #pragma unroll 4
        for (int kf = 0; kf < 16; kf++) {
            uint32_t a[4], bh[4];
            {
                uint32_t ro = (wM2 + (lane & 15))*264 + kf*16 + ((lane >> 4) << 3);
                LDSM_X4(a[0], a[1], a[2], a[3], smem_u32(&Ph[ro]));
            }
            {
                uint32_t vo = (kf*16 + (lane & 15))*72 + wN2 + ((lane >> 4) << 3);
                LDSM_X4_T(bh[0], bh[1], bh[2], bh[3], smem_u32(&Vh[vo]));
            }
            MMA_BF16(o[0], a, bh[0], bh[1]);
            MMA_BF16(o[1], a, bh[2], bh[3]);
        }
        #pragma unroll
        for (int s = 0; s < 2; s++)
            #pragma unroll
            for (int hr = 0; hr < 2; hr++) {
                int row = q0 + wM2 + (lane >> 2) + hr*8;
                int col = h*64 + wN2 + s*8 + ((lane & 3) << 1);
                *(float2*)&sp[((size_t)b*Lc + row)*Dc + col] =
                    make_float2(o[s][hr*2], o[s][hr*2+1]);
            }
    }
}

// ---------------- small kernels ----------------
__global__ void build_x_kernel(const int* __restrict__ paths,
                               const float* __restrict__ ego,
                               const float* __restrict__ pos)
{
    int bl = blockIdx.x, c = threadIdx.x;
    int p = paths[bl], l = bl & (Lc - 1);
    float v = ego[(size_t)p * Dc + c] + pos[l * Dc + c];
    g_x[(size_t)bl * Dc + c] = v;
    bf16 h, lo; split_hl(v, h, lo);
    g_xh[(size_t)bl * Dc + c] = h;
    g_xl[(size_t)bl * Dc + c] = lo;
    if (c == 0) g_mask[bl] = (p < NUM_TOTAL_C) ? 0.f : -10000.f;
}

__global__ void build_cs_kernel()
{
    int layer = blockIdx.x, n = threadIdx.x;
    int left = c_lefts[layer], right = c_rights[layer];
    double s = 0.0;
    for (int f = left; f < right; f++) {
        double w;
        if (f == 0)           w = 1.0;
        else if (f == Lc/2)   w = (n & 1) ? -1.0 : 1.0;
        else                  w = 2.0 * cos(2.0 * M_PI * (double)f * (double)n / (double)Lc);
        s += w;
    }
    g_cs[layer*Lc + n] = (float)(s / (double)Lc);
}

__global__ void buildC_kernel()
{
    int n = blockIdx.x, layer = blockIdx.y, m = threadIdx.x;
    float v = g_cs[layer*Lc + ((n - m + Lc) & (Lc - 1))];
    bf16 h, l; split_hl(v, h, l);
    g_Cmh[layer*Lc*Lc + n*Lc + m] = h;
    g_Cml[layer*Lc*Lc + n*Lc + m] = l;
}

__global__ void convW_kernel(const float* __restrict__ Wq, const float* __restrict__ Wk,
                             const float* __restrict__ Wv, const float* __restrict__ Wp,
                             const float* __restrict__ F1, const float* __restrict__ F2)
{
    int gidx = blockIdx.x * 256 + threadIdx.x;     // 0..262143
    int layer = gidx >> 17;
    int idx = gidx & 131071;
    float v;
    if (idx < 49152) {
        int k = idx / 384, c = idx - k*384;
        int w = c >> 7, n = c & 127;
        const float* src = (w == 0 ? Wq : w == 1 ? Wk : Wv) + layer*Dc*Dc;
        v = src[k*128 + n];
    } else if (idx < 65536) {
        v = Wp[layer*Dc*Dc + idx - 49152];
    } else if (idx < 98304) {
        v = F1[layer*Dc*2*Dc + idx - 65536];
    } else {
        v = F2[layer*2*Dc*Dc + idx - 98304];
    }
    bf16 h, l; split_hl(v, h, l);
    g_Wh[layer*131072 + idx] = h;
    g_Wl[layer*131072 + idx] = l;
}

__global__ void meanred_kernel()
{
    int b = blockIdx.x, d = threadIdx.x;
    float s = 0.f;
    #pragma unroll
    for (int p = 0; p < 16; p++) s += g_mvp[((size_t)p * Bc + b) * Lc + d];
    g_mv[b * Lc + d] = s;
}

__global__ void stats_kernel()
{
    __shared__ float sv[Lc];
    __shared__ int   si[Lc];
    __shared__ int   dls[TOPKc];
    int t = threadIdx.x;

    float s = 0.f;
    for (int b = 0; b < Bc; b++) s += g_mv[b * Lc + t];
    float my = s * (1.0f / (float)Bc);

    for (int it = 0; it < TOPKc; it++) {
        sv[t] = my; si[t] = t;
        __syncthreads();
        for (int st = 128; st > 0; st >>= 1) {
            if (t < st) {
                float v2 = sv[t + st]; int i2 = si[t + st];
                if (v2 > sv[t] || (v2 == sv[t] && i2 < si[t])) { sv[t] = v2; si[t] = i2; }
            }
            __syncthreads();
        }
        int win = si[0];
        if (t == 0) { g_delays[it] = win; dls[it] = win; }
        __syncthreads();
        if (t == win) my = -INFINITY;
    }

    float w[TOPKc];
    float mx = -1e30f;
    #pragma unroll
    for (int i = 0; i < TOPKc; i++) {
        w[i] = g_mv[t * Lc + dls[i]];
        mx = fmaxf(mx, w[i]);
    }
    float sm = 0.f;
    #pragma unroll
    for (int i = 0; i < TOPKc; i++) { w[i] = expf(w[i] - mx); sm += w[i]; }
    float inv = 1.0f / sm;
    #pragma unroll
    for (int i = 0; i < TOPKc; i++) g_w[t * TOPKc + i] = w[i] * inv;
}

__global__ void combine_kernel()
{
    int bl = blockIdx.x, c = threadIdx.x;
    int b = bl >> 8, l = bl & 255;
    __shared__ float w[TOPKc];
    __shared__ int   dl[TOPKc];
    if (c < TOPKc) { w[c] = g_w[b * TOPKc + c]; dl[c] = g_delays[c]; }
    __syncthreads();
    float f = 0.f;
    #pragma unroll
    for (int t = 0; t < TOPKc; t++) {
        int ls = (l + dl[t]) & 255;
        f += w[t] * g_vb[((size_t)b * Lc + ls) * Dc + c];
    }
    float v = 0.9f * f + 0.1f * g_sp[(size_t)bl * Dc + c];
    bf16 h, lo; split_hl(v, h, lo);
    g_oh[(size_t)bl * Dc + c] = h;
    g_ol[(size_t)bl * Dc + c] = lo;
}

__global__ void gather_kernel(const int* __restrict__ lengths, float* __restrict__ out)
{
    int b = blockIdx.x, c = threadIdx.x;
    int l = lengths[b] - 1;
    out[b * Dc + c] = g_x[((size_t)b * Lc + l) * Dc + c];
}

// ---------------- host side ----------------
static inline void mma_go(const bf16* Ah, const bf16* Al,
                          const bf16* Bh, const bf16* Bl, float* C,
                          int M, int N, int K, int lda, int ldb, int ldc,
                          int batch, long sA, long sB, long sC,
                          const float* R, int ldr, int fuse,
                          int emit, bf16* Oh, bf16* Ol, int nterms)
{
    dim3 grid(M / 128, N / 128, batch);
    if (nterms == 1)
        mma_kernel<1><<<grid, 256, MMA_SMEM_BYTES>>>(Ah, Al, Bh, Bl, C, K, lda, ldb, ldc,
            sA, sB, sC, R, ldr, fuse, emit, Oh, Ol);
    else
        mma_kernel<3><<<grid, 256, MMA_SMEM_BYTES>>>(Ah, Al, Bh, Bl, C, K, lda, ldb, ldc,
            sA, sB, sC, R, ldr, fuse, emit, Oh, Ol);
}

extern "C" void kernel_launch(void* const* d_in, const int* in_sizes, int n_in,
                              void* d_out, int out_size)
{
    (void)in_sizes; (void)n_in; (void)out_size;
    const int*   paths   = (const int*)  d_in[0];
    const int*   lengths = (const int*)  d_in[1];
    const float* ego     = (const float*)d_in[4];
    const float* pos     = (const float*)d_in[5];
    const float* Wq      = (const float*)d_in[6];
    const float* Wk      = (const float*)d_in[7];
    const float* Wv      = (const float*)d_in[8];
    const float* Wp      = (const float*)d_in[9];
    const float* F1      = (const float*)d_in[10];
    const float* F2      = (const float*)d_in[11];
    float* out = (float*)d_out;

    float *px, *pmask, *pvb, *psp, *pmvp;
    bf16 *pxh, *pxl, *pxth, *pqkvh, *poh, *pol, *pah, *pal,
         *phh, *phl, *pCmh, *pCml, *pWh, *pWl;
    cudaGetSymbolAddress((void**)&px,    g_x);
    cudaGetSymbolAddress((void**)&pmask, g_mask);
    cudaGetSymbolAddress((void**)&pvb,   g_vb);
    cudaGetSymbolAddress((void**)&psp,   g_sp);
    cudaGetSymbolAddress((void**)&pmvp,  g_mvp);
    cudaGetSymbolAddress((void**)&pxh,   g_xh);
    cudaGetSymbolAddress((void**)&pxl,   g_xl);
    cudaGetSymbolAddress((void**)&pxth,  g_xth);
    cudaGetSymbolAddress((void**)&pqkvh, g_qkvh);
    cudaGetSymbolAddress((void**)&poh,   g_oh);
    cudaGetSymbolAddress((void**)&pol,   g_ol);
    cudaGetSymbolAddress((void**)&pah,   g_ah);
    cudaGetSymbolAddress((void**)&pal,   g_al);
    cudaGetSymbolAddress((void**)&phh,   g_hh);
    cudaGetSymbolAddress((void**)&phl,   g_hl);
    cudaGetSymbolAddress((void**)&pCmh,  g_Cmh);
    cudaGetSymbolAddress((void**)&pCml,  g_Cml);
    cudaGetSymbolAddress((void**)&pWh,   g_Wh);
    cudaGetSymbolAddress((void**)&pWl,   g_Wl);

    cudaFuncSetAttribute(fattn_kernel,
                         cudaFuncAttributeMaxDynamicSharedMemorySize, FA_SMEM);
    cudaFuncSetAttribute(mma_kernel<1>,
                         cudaFuncAttributeMaxDynamicSharedMemorySize, MMA_SMEM_BYTES);
    cudaFuncSetAttribute(mma_kernel<3>,
                         cudaFuncAttributeMaxDynamicSharedMemorySize, MMA_SMEM_BYTES);

    const int  BL = Bc * Lc;
    const long LD = (long)Lc * Dc;

    // input prep upfront
    build_x_kernel<<<BL, Dc>>>(paths, ego, pos);
    build_cs_kernel<<<NLc, Lc>>>();
    buildC_kernel<<<dim3(Lc, NLc), Lc>>>();
    convW_kernel<<<1024, 256>>>(Wq, Wk, Wv, Wp, F1, F2);

    for (int k = 0; k < NLc; k++) {
        const bf16* Cmh = pCmh + (size_t)k * Lc * Lc;
        const bf16* Cml = pCml + (size_t)k * Lc * Lc;
        const bf16* Wh  = pWh  + (size_t)k * 131072;
        const bf16* Wl  = pWl  + (size_t)k * 131072;

        // xt = Cm @ x (batched over b) — SINGLE-TERM (feeds only the S-tolerant path)
        mma_go(Cmh, Cmh, pxh, pxh, psp /*unused*/,
               Lc, Dc, Lc, Lc, Dc, Dc,
               Bc, 0, LD, LD, nullptr, 0, 0, 4, pxth, nullptr, 1);

        // qkv = xt @ [Wq|Wk|Wv]  (N=384, single-term)
        mma_go(pxth, pxth, Wh + WO_QKV, Wh + WO_QKV, psp /*unused*/,
               BL, 3*Dc, Dc, Dc, 3*Dc, 3*Dc,
               1, 0, 0, 0, nullptr, 0, 0, 4, pqkvh, nullptr, 1);

        // fused attention
        {
            dim3 grid(4, Bc * 2);
            fattn_kernel<<<grid, 512, FA_SMEM>>>(pqkvh, pmask, psp, pmvp);
        }
        meanred_kernel<<<Bc, Lc>>>();
        stats_kernel<<<1, Lc>>>();

        // vb = x @ Wv (fp32, 3-term; 0.9-weighted main branch)
        mma_go(pxh, pxl, Wh + WO_QKV + 256, Wl + WO_QKV + 256, pvb,
               BL, Dc, Dc, Dc, 3*Dc, Dc,
               1, 0, 0, 0, nullptr, 0, 0, 1, nullptr, nullptr, 3);

        combine_kernel<<<BL, Dc>>>();

        // a = o @ Wp + x
        mma_go(poh, pol, Wh + WO_P, Wl + WO_P, psp /*unused*/,
               BL, Dc, Dc, Dc, Dc, Dc,
               1, 0, 0, 0, px, Dc, 1, 2, pah, pal, 3);

        // h = GELU(a @ F1)  (N=256)
        mma_go(pah, pal, Wh + WO_F1, Wl + WO_F1, psp /*unused*/,
               BL, 2*Dc, Dc, Dc, 2*Dc, 2*Dc,
               1, 0, 0, 0, nullptr, 0, 2, 2, phh, phl, 3);

        // x = h @ F2  (K=256) -> fp32 x + planes
        mma_go(phh, phl, Wh + WO_F2, Wl + WO_F2, px,
               BL, Dc, 2*Dc, 2*Dc, Dc, Dc,
               1, 0, 0, 0, nullptr, 0, 0, 3, pxh, pxl, 3);
    }

    gather_kernel<<<Bc, Dc>>>(lengths, out);
}